// round 8
// baseline (speedup 1.0000x reference)
#include <cuda_runtime.h>
#include <cuda_bf16.h>
#include <math.h>
#include <stdint.h>

#define BB    16
#define CCH   512
#define NN    3136
#define NKK   49
#define HEADS 8
#define JJ    392
#define HIDC  24
#define SCALE 0.125f

// ---------------- device scratch ----------------
__device__ float g_kvx[BB*NKK*CCH];
__device__ float g_kv [BB*NKK*1024];
__device__ float g_Wvp[BB*JJ*CCH];
__device__ __nv_bfloat16 g_xTh[(size_t)BB*NN*CCH];
__device__ __nv_bfloat16 g_xTl[(size_t)BB*NN*CCH];
__device__ __nv_bfloat16 g_wqh[BB*JJ*CCH];
__device__ __nv_bfloat16 g_wql[BB*JJ*CCH];
__device__ __nv_bfloat16 g_wvh[BB*CCH*JJ];
__device__ __nv_bfloat16 g_wvl[BB*CCH*JJ];
__device__ float g_attn[(size_t)BB*NN*JJ];
__device__ float g_dwout[(size_t)BB*NN*HIDC*NKK];
__device__ __nv_bfloat16 g_ath[(size_t)BB*NN*JJ];
__device__ __nv_bfloat16 g_atl[(size_t)BB*NN*JJ];
__device__ float g_part1[BB*49*36];
__device__ float g_part2[BB*3*196*2];
__device__ float g_part3[BB*392*2];
__device__ float g_ab1[BB*HIDC*2];
__device__ float g_ab2[BB*HIDC*2];
__device__ float g_ab3[BB*HEADS*2];
__device__ float g_bias2[BB*CCH];

__device__ __forceinline__ float swishf(float x) { return x / (1.f + __expf(-x)); }

__device__ __forceinline__ void bsplit(float v, __nv_bfloat16& h, __nv_bfloat16& l) {
    h = __float2bfloat16(v);
    l = __float2bfloat16(v - __bfloat162float(h));
}

__device__ __forceinline__ uint32_t smem_u32(const void* p) {
    uint32_t a;
    asm("{ .reg .u64 t; cvta.to.shared.u64 t, %1; cvt.u32.u64 %0, t; }" : "=r"(a) : "l"(p));
    return a;
}
__device__ __forceinline__ void ldm_x4(uint32_t* r, uint32_t addr) {
    asm volatile("ldmatrix.sync.aligned.m8n8.x4.shared.b16 {%0,%1,%2,%3}, [%4];"
        : "=r"(r[0]), "=r"(r[1]), "=r"(r[2]), "=r"(r[3]) : "r"(addr));
}
__device__ __forceinline__ void ldm_x2(uint32_t* r, uint32_t addr) {
    asm volatile("ldmatrix.sync.aligned.m8n8.x2.shared.b16 {%0,%1}, [%2];"
        : "=r"(r[0]), "=r"(r[1]) : "r"(addr));
}
__device__ __forceinline__ void mma_bf16(float* c, const uint32_t* a, const uint32_t* b) {
    asm volatile(
        "mma.sync.aligned.m16n8k16.row.col.f32.bf16.bf16.f32 "
        "{%0,%1,%2,%3}, {%4,%5,%6,%7}, {%8,%9}, {%0,%1,%2,%3};"
        : "+f"(c[0]), "+f"(c[1]), "+f"(c[2]), "+f"(c[3])
        : "r"(a[0]), "r"(a[1]), "r"(a[2]), "r"(a[3]), "r"(b[0]), "r"(b[1]));
}
__device__ __forceinline__ void cpa16(uint32_t dst, const void* src, bool v) {
    int sz = v ? 16 : 0;
    asm volatile("cp.async.cg.shared.global [%0], [%1], 16, %2;"
        :: "r"(dst), "l"(src), "r"(sz) : "memory");
}
__device__ __forceinline__ void cp_commit() {
    asm volatile("cp.async.commit_group;" ::: "memory");
}
__device__ __forceinline__ void cp_wait1() {
    asm volatile("cp.async.wait_group 1;" ::: "memory");
}
__device__ __forceinline__ void cp_wait0() {
    asm volatile("cp.async.wait_group 0;" ::: "memory");
}

// ---------------- 1. depthwise 8x8/8 downsample ----------------
__global__ void k_down(const float* __restrict__ x, const float* __restrict__ down_w) {
    int bc = blockIdx.x, c = bc & 511, b = bc >> 9;
    __shared__ float plane[3136];
    __shared__ float w[64];
    const float* xp = x + (size_t)bc * 3136;
    for (int i = threadIdx.x; i < 3136; i += 256) plane[i] = xp[i];
    if (threadIdx.x < 64) w[threadIdx.x] = down_w[c*64 + threadIdx.x];
    __syncthreads();
    if (threadIdx.x < 49) {
        int my = threadIdx.x / 7, mx = threadIdx.x % 7;
        float s = 0.f;
        #pragma unroll
        for (int i = 0; i < 8; i++)
            #pragma unroll
            for (int j = 0; j < 8; j++)
                s += plane[(my*8+i)*56 + mx*8 + j] * w[i*8+j];
        g_kvx[(b*49 + threadIdx.x)*512 + c] = s;
    }
}

// ---------------- 2. kv = kvx @ kv_w ----------------
__global__ void k_kv(const float* __restrict__ kv_w) {
    int b = blockIdx.z, m0 = blockIdx.y * 7, oc = blockIdx.x;
    __shared__ float a[7][512];
    for (int i = threadIdx.x; i < 7*512; i += 256)
        a[i >> 9][i & 511] = g_kvx[(b*49 + m0 + (i >> 9))*512 + (i & 511)];
    __syncthreads();
    int o = oc*256 + threadIdx.x;
    float acc[7] = {0,0,0,0,0,0,0};
    for (int c = 0; c < 512; c++) {
        float w = kv_w[c*1024 + o];
        #pragma unroll
        for (int mm = 0; mm < 7; mm++) acc[mm] += a[mm][c] * w;
    }
    #pragma unroll
    for (int mm = 0; mm < 7; mm++)
        g_kv[(b*49 + m0 + mm)*1024 + o] = acc[mm];
}

// ---------------- 3. Wqk fused compute + bf16 split ----------------
__global__ __launch_bounds__(256) void k_wqk_split(const float* __restrict__ q_w) {
    int half = blockIdx.x, h = blockIdx.y, b = blockIdx.z;
    __shared__ float ks[49][64];
    for (int i = threadIdx.x; i < 49*64; i += 256)
        ks[i >> 6][i & 63] = g_kv[(b*49 + (i >> 6))*1024 + h*64 + (i & 63)];
    __syncthreads();
    int cin = half*256 + threadIdx.x;
    float acc[49];
    #pragma unroll
    for (int m = 0; m < 49; m++) acc[m] = 0.f;
    const float4* q4 = (const float4*)(q_w + (size_t)cin*512 + h*64);
    const float4* ks4 = (const float4*)&ks[0][0];
    for (int d4 = 0; d4 < 16; d4++) {
        float4 q = __ldg(q4 + d4);
        #pragma unroll
        for (int m = 0; m < 49; m++) {
            float4 k = ks4[m*16 + d4];
            acc[m] += q.x*k.x + q.y*k.y + q.z*k.z + q.w*k.w;
        }
    }
    size_t obase = ((size_t)b*392 + h*49)*512 + cin;
    #pragma unroll
    for (int m = 0; m < 49; m++) {
        float v = acc[m] * SCALE;
        __nv_bfloat16 hh, ll; bsplit(v, hh, ll);
        g_wqh[obase + (size_t)m*512] = hh;
        g_wql[obase + (size_t)m*512] = ll;
    }
}

// ---------------- 4. Wvp ----------------
__global__ void k_wvp(const float* __restrict__ proj_w) {
    int b = blockIdx.z, h = blockIdx.y, mc = blockIdx.x * 7;
    __shared__ float vs[7][64];
    for (int i = threadIdx.x; i < 7*64; i += 256)
        vs[i >> 6][i & 63] = g_kv[(b*49 + mc + (i >> 6))*1024 + 512 + h*64 + (i & 63)];
    __syncthreads();
    int t = threadIdx.x;
    float acc[7][2] = {{0}};
    for (int d = 0; d < 64; d++) {
        float w0 = proj_w[(h*64+d)*512 + t];
        float w1 = proj_w[(h*64+d)*512 + 256 + t];
        #pragma unroll
        for (int mm = 0; mm < 7; mm++) {
            float vv = vs[mm][d];
            acc[mm][0] += vv * w0;
            acc[mm][1] += vv * w1;
        }
    }
    #pragma unroll
    for (int mm = 0; mm < 7; mm++) {
        int j = h*49 + mc + mm;
        g_Wvp[(b*392 + j)*512 + t]       = acc[mm][0];
        g_Wvp[(b*392 + j)*512 + 256 + t] = acc[mm][1];
    }
}

// ---------------- 4b. transpose+split x ----------------
__global__ void k_xsplit(const float* __restrict__ x) {
    int tn = blockIdx.x, tc = blockIdx.y, b = blockIdx.z;
    __shared__ float tile[32][33];
    int a = threadIdx.x >> 5, q = threadIdx.x & 31;
    #pragma unroll
    for (int r = 0; r < 4; r++) {
        int cc = tc*32 + a + r*8, nn = tn*32 + q;
        tile[a + r*8][q] = x[((size_t)b*512 + cc)*3136 + nn];
    }
    __syncthreads();
    #pragma unroll
    for (int r = 0; r < 4; r++) {
        int nn = tn*32 + a + r*8, cc = tc*32 + q;
        float v = tile[q][a + r*8];
        __nv_bfloat16 h, l; bsplit(v, h, l);
        size_t o = ((size_t)b*3136 + nn)*512 + cc;
        g_xTh[o] = h; g_xTl[o] = l;
    }
}

// ---------------- 4d. transpose+scale+split Wvp ----------------
__global__ void k_wvpsplit(void) {
    int tj = blockIdx.x, tc = blockIdx.y, b = blockIdx.z;
    __shared__ float tile[32][33];
    int a = threadIdx.x >> 5, q = threadIdx.x & 31;
    #pragma unroll
    for (int r = 0; r < 4; r++) {
        int jj = tj*32 + a + r*8, cc = tc*32 + q;
        float v = 0.f;
        if (jj < 392) v = g_Wvp[((size_t)b*392 + jj)*512 + cc] * g_ab3[(b*8 + jj/49)*2];
        tile[a + r*8][q] = v;
    }
    __syncthreads();
    #pragma unroll
    for (int r = 0; r < 4; r++) {
        int cc = tc*32 + a + r*8, jj = tj*32 + q;
        if (jj < 392) {
            float v = tile[q][a + r*8];
            __nv_bfloat16 h, l; bsplit(v, h, l);
            size_t o = ((size_t)b*512 + cc)*392 + jj;
            g_wvh[o] = h; g_wvl[o] = l;
        }
    }
}

// ---------------- 4e. bias2 ----------------
__global__ void k_wvpbias(const float* __restrict__ proj_b) {
    int b = blockIdx.x, c = threadIdx.x;
    float acc = 0.f;
    for (int j = 0; j < 392; j++)
        acc += g_ab3[(b*8 + j/49)*2 + 1] * g_Wvp[((size_t)b*392 + j)*512 + c];
    g_bias2[b*512 + c] = acc + proj_b[c];
}

// ---------------- 5. GEMM1 fused (single-buffered operands, 2 CTAs/SM) ----------------
#define G1_AH 0u
#define G1_AL 5120u
#define G1_BH 10240u
#define G1_BL 43520u
#define G1_SMEM 103552
__device__ __forceinline__ void g1f_load(uint32_t sb, int b, int nt0, int kt, int t) {
    int k0 = kt*32;
    {
        int row = t >> 2, q = t & 3;
        size_t e = ((size_t)b*3136 + nt0 + row)*512 + k0 + q*8;
        uint32_t doff = (uint32_t)(row*40 + q*8)*2;
        cpa16(sb + G1_AH + doff, g_xTh + e, true);
        cpa16(sb + G1_AL + doff, g_xTl + e, true);
    }
    #pragma unroll
    for (int rr = 0; rr < 13; rr++) {
        int idx = rr*256 + t;
        int hl = idx >= 1664;
        int ii = idx - hl*1664;
        int row = ii >> 2, q = ii & 3;
        bool v = row < 392;
        size_t e = ((size_t)b*392 + (v ? row : 0))*512 + k0 + q*8;
        uint32_t doff = (uint32_t)(row*40 + q*8)*2;
        const __nv_bfloat16* src = hl ? g_wql : g_wqh;
        cpa16(sb + (hl ? G1_BL : G1_BH) + doff, src + e, v);
    }
}

__global__ __launch_bounds__(256) void k_gemm1_fused(const float* __restrict__ rel_bias) {
    extern __shared__ char smraw[];
    uint32_t sb = smem_u32(smraw);
    int b = blockIdx.y, nt0 = blockIdx.x * 64;
    int t = threadIdx.x, w = t >> 5, lane = t & 31;
    int wn = (w & 1)*32, wj = (w >> 1)*104;
    float acc[2][13][4];
    #pragma unroll
    for (int i = 0; i < 2; i++)
        #pragma unroll
        for (int j = 0; j < 13; j++)
            #pragma unroll
            for (int k = 0; k < 4; k++) acc[i][j][k] = 0.f;

    for (int kt = 0; kt < 16; kt++) {
        g1f_load(sb, b, nt0, kt, t);
        cp_commit();
        cp_wait0();
        __syncthreads();
        #pragma unroll
        for (int kk = 0; kk < 2; kk++) {
            int kb = kk*16;
            uint32_t ah[2][4], al[2][4];
            int arow = wn + (lane & 15);
            int acol = kb + ((lane & 16) ? 8 : 0);
            ldm_x4(ah[0], sb + G1_AH + (uint32_t)(arow*40 + acol)*2);
            ldm_x4(ah[1], sb + G1_AH + (uint32_t)((arow+16)*40 + acol)*2);
            ldm_x4(al[0], sb + G1_AL + (uint32_t)(arow*40 + acol)*2);
            ldm_x4(al[1], sb + G1_AL + (uint32_t)((arow+16)*40 + acol)*2);
            #pragma unroll
            for (int p2 = 0; p2 < 6; p2++) {
                int jrow = wj + p2*16 + (lane & 7) + ((lane & 16) ? 8 : 0);
                int col = kb + ((lane & 8) ? 8 : 0);
                uint32_t off = (uint32_t)(jrow*40 + col)*2;
                uint32_t rh[4], rl[4];
                ldm_x4(rh, sb + G1_BH + off);
                ldm_x4(rl, sb + G1_BL + off);
                #pragma unroll
                for (int mt = 0; mt < 2; mt++)
                    #pragma unroll
                    for (int e = 0; e < 2; e++) {
                        mma_bf16(acc[mt][2*p2+e], ah[mt], &rh[2*e]);
                        mma_bf16(acc[mt][2*p2+e], al[mt], &rh[2*e]);
                        mma_bf16(acc[mt][2*p2+e], ah[mt], &rl[2*e]);
                    }
            }
            {
                int jrow = wj + 96 + (lane & 7);
                int col = kb + ((lane & 8) ? 8 : 0);
                uint32_t off = (uint32_t)(jrow*40 + col)*2;
                uint32_t bh2[2], bl2[2];
                ldm_x2(bh2, sb + G1_BH + off);
                ldm_x2(bl2, sb + G1_BL + off);
                #pragma unroll
                for (int mt = 0; mt < 2; mt++) {
                    mma_bf16(acc[mt][12], ah[mt], bh2);
                    mma_bf16(acc[mt][12], al[mt], bh2);
                    mma_bf16(acc[mt][12], ah[mt], bl2);
                }
            }
        }
        __syncthreads();
    }
    // ---- epilogue: stage logits in SMEM ----
    float* S = (float*)smraw;            // [64][400]
    float* Gred = S + 64*400;            // [8][36]
    #pragma unroll
    for (int mt = 0; mt < 2; mt++) {
        int nl = wn + mt*16 + (lane >> 2);
        #pragma unroll
        for (int jt = 0; jt < 13; jt++) {
            int j0 = wj + jt*8 + ((lane & 3) << 1);
            if (j0 < 392) {
                S[nl*400 + j0]       = acc[mt][jt][0];
                S[nl*400 + j0 + 1]   = acc[mt][jt][1];
                S[(nl+8)*400 + j0]   = acc[mt][jt][2];
                S[(nl+8)*400 + j0+1] = acc[mt][jt][3];
            }
        }
    }
    __syncthreads();
    // ---- softmax per (n,h) row, adding rel_bias ----
    #pragma unroll
    for (int rr = 0; rr < 2; rr++) {
        int row = t + rr*256;
        int n = row >> 3, h = row & 7;
        float* p = S + n*400 + h*49;
        const float* rb = rel_bias + (size_t)(nt0 + n)*49;
        float mx = -1e30f;
        for (int i = 0; i < 49; i++) {
            float lv = p[i] + __ldg(rb + i);
            p[i] = lv;
            mx = fmaxf(mx, lv);
        }
        float sum = 0.f;
        for (int i = 0; i < 49; i++) { float e = __expf(p[i] - mx); p[i] = e; sum += e; }
        float inv = 1.f / sum;
        for (int i = 0; i < 49; i++) p[i] *= inv;
    }
    __syncthreads();
    // ---- Gram partials ----
    float g[36];
    #pragma unroll
    for (int k = 0; k < 36; k++) g[k] = 0.f;
    for (int pos = t; pos < 64*49; pos += 256) {
        int n = pos / 49, m = pos - n*49;
        float a[8];
        #pragma unroll
        for (int h = 0; h < 8; h++) a[h] = S[n*400 + h*49 + m];
        int k = 0;
        #pragma unroll
        for (int h = 0; h < 8; h++)
            #pragma unroll
            for (int h2 = h; h2 < 8; h2++) { g[k] += a[h]*a[h2]; k++; }
    }
    size_t ob = ((size_t)b*3136 + nt0)*392;
    for (int i = t; i < 64*392; i += 256) {
        int n = i / 392, c = i - n*392;
        g_attn[ob + i] = S[n*400 + c];
    }
    #pragma unroll
    for (int s = 16; s; s >>= 1)
        #pragma unroll
        for (int k = 0; k < 36; k++) g[k] += __shfl_xor_sync(0xffffffffu, g[k], s);
    if (lane == 0)
        #pragma unroll
        for (int k = 0; k < 36; k++) Gred[w*36 + k] = g[k];
    __syncthreads();
    if (t < 36) {
        float s = 0.f;
        #pragma unroll
        for (int ww = 0; ww < 8; ww++) s += Gred[ww*36 + t];
        g_part1[((size_t)b*49 + blockIdx.x)*36 + t] = s;
    }
}

// ---------------- 6. gn1 finalize from Gram ----------------
__global__ void k_gn1_final(const float* __restrict__ gs, const float* __restrict__ gb,
                            const float* __restrict__ ew) {
    int b = blockIdx.x, t = threadIdx.x;   // 64 threads
    __shared__ float M36[36];
    __shared__ float Mf[64];
    __shared__ float s1s[24], sqs[24];
    __shared__ float mg[3], rg[3];
    if (t < 36) {
        float s = 0.f;
        for (int nt = 0; nt < 49; nt++) s += g_part1[((size_t)b*49 + nt)*36 + t];
        M36[t] = s;
    }
    __syncthreads();
    if (t == 0) {
        int k = 0;
        for (int h = 0; h < 8; h++)
            for (int h2 = h; h2 < 8; h2++) { Mf[h*8+h2] = M36[k]; Mf[h2*8+h] = M36[k]; k++; }
    }
    __syncthreads();
    if (t < 24) {
        float wv[8], sw = 0.f;
        #pragma unroll
        for (int h = 0; h < 8; h++) { wv[h] = ew[t*8+h]; sw += wv[h]; }
        float sq = 0.f;
        #pragma unroll
        for (int h = 0; h < 8; h++)
            #pragma unroll
            for (int h2 = 0; h2 < 8; h2++) sq += wv[h]*wv[h2]*Mf[h*8+h2];
        s1s[t] = 3136.f * sw;
        sqs[t] = sq;
    }
    __syncthreads();
    if (t < 3) {
        float s1 = 0.f, sq = 0.f;
        for (int c = 0; c < 8; c++) { s1 += s1s[t*8+c]; sq += sqs[t*8+c]; }
        float cnt = 8.f*3136.f*49.f;
        float mean = s1/cnt;
        float var  = sq/cnt - mean*mean;
        mg[t] = mean;
        rg[t] = rsqrtf(var + 1e-5f);
    }
    __syncthreads();
    if (t < 24) {
        float A = rg[t>>3]*gs[t];
        g_ab1[(b*24 + t)*2]     = A;
        g_ab1[(b*24 + t)*2 + 1] = gb[t] - mg[t>>3]*A;
    }
}

// ---------------- stats finalize (gn2/gn3) ----------------
__global__ void k_stats_final(const float* __restrict__ gs, const float* __restrict__ gb,
                              float* __restrict__ ab, const float* __restrict__ part,
                              int G, int npart) {
    int b = blockIdx.x / G, g = blockIdx.x % G;
    const float* p = part + (size_t)(b*G + g)*npart*2;
    float sm = 0.f, sq = 0.f;
    for (int i = threadIdx.x; i < npart; i += 256) { sm += p[2*i]; sq += p[2*i+1]; }
    __shared__ float rs[256], rq[256];
    __shared__ float mean_s, rstd_s;
    int t = threadIdx.x;
    rs[t] = sm; rq[t] = sq;
    __syncthreads();
    for (int st = 128; st; st >>= 1) {
        if (t < st) { rs[t] += rs[t+st]; rq[t] += rq[t+st]; }
        __syncthreads();
    }
    if (!t) {
        float cnt  = 8.f * 3136.f * 49.f;
        float mean = rs[0] / cnt;
        float var  = rq[0] / cnt - mean*mean;
        mean_s = mean;
        rstd_s = rsqrtf(var + 1e-5f);
    }
    __syncthreads();
    if (t < 8) {
        int c = g*8 + t;
        float A = rstd_s * gs[c];
        int CH = G*8;
        ab[(b*CH + c)*2]     = A;
        ab[(b*CH + c)*2 + 1] = gb[c] - mean_s*A;
    }
}

// ---------------- 7. pass B: expand+dw -> store dwout + gn2 partials ----------------
#define B_AT  0
#define B_HID 7056
#define B_EW  14416
#define B_AB  14608
#define B_RED 14656
#define B_TOT (14656 + 1536)
#define B_SMEM (B_TOT*4)
__global__ __launch_bounds__(256) void k_dw_gn2(const float* __restrict__ dw_w,
                                                const float* __restrict__ expand_w) {
    extern __shared__ float sm[];
    float* at  = sm + B_AT;
    float* ew  = sm + B_EW;
    float* ab  = sm + B_AB;
    float* red = sm + B_RED;
    int nt = blockIdx.x, b = blockIdx.y, t = threadIdx.x;
    int w = t >> 5, lane = t & 31;
    float* hid = sm + B_HID + w*920;
    int n0 = nt * 16;
    if (t < 192) ew[t] = expand_w[t];
    if (t >= 192 && t < 240) ab[t-192] = g_ab1[b*48 + (t-192)];
    for (int i = t; i < 18*392; i += 256) {
        int r = i / 392, m = i - r*392;
        int n = n0 - 1 + r;
        at[i] = (n >= 0 && n < 3136) ? g_attn[((size_t)b*3136 + n)*392 + m] : 0.f;
    }
    __syncthreads();
    float sk[3] = {0,0,0}, qk[3] = {0,0,0};
    #pragma unroll
    for (int k = 0; k < 3; k++) {
        int c = w + k*8;
        float A1 = ab[c*2], B1 = ab[c*2+1];
        const float* wp = ew + c*8;
        for (int i = lane; i < 918; i += 32) {
            int r = i / 51, mm = i - r*51;
            int n = n0 - 1 + r;
            float v = 0.f;
            if (mm >= 1 && mm <= 49 && n >= 0 && n < 3136) {
                const float* sp = at + r*392 + (mm - 1);
                float hsum = 0.f;
                #pragma unroll
                for (int hh = 0; hh < 8; hh++) hsum += sp[hh*49] * wp[hh];
                v = swishf(A1*hsum + B1);
            }
            hid[i] = v;
        }
        __syncwarp();
        float lw[9];
        #pragma unroll
        for (int i = 0; i < 9; i++) lw[i] = dw_w[c*9 + i];
        for (int o = lane; o < 784; o += 32) {
            int ny = o / 49, m = o - ny*49;
            float a = 0.f;
            #pragma unroll
            for (int dy = 0; dy < 3; dy++)
                #pragma unroll
                for (int dx = 0; dx < 3; dx++)
                    a += hid[(ny+dy)*51 + m+dx] * lw[dy*3+dx];
            g_dwout[(((size_t)b*3136 + n0 + ny)*24 + c)*49 + m] = a;
            sk[k] += a; qk[k] += a*a;
        }
        __syncwarp();
    }
    #pragma unroll
    for (int g = 0; g < 3; g++) { red[g*256 + t] = sk[g]; red[(3+g)*256 + t] = qk[g]; }
    __syncthreads();
    for (int st = 128; st; st >>= 1) {
        if (t < st)
            #pragma unroll
            for (int g = 0; g < 6; g++) red[g*256 + t] += red[g*256 + t + st];
        __syncthreads();
    }
    if (t < 3) {
        g_part2[((b*3 + t)*196 + nt)*2]     = red[t*256];
        g_part2[((b*3 + t)*196 + nt)*2 + 1] = red[(t+3)*256];
    }
}

// ---------------- 8. pass C (slim): dwout -> norm2+swish -> reduce -> attnF + gn3 ----------------
#define C2_DWS 0
#define C2_RW  9408
#define C2_AB  9600
#define C2_RED 9648
#define C2_SMEM ((9648 + 512)*4)
__global__ __launch_bounds__(256) void k_dla_out(const float* __restrict__ reduce_w) {
    extern __shared__ float sm[];
    float* dws = sm + C2_DWS;   // [8n][24c][49m] with norm2+swish applied
    float* rw  = sm + C2_RW;
    float* ab  = sm + C2_AB;
    float* red = sm + C2_RED;
    int nt = blockIdx.x, b = blockIdx.y, t = threadIdx.x;
    int n0 = nt * 8;
    if (t < 192) rw[t] = reduce_w[t];
    if (t >= 192 && t < 240) ab[t-192] = g_ab2[b*48 + (t-192)];
    __syncthreads();
    const float* src = g_dwout + ((size_t)b*3136 + n0)*24*49;
    for (int i = t; i < 8*24*49; i += 256) {
        int c = (i / 49) - (i / 1176)*24;
        dws[i] = swishf(ab[c*2]*src[i] + ab[c*2+1]);
    }
    __syncthreads();
    float lsum = 0.f, lsq = 0.f;
    for (int o = t; o < 392; o += 256) {
        int ny = o / 49, m = o - ny*49;
        int n = n0 + ny;
        float in[24];
        #pragma unroll
        for (int c = 0; c < 24; c++) in[c] = dws[(ny*24 + c)*49 + m];
        size_t ob = ((size_t)b*3136 + n)*392 + m;
        #pragma unroll
        for (int h = 0; h < 8; h++) {
            float r = 0.f;
            #pragma unroll
            for (int c = 0; c < 24; c++) r += in[c] * rw[h*24 + c];
            __nv_bfloat16 hh, ll; bsplit(r, hh, ll);
            g_ath[ob + h*49] = hh;
            g_atl[ob + h*49] = ll;
            lsum += r; lsq += r*r;
        }
    }
    red[t] = lsum; red[256 + t] = lsq;
    __syncthreads();
    for (int st = 128; st; st >>= 1) {
        if (t < st) { red[t] += red[t+st]; red[256+t] += red[256+t+st]; }
        __syncthreads();
    }
    if (!t) {
        g_part3[(b*392 + nt)*2]     = red[0];
        g_part3[(b*392 + nt)*2 + 1] = red[256];
    }
}

// ---------------- 9. GEMM2 (bf16x3 mma.sync) ----------------
#define G2_BUF 15360
#define G2_AH 0
#define G2_AL 5120
#define G2_BH 10240
#define G2_BL 12800
#define G2_SMEM (G2_BUF*2*2)
__device__ __forceinline__ void g2_load(uint32_t sb, int b, int nt0, int ct0,
                                        int kt, int p, int t) {
    int k0 = kt*32;
    uint32_t base = sb + (uint32_t)p*G2_BUF*2;
    #pragma unroll
    for (int rr = 0; rr < 2; rr++) {
        int idx = t + rr*256;
        int row = idx >> 2, q = idx & 3;
        int n = nt0 + row, j0 = k0 + q*8;
        bool v = (n < 3136) && (j0 < 392);
        size_t e = ((size_t)b*3136 + (n < 3136 ? n : 0))*392 + (j0 < 392 ? j0 : 0);
        uint32_t doff = (uint32_t)(row*40 + q*8)*2;
        cpa16(base + G2_AH*2 + doff, g_ath + e, v);
        cpa16(base + G2_AL*2 + doff, g_atl + e, v);
    }
    {
        int idx = t;
        int row = idx >> 2, q = idx & 3;
        int c = ct0 + row, j0 = k0 + q*8;
        bool v = j0 < 392;
        size_t e = ((size_t)b*512 + c)*392 + (v ? j0 : 0);
        uint32_t doff = (uint32_t)(row*40 + q*8)*2;
        cpa16(base + G2_BH*2 + doff, g_wvh + e, v);
        cpa16(base + G2_BL*2 + doff, g_wvl + e, v);
    }
}

__global__ __launch_bounds__(256) void k_gemm2_mma(float* __restrict__ out) {
    extern __shared__ __nv_bfloat16 dsm2[];
    uint32_t sb = smem_u32(dsm2);
    int b = blockIdx.z, nt0 = blockIdx.y*128, ct0 = blockIdx.x*64;
    int t = threadIdx.x, w = t >> 5, lane = t & 31;
    int wn = (w & 3)*32, wc = (w >> 2)*32;
    float acc[2][4][4];
    #pragma unroll
    for (int i = 0; i < 2; i++)
        #pragma unroll
        for (int j = 0; j < 4; j++)
            #pragma unroll
            for (int k = 0; k < 4; k++) acc[i][j][k] = 0.f;

    g2_load(sb, b, nt0, ct0, 0, 0, t);
    cp_commit();
    for (int kt = 0; kt < 13; kt++) {
        if (kt < 12) {
            g2_load(sb, b, nt0, ct0, kt+1, (kt+1) & 1, t);
            cp_commit();
            cp_wait1();
        } else cp_wait0();
        __syncthreads();
        uint32_t base = sb + (uint32_t)(kt & 1)*G2_BUF*2;
        #pragma unroll
        for (int kk = 0; kk < 2; kk++) {
            int kb = kk*16;
            uint32_t ah[2][4], al[2][4];
            #pragma unroll
            for (int mt = 0; mt < 2; mt++) {
                int row = wn + mt*16 + (lane & 15);
                int col = kb + ((lane & 16) ? 8 : 0);
                uint32_t off = (uint32_t)(row*40 + col)*2;
                ldm_x4(ah[mt], base + G2_AH*2 + off);
                ldm_x4(al[mt], base + G2_AL*2 + off);
            }
            uint32_t bh[4][2], bl[4][2];
            #pragma unroll
            for (int p = 0; p < 2; p++) {
                int crow = wc + p*16 + (lane & 7) + ((lane & 16) ? 8 : 0);
                int col = kb + ((lane & 8) ? 8 : 0);
                uint32_t off = (uint32_t)(crow*40 + col)*2;
                uint32_t r4[4];
                ldm_x4(r4, base + G2_BH*2 + off);
                bh[2*p][0]=r4[0]; bh[2*p][1]=r4[1]; bh[2*p+1][0]=r4[2]; bh[2*p+1][1]=r4[3];
                ldm_x4(r4, base + G2_BL*2 + off);
                bl[2*p][0]=r4[0]; bl[2*p][1]=r4[1]; bl[2*p+1][0]=r4[2]; bl[2*p+1][1]=r4[3];
            }
            #pragma unroll
            for (int mt = 0; mt < 2; mt++)
                #pragma unroll
                for (int ct = 0; ct < 4; ct++) {
                    mma_bf16(acc[mt][ct], ah[mt], bh[ct]);
                    mma_bf16(acc[mt][ct], al[mt], bh[ct]);
                    mma_bf16(acc[mt][ct], ah[mt], bl[ct]);
                }
        }
        __syncthreads();
    }
    int nrow = nt0 + wn + (lane >> 2);
    #pragma unroll
    for (int mt = 0; mt < 2; mt++) {
        #pragma unroll
        for (int ct = 0; ct < 4; ct++) {
            int c0 = ct0 + wc + ct*8 + ((lane & 3) << 1);
            float b0 = g_bias2[b*512 + c0];
            float b1 = g_bias2[b*512 + c0 + 1];
            #pragma unroll
            for (int half = 0; half < 2; half++) {
                int n = nrow + mt*16 + half*8;
                if (n < 3136) {
                    size_t o = ((size_t)b*3136 + n)*512 + c0;
                    *(float2*)&out[o] = make_float2(acc[mt][ct][half*2] + b0,
                                                    acc[mt][ct][half*2+1] + b1);
                }
            }
        }
    }
}

// ---------------- launcher ----------------
extern "C" void kernel_launch(void* const* d_in, const int* in_sizes, int n_in,
                              void* d_out, int out_size) {
    const float* x        = (const float*)d_in[0];
    const float* q_w      = (const float*)d_in[1];
    const float* down_w   = (const float*)d_in[2];
    const float* kv_w     = (const float*)d_in[3];
    const float* proj_w   = (const float*)d_in[4];
    const float* proj_b   = (const float*)d_in[5];
    const float* rel_bias = (const float*)d_in[6];
    const float* expand_w = (const float*)d_in[7];
    const float* gn1_s    = (const float*)d_in[8];
    const float* gn1_b    = (const float*)d_in[9];
    const float* dw_w     = (const float*)d_in[10];
    const float* gn2_s    = (const float*)d_in[11];
    const float* gn2_b    = (const float*)d_in[12];
    const float* reduce_w = (const float*)d_in[13];
    const float* gn3_s    = (const float*)d_in[14];
    const float* gn3_b    = (const float*)d_in[15];
    float* out = (float*)d_out;

    float *ab2, *ab3, *p2, *p3;
    cudaGetSymbolAddress((void**)&ab2, g_ab2);
    cudaGetSymbolAddress((void**)&ab3, g_ab3);
    cudaGetSymbolAddress((void**)&p2, g_part2);
    cudaGetSymbolAddress((void**)&p3, g_part3);

    cudaFuncSetAttribute(k_gemm1_fused, cudaFuncAttributeMaxDynamicSharedMemorySize, G1_SMEM);
    cudaFuncSetAttribute(k_gemm2_mma, cudaFuncAttributeMaxDynamicSharedMemorySize, G2_SMEM);
    cudaFuncSetAttribute(k_dw_gn2,    cudaFuncAttributeMaxDynamicSharedMemorySize, B_SMEM);
    cudaFuncSetAttribute(k_dla_out,   cudaFuncAttributeMaxDynamicSharedMemorySize, C2_SMEM);

    k_xsplit<<<dim3(98, 16, BB), 256>>>(x);
    k_down<<<BB*CCH, 256>>>(x, down_w);
    k_kv  <<<dim3(4, 7, BB), 256>>>(kv_w);
    k_wqk_split<<<dim3(2, 8, BB), 256>>>(q_w);
    k_wvp <<<dim3(7, 8, BB), 256>>>(proj_w);
    k_gemm1_fused<<<dim3(49, BB), 256, G1_SMEM>>>(rel_bias);
    k_gn1_final<<<BB, 64>>>(gn1_s, gn1_b, expand_w);
    k_dw_gn2<<<dim3(196, BB), 256, B_SMEM>>>(dw_w, expand_w);
    k_stats_final<<<BB*3, 256>>>(gn2_s, gn2_b, ab2, p2, 3, 196);
    k_dla_out<<<dim3(392, BB), 256, C2_SMEM>>>(reduce_w);
    k_stats_final<<<BB, 256>>>(gn3_s, gn3_b, ab3, p3, 1, 392);
    k_wvpsplit<<<dim3(13, 16, BB), 256>>>();
    k_wvpbias<<<BB, 512>>>(proj_b);
    k_gemm2_mma<<<dim3(8, 25, BB), 256, G2_SMEM>>>(out);
}

// round 9
// speedup vs baseline: 1.0063x; 1.0063x over previous
#include <cuda_runtime.h>
#include <cuda_bf16.h>
#include <math.h>
#include <stdint.h>

#define BB    16
#define CCH   512
#define NN    3136
#define NKK   49
#define HEADS 8
#define JJ    392
#define HIDC  24
#define SCALE 0.125f

// ---------------- device scratch ----------------
__device__ float g_kvx[BB*NKK*CCH];
__device__ float g_kv [BB*NKK*1024];
__device__ float g_Wvp[BB*JJ*CCH];
__device__ __nv_bfloat16 g_xTh[(size_t)BB*NN*CCH];
__device__ __nv_bfloat16 g_xTl[(size_t)BB*NN*CCH];
__device__ __nv_bfloat16 g_wqh[BB*JJ*CCH];
__device__ __nv_bfloat16 g_wql[BB*JJ*CCH];
__device__ __nv_bfloat16 g_wvh[BB*CCH*JJ];
__device__ __nv_bfloat16 g_wvl[BB*CCH*JJ];
__device__ float g_attn[(size_t)BB*NN*JJ];
__device__ __nv_bfloat16 g_ath[(size_t)BB*NN*JJ];
__device__ __nv_bfloat16 g_atl[(size_t)BB*NN*JJ];
__device__ float g_part1[BB*49*36];
__device__ float g_part2[BB*3*196*2];
__device__ float g_part3[BB*392*2];
__device__ float g_ab1[BB*HIDC*2];
__device__ float g_ab2[BB*HIDC*2];
__device__ float g_ab3[BB*HEADS*2];
__device__ float g_bias2[BB*CCH];

__device__ __forceinline__ float swishf(float x) { return x / (1.f + __expf(-x)); }

__device__ __forceinline__ void bsplit(float v, __nv_bfloat16& h, __nv_bfloat16& l) {
    h = __float2bfloat16(v);
    l = __float2bfloat16(v - __bfloat162float(h));
}

__device__ __forceinline__ uint32_t smem_u32(const void* p) {
    uint32_t a;
    asm("{ .reg .u64 t; cvta.to.shared.u64 t, %1; cvt.u32.u64 %0, t; }" : "=r"(a) : "l"(p));
    return a;
}
__device__ __forceinline__ void ldm_x4(uint32_t* r, uint32_t addr) {
    asm volatile("ldmatrix.sync.aligned.m8n8.x4.shared.b16 {%0,%1,%2,%3}, [%4];"
        : "=r"(r[0]), "=r"(r[1]), "=r"(r[2]), "=r"(r[3]) : "r"(addr));
}
__device__ __forceinline__ void ldm_x2(uint32_t* r, uint32_t addr) {
    asm volatile("ldmatrix.sync.aligned.m8n8.x2.shared.b16 {%0,%1}, [%2];"
        : "=r"(r[0]), "=r"(r[1]) : "r"(addr));
}
__device__ __forceinline__ void mma_bf16(float* c, const uint32_t* a, const uint32_t* b) {
    asm volatile(
        "mma.sync.aligned.m16n8k16.row.col.f32.bf16.bf16.f32 "
        "{%0,%1,%2,%3}, {%4,%5,%6,%7}, {%8,%9}, {%0,%1,%2,%3};"
        : "+f"(c[0]), "+f"(c[1]), "+f"(c[2]), "+f"(c[3])
        : "r"(a[0]), "r"(a[1]), "r"(a[2]), "r"(a[3]), "r"(b[0]), "r"(b[1]));
}
__device__ __forceinline__ void cpa16(uint32_t dst, const void* src, bool v) {
    int sz = v ? 16 : 0;
    asm volatile("cp.async.cg.shared.global [%0], [%1], 16, %2;"
        :: "r"(dst), "l"(src), "r"(sz) : "memory");
}
__device__ __forceinline__ void cp_commit() {
    asm volatile("cp.async.commit_group;" ::: "memory");
}
__device__ __forceinline__ void cp_wait1() {
    asm volatile("cp.async.wait_group 1;" ::: "memory");
}
__device__ __forceinline__ void cp_wait0() {
    asm volatile("cp.async.wait_group 0;" ::: "memory");
}

// ---------------- 1. depthwise 8x8/8 downsample ----------------
__global__ void k_down(const float* __restrict__ x, const float* __restrict__ down_w) {
    int bc = blockIdx.x, c = bc & 511, b = bc >> 9;
    __shared__ float plane[3136];
    __shared__ float w[64];
    const float* xp = x + (size_t)bc * 3136;
    for (int i = threadIdx.x; i < 3136; i += 256) plane[i] = xp[i];
    if (threadIdx.x < 64) w[threadIdx.x] = down_w[c*64 + threadIdx.x];
    __syncthreads();
    if (threadIdx.x < 49) {
        int my = threadIdx.x / 7, mx = threadIdx.x % 7;
        float s = 0.f;
        #pragma unroll
        for (int i = 0; i < 8; i++)
            #pragma unroll
            for (int j = 0; j < 8; j++)
                s += plane[(my*8+i)*56 + mx*8 + j] * w[i*8+j];
        g_kvx[(b*49 + threadIdx.x)*512 + c] = s;
    }
}

// ---------------- 2. kv = kvx @ kv_w ----------------
__global__ void k_kv(const float* __restrict__ kv_w) {
    int b = blockIdx.z, m0 = blockIdx.y * 7, oc = blockIdx.x;
    __shared__ float a[7][512];
    for (int i = threadIdx.x; i < 7*512; i += 256)
        a[i >> 9][i & 511] = g_kvx[(b*49 + m0 + (i >> 9))*512 + (i & 511)];
    __syncthreads();
    int o = oc*256 + threadIdx.x;
    float acc[7] = {0,0,0,0,0,0,0};
    for (int c = 0; c < 512; c++) {
        float w = kv_w[c*1024 + o];
        #pragma unroll
        for (int mm = 0; mm < 7; mm++) acc[mm] += a[mm][c] * w;
    }
    #pragma unroll
    for (int mm = 0; mm < 7; mm++)
        g_kv[(b*49 + m0 + mm)*1024 + o] = acc[mm];
}

// ---------------- 3. Wqk fused compute + bf16 split ----------------
__global__ __launch_bounds__(256) void k_wqk_split(const float* __restrict__ q_w) {
    int half = blockIdx.x, h = blockIdx.y, b = blockIdx.z;
    __shared__ float ks[49][64];
    for (int i = threadIdx.x; i < 49*64; i += 256)
        ks[i >> 6][i & 63] = g_kv[(b*49 + (i >> 6))*1024 + h*64 + (i & 63)];
    __syncthreads();
    int cin = half*256 + threadIdx.x;
    float acc[49];
    #pragma unroll
    for (int m = 0; m < 49; m++) acc[m] = 0.f;
    const float4* q4 = (const float4*)(q_w + (size_t)cin*512 + h*64);
    const float4* ks4 = (const float4*)&ks[0][0];
    for (int d4 = 0; d4 < 16; d4++) {
        float4 q = __ldg(q4 + d4);
        #pragma unroll
        for (int m = 0; m < 49; m++) {
            float4 k = ks4[m*16 + d4];
            acc[m] += q.x*k.x + q.y*k.y + q.z*k.z + q.w*k.w;
        }
    }
    size_t obase = ((size_t)b*392 + h*49)*512 + cin;
    #pragma unroll
    for (int m = 0; m < 49; m++) {
        float v = acc[m] * SCALE;
        __nv_bfloat16 hh, ll; bsplit(v, hh, ll);
        g_wqh[obase + (size_t)m*512] = hh;
        g_wql[obase + (size_t)m*512] = ll;
    }
}

// ---------------- 4. Wvp ----------------
__global__ void k_wvp(const float* __restrict__ proj_w) {
    int b = blockIdx.z, h = blockIdx.y, mc = blockIdx.x * 7;
    __shared__ float vs[7][64];
    for (int i = threadIdx.x; i < 7*64; i += 256)
        vs[i >> 6][i & 63] = g_kv[(b*49 + mc + (i >> 6))*1024 + 512 + h*64 + (i & 63)];
    __syncthreads();
    int t = threadIdx.x;
    float acc[7][2] = {{0}};
    for (int d = 0; d < 64; d++) {
        float w0 = proj_w[(h*64+d)*512 + t];
        float w1 = proj_w[(h*64+d)*512 + 256 + t];
        #pragma unroll
        for (int mm = 0; mm < 7; mm++) {
            float vv = vs[mm][d];
            acc[mm][0] += vv * w0;
            acc[mm][1] += vv * w1;
        }
    }
    #pragma unroll
    for (int mm = 0; mm < 7; mm++) {
        int j = h*49 + mc + mm;
        g_Wvp[(b*392 + j)*512 + t]       = acc[mm][0];
        g_Wvp[(b*392 + j)*512 + 256 + t] = acc[mm][1];
    }
}

// ---------------- 4b. transpose+split x ----------------
__global__ void k_xsplit(const float* __restrict__ x) {
    int tn = blockIdx.x, tc = blockIdx.y, b = blockIdx.z;
    __shared__ float tile[32][33];
    int a = threadIdx.x >> 5, q = threadIdx.x & 31;
    #pragma unroll
    for (int r = 0; r < 4; r++) {
        int cc = tc*32 + a + r*8, nn = tn*32 + q;
        tile[a + r*8][q] = x[((size_t)b*512 + cc)*3136 + nn];
    }
    __syncthreads();
    #pragma unroll
    for (int r = 0; r < 4; r++) {
        int nn = tn*32 + a + r*8, cc = tc*32 + q;
        float v = tile[q][a + r*8];
        __nv_bfloat16 h, l; bsplit(v, h, l);
        size_t o = ((size_t)b*3136 + nn)*512 + cc;
        g_xTh[o] = h; g_xTl[o] = l;
    }
}

// ---------------- 4d. transpose+scale+split Wvp ----------------
__global__ void k_wvpsplit(void) {
    int tj = blockIdx.x, tc = blockIdx.y, b = blockIdx.z;
    __shared__ float tile[32][33];
    int a = threadIdx.x >> 5, q = threadIdx.x & 31;
    #pragma unroll
    for (int r = 0; r < 4; r++) {
        int jj = tj*32 + a + r*8, cc = tc*32 + q;
        float v = 0.f;
        if (jj < 392) v = g_Wvp[((size_t)b*392 + jj)*512 + cc] * g_ab3[(b*8 + jj/49)*2];
        tile[a + r*8][q] = v;
    }
    __syncthreads();
    #pragma unroll
    for (int r = 0; r < 4; r++) {
        int cc = tc*32 + a + r*8, jj = tj*32 + q;
        if (jj < 392) {
            float v = tile[q][a + r*8];
            __nv_bfloat16 h, l; bsplit(v, h, l);
            size_t o = ((size_t)b*512 + cc)*392 + jj;
            g_wvh[o] = h; g_wvl[o] = l;
        }
    }
}

// ---------------- 4e. bias2 ----------------
__global__ void k_wvpbias(const float* __restrict__ proj_b) {
    int b = blockIdx.x, c = threadIdx.x;
    float acc = 0.f;
    for (int j = 0; j < 392; j++)
        acc += g_ab3[(b*8 + j/49)*2 + 1] * g_Wvp[((size_t)b*392 + j)*512 + c];
    g_bias2[b*512 + c] = acc + proj_b[c];
}

// ---------------- 5. GEMM1 fused: k-tile 16, double-buffered, 2 CTAs/SM ----------------
// per-buffer layout (bytes): Ah 0, Al 3072, Bh 6144, Bl 26112; buffer size 46080
#define G1_BUFSZ 46080u
#define G1_AH 0u
#define G1_AL 3072u
#define G1_BH 6144u
#define G1_BL 26112u
#define G1_SMEM 103552
__device__ __forceinline__ void g1f_load(uint32_t sb, int b, int nt0, int kt, int p, int t) {
    int k0 = kt*16;
    uint32_t base = sb + (uint32_t)p*G1_BUFSZ;
    {   // A: 64 rows x 2 chunks x {h,l} = 256 ops, one per thread
        int hl = t >= 128;
        int ii = t - hl*128;
        int row = ii >> 1, q = ii & 1;
        size_t e = ((size_t)b*3136 + nt0 + row)*512 + k0 + q*8;
        uint32_t doff = (uint32_t)(row*48 + q*16);
        cpa16(base + (hl ? G1_AL : G1_AH) + doff, (hl ? g_xTl : g_xTh) + e, true);
    }
    #pragma unroll
    for (int rr = 0; rr < 7; rr++) {   // B: 416 rows x 2 chunks x {h,l} = 1664 ops
        int idx = rr*256 + t;
        if (idx < 1664) {
            int hl = idx >= 832;
            int ii = idx - hl*832;
            int row = ii >> 1, q = ii & 1;
            bool v = row < 392;
            size_t e = ((size_t)b*392 + (v ? row : 0))*512 + k0 + q*8;
            uint32_t doff = (uint32_t)(row*48 + q*16);
            cpa16(base + (hl ? G1_BL : G1_BH) + doff, (hl ? g_wql : g_wqh) + e, v);
        }
    }
}

__global__ __launch_bounds__(256) void k_gemm1_fused(const float* __restrict__ rel_bias) {
    extern __shared__ char smraw[];
    uint32_t sb = smem_u32(smraw);
    int b = blockIdx.y, nt0 = blockIdx.x * 64;
    int t = threadIdx.x, w = t >> 5, lane = t & 31;
    int wn = (w & 1)*32, wj = (w >> 1)*104;
    float acc[2][13][4];
    #pragma unroll
    for (int i = 0; i < 2; i++)
        #pragma unroll
        for (int j = 0; j < 13; j++)
            #pragma unroll
            for (int k = 0; k < 4; k++) acc[i][j][k] = 0.f;

    g1f_load(sb, b, nt0, 0, 0, t);
    cp_commit();
    for (int kt = 0; kt < 32; kt++) {
        if (kt < 31) {
            g1f_load(sb, b, nt0, kt+1, (kt+1) & 1, t);
            cp_commit();
            cp_wait1();
        } else cp_wait0();
        __syncthreads();
        uint32_t base = sb + (uint32_t)(kt & 1)*G1_BUFSZ;
        uint32_t ah[2][4], al[2][4];
        int arow = wn + (lane & 15);
        int acol = (lane & 16) ? 8 : 0;
        ldm_x4(ah[0], base + G1_AH + (uint32_t)(arow*48 + acol*2));
        ldm_x4(ah[1], base + G1_AH + (uint32_t)((arow+16)*48 + acol*2));
        ldm_x4(al[0], base + G1_AL + (uint32_t)(arow*48 + acol*2));
        ldm_x4(al[1], base + G1_AL + (uint32_t)((arow+16)*48 + acol*2));
        #pragma unroll
        for (int p2 = 0; p2 < 6; p2++) {
            int jrow = wj + p2*16 + (lane & 7) + ((lane & 16) ? 8 : 0);
            int col = (lane & 8) ? 8 : 0;
            uint32_t off = (uint32_t)(jrow*48 + col*2);
            uint32_t rh[4], rl[4];
            ldm_x4(rh, base + G1_BH + off);
            ldm_x4(rl, base + G1_BL + off);
            #pragma unroll
            for (int mt = 0; mt < 2; mt++)
                #pragma unroll
                for (int e = 0; e < 2; e++) {
                    mma_bf16(acc[mt][2*p2+e], ah[mt], &rh[2*e]);
                    mma_bf16(acc[mt][2*p2+e], al[mt], &rh[2*e]);
                    mma_bf16(acc[mt][2*p2+e], ah[mt], &rl[2*e]);
                }
        }
        {
            int jrow = wj + 96 + (lane & 7);
            int col = (lane & 8) ? 8 : 0;
            uint32_t off = (uint32_t)(jrow*48 + col*2);
            uint32_t bh2[2], bl2[2];
            ldm_x2(bh2, base + G1_BH + off);
            ldm_x2(bl2, base + G1_BL + off);
            #pragma unroll
            for (int mt = 0; mt < 2; mt++) {
                mma_bf16(acc[mt][12], ah[mt], bh2);
                mma_bf16(acc[mt][12], al[mt], bh2);
                mma_bf16(acc[mt][12], ah[mt], bl2);
            }
        }
        __syncthreads();
    }
    // ---- epilogue: stage logits in SMEM ----
    float* S = (float*)smraw;            // [64][400]
    float* Gred = S + 64*400;            // [8][36]
    #pragma unroll
    for (int mt = 0; mt < 2; mt++) {
        int nl = wn + mt*16 + (lane >> 2);
        #pragma unroll
        for (int jt = 0; jt < 13; jt++) {
            int j0 = wj + jt*8 + ((lane & 3) << 1);
            if (j0 < 392) {
                S[nl*400 + j0]       = acc[mt][jt][0];
                S[nl*400 + j0 + 1]   = acc[mt][jt][1];
                S[(nl+8)*400 + j0]   = acc[mt][jt][2];
                S[(nl+8)*400 + j0+1] = acc[mt][jt][3];
            }
        }
    }
    __syncthreads();
    // ---- softmax per (n,h) row, adding rel_bias ----
    #pragma unroll
    for (int rr = 0; rr < 2; rr++) {
        int row = t + rr*256;
        int n = row >> 3, h = row & 7;
        float* p = S + n*400 + h*49;
        const float* rb = rel_bias + (size_t)(nt0 + n)*49;
        float mx = -1e30f;
        for (int i = 0; i < 49; i++) {
            float lv = p[i] + __ldg(rb + i);
            p[i] = lv;
            mx = fmaxf(mx, lv);
        }
        float sum = 0.f;
        for (int i = 0; i < 49; i++) { float e = __expf(p[i] - mx); p[i] = e; sum += e; }
        float inv = 1.f / sum;
        for (int i = 0; i < 49; i++) p[i] *= inv;
    }
    __syncthreads();
    // ---- Gram partials ----
    float g[36];
    #pragma unroll
    for (int k = 0; k < 36; k++) g[k] = 0.f;
    for (int pos = t; pos < 64*49; pos += 256) {
        int n = pos / 49, m = pos - n*49;
        float a[8];
        #pragma unroll
        for (int h = 0; h < 8; h++) a[h] = S[n*400 + h*49 + m];
        int k = 0;
        #pragma unroll
        for (int h = 0; h < 8; h++)
            #pragma unroll
            for (int h2 = h; h2 < 8; h2++) { g[k] += a[h]*a[h2]; k++; }
    }
    size_t ob = ((size_t)b*3136 + nt0)*392;
    for (int i = t; i < 64*392; i += 256) {
        int n = i / 392, c = i - n*392;
        g_attn[ob + i] = S[n*400 + c];
    }
    #pragma unroll
    for (int s = 16; s; s >>= 1)
        #pragma unroll
        for (int k = 0; k < 36; k++) g[k] += __shfl_xor_sync(0xffffffffu, g[k], s);
    if (lane == 0)
        #pragma unroll
        for (int k = 0; k < 36; k++) Gred[w*36 + k] = g[k];
    __syncthreads();
    if (t < 36) {
        float s = 0.f;
        #pragma unroll
        for (int ww = 0; ww < 8; ww++) s += Gred[ww*36 + t];
        g_part1[((size_t)b*49 + blockIdx.x)*36 + t] = s;
    }
}

// ---------------- 6. gn1 finalize from Gram ----------------
__global__ void k_gn1_final(const float* __restrict__ gs, const float* __restrict__ gb,
                            const float* __restrict__ ew) {
    int b = blockIdx.x, t = threadIdx.x;   // 64 threads
    __shared__ float M36[36];
    __shared__ float Mf[64];
    __shared__ float s1s[24], sqs[24];
    __shared__ float mg[3], rg[3];
    if (t < 36) {
        float s = 0.f;
        for (int nt = 0; nt < 49; nt++) s += g_part1[((size_t)b*49 + nt)*36 + t];
        M36[t] = s;
    }
    __syncthreads();
    if (t == 0) {
        int k = 0;
        for (int h = 0; h < 8; h++)
            for (int h2 = h; h2 < 8; h2++) { Mf[h*8+h2] = M36[k]; Mf[h2*8+h] = M36[k]; k++; }
    }
    __syncthreads();
    if (t < 24) {
        float wv[8], sw = 0.f;
        #pragma unroll
        for (int h = 0; h < 8; h++) { wv[h] = ew[t*8+h]; sw += wv[h]; }
        float sq = 0.f;
        #pragma unroll
        for (int h = 0; h < 8; h++)
            #pragma unroll
            for (int h2 = 0; h2 < 8; h2++) sq += wv[h]*wv[h2]*Mf[h*8+h2];
        s1s[t] = 3136.f * sw;
        sqs[t] = sq;
    }
    __syncthreads();
    if (t < 3) {
        float s1 = 0.f, sq = 0.f;
        for (int c = 0; c < 8; c++) { s1 += s1s[t*8+c]; sq += sqs[t*8+c]; }
        float cnt = 8.f*3136.f*49.f;
        float mean = s1/cnt;
        float var  = sq/cnt - mean*mean;
        mg[t] = mean;
        rg[t] = rsqrtf(var + 1e-5f);
    }
    __syncthreads();
    if (t < 24) {
        float A = rg[t>>3]*gs[t];
        g_ab1[(b*24 + t)*2]     = A;
        g_ab1[(b*24 + t)*2 + 1] = gb[t] - mg[t>>3]*A;
    }
}

// ---------------- stats finalize (gn2/gn3) ----------------
__global__ void k_stats_final(const float* __restrict__ gs, const float* __restrict__ gb,
                              float* __restrict__ ab, const float* __restrict__ part,
                              int G, int npart) {
    int b = blockIdx.x / G, g = blockIdx.x % G;
    const float* p = part + (size_t)(b*G + g)*npart*2;
    float sm = 0.f, sq = 0.f;
    for (int i = threadIdx.x; i < npart; i += 256) { sm += p[2*i]; sq += p[2*i+1]; }
    __shared__ float rs[256], rq[256];
    __shared__ float mean_s, rstd_s;
    int t = threadIdx.x;
    rs[t] = sm; rq[t] = sq;
    __syncthreads();
    for (int st = 128; st; st >>= 1) {
        if (t < st) { rs[t] += rs[t+st]; rq[t] += rq[t+st]; }
        __syncthreads();
    }
    if (!t) {
        float cnt  = 8.f * 3136.f * 49.f;
        float mean = rs[0] / cnt;
        float var  = rq[0] / cnt - mean*mean;
        mean_s = mean;
        rstd_s = rsqrtf(var + 1e-5f);
    }
    __syncthreads();
    if (t < 8) {
        int c = g*8 + t;
        float A = rstd_s * gs[c];
        int CH = G*8;
        ab[(b*CH + c)*2]     = A;
        ab[(b*CH + c)*2 + 1] = gb[c] - mean_s*A;
    }
}

// ---------------- 7. pass B: warp-parallel expand+dw -> gn2 partials ----------------
#define B_AT  0
#define B_HID 7056
#define B_EW  14416
#define B_AB  14608
#define B_RED 14656
#define B_TOT (14656 + 1536)
#define B_SMEM (B_TOT*4)
__global__ __launch_bounds__(256) void k_dw_gn2(const float* __restrict__ dw_w,
                                                const float* __restrict__ expand_w) {
    extern __shared__ float sm[];
    float* at  = sm + B_AT;
    float* ew  = sm + B_EW;
    float* ab  = sm + B_AB;
    float* red = sm + B_RED;
    int nt = blockIdx.x, b = blockIdx.y, t = threadIdx.x;
    int w = t >> 5, lane = t & 31;
    float* hid = sm + B_HID + w*920;
    int n0 = nt * 16;
    if (t < 192) ew[t] = expand_w[t];
    if (t >= 192 && t < 240) ab[t-192] = g_ab1[b*48 + (t-192)];
    for (int i = t; i < 18*392; i += 256) {
        int r = i / 392, m = i - r*392;
        int n = n0 - 1 + r;
        at[i] = (n >= 0 && n < 3136) ? g_attn[((size_t)b*3136 + n)*392 + m] : 0.f;
    }
    __syncthreads();
    float sk[3] = {0,0,0}, qk[3] = {0,0,0};
    #pragma unroll
    for (int k = 0; k < 3; k++) {
        int c = w + k*8;
        float A1 = ab[c*2], B1 = ab[c*2+1];
        const float* wp = ew + c*8;
        for (int i = lane; i < 918; i += 32) {
            int r = i / 51, mm = i - r*51;
            int n = n0 - 1 + r;
            float v = 0.f;
            if (mm >= 1 && mm <= 49 && n >= 0 && n < 3136) {
                const float* sp = at + r*392 + (mm - 1);
                float hsum = 0.f;
                #pragma unroll
                for (int hh = 0; hh < 8; hh++) hsum += sp[hh*49] * wp[hh];
                v = swishf(A1*hsum + B1);
            }
            hid[i] = v;
        }
        __syncwarp();
        float lw[9];
        #pragma unroll
        for (int i = 0; i < 9; i++) lw[i] = dw_w[c*9 + i];
        for (int o = lane; o < 784; o += 32) {
            int ny = o / 49, m = o - ny*49;
            float a = 0.f;
            #pragma unroll
            for (int dy = 0; dy < 3; dy++)
                #pragma unroll
                for (int dx = 0; dx < 3; dx++)
                    a += hid[(ny+dy)*51 + m+dx] * lw[dy*3+dx];
            sk[k] += a; qk[k] += a*a;
        }
        __syncwarp();
    }
    #pragma unroll
    for (int g = 0; g < 3; g++) { red[g*256 + t] = sk[g]; red[(3+g)*256 + t] = qk[g]; }
    __syncthreads();
    for (int st = 128; st; st >>= 1) {
        if (t < st)
            #pragma unroll
            for (int g = 0; g < 6; g++) red[g*256 + t] += red[g*256 + t + st];
        __syncthreads();
    }
    if (t < 3) {
        g_part2[((b*3 + t)*196 + nt)*2]     = red[t*256];
        g_part2[((b*3 + t)*196 + nt)*2 + 1] = red[(t+3)*256];
    }
}

// ---------------- 8. pass C: expand+dw+norm2+swish, reduce -> attnF + gn3 ----------------
#define C_AT  0
#define C_HID 3920
#define C_DWS 8016
#define C_EW  17424
#define C_RW  17616
#define C_AB  17808
#define C_RED 17904
#define C_TOT (17904 + 512)
#define C_SMEM (C_TOT*4)
__global__ __launch_bounds__(256) void k_dla_out(const float* __restrict__ dw_w,
                                                 const float* __restrict__ expand_w,
                                                 const float* __restrict__ reduce_w) {
    extern __shared__ float sm[];
    float* at  = sm + C_AT;
    float* dws = sm + C_DWS;
    float* ew  = sm + C_EW;
    float* rw  = sm + C_RW;
    float* ab  = sm + C_AB;
    float* red = sm + C_RED;
    int nt = blockIdx.x, b = blockIdx.y, t = threadIdx.x;
    int w = t >> 5, lane = t & 31;
    float* hid = sm + C_HID + w*512;
    int n0 = nt * 8;
    if (t < 192) { ew[t] = expand_w[t]; rw[t] = reduce_w[t]; }
    if (t < 96) ab[t] = (t < 48) ? g_ab1[b*48 + t] : g_ab2[b*48 + (t-48)];
    for (int i = t; i < 10*392; i += 256) {
        int r = i / 392, m = i - r*392;
        int n = n0 - 1 + r;
        at[i] = (n >= 0 && n < 3136) ? g_attn[((size_t)b*3136 + n)*392 + m] : 0.f;
    }
    __syncthreads();
    #pragma unroll
    for (int k = 0; k < 3; k++) {
        int c = w + k*8;
        float A1 = ab[c*2], B1 = ab[c*2+1];
        float A2 = ab[48 + c*2], B2 = ab[49 + c*2];
        const float* wp = ew + c*8;
        for (int i = lane; i < 510; i += 32) {
            int r = i / 51, mm = i - r*51;
            int n = n0 - 1 + r;
            float v = 0.f;
            if (mm >= 1 && mm <= 49 && n >= 0 && n < 3136) {
                const float* sp = at + r*392 + (mm - 1);
                float hsum = 0.f;
                #pragma unroll
                for (int hh = 0; hh < 8; hh++) hsum += sp[hh*49] * wp[hh];
                v = swishf(A1*hsum + B1);
            }
            hid[i] = v;
        }
        __syncwarp();
        float lw[9];
        #pragma unroll
        for (int i = 0; i < 9; i++) lw[i] = dw_w[c*9 + i];
        for (int o = lane; o < 392; o += 32) {
            int ny = o / 49, m = o - ny*49;
            float a = 0.f;
            #pragma unroll
            for (int dy = 0; dy < 3; dy++)
                #pragma unroll
                for (int dx = 0; dx < 3; dx++)
                    a += hid[(ny+dy)*51 + m+dx] * lw[dy*3+dx];
            dws[(ny*24 + c)*49 + m] = swishf(A2*a + B2);
        }
        __syncwarp();
    }
    __syncthreads();
    float lsum = 0.f, lsq = 0.f;
    for (int o = t; o < 392; o += 256) {
        int ny = o / 49, m = o - ny*49;
        int n = n0 + ny;
        float in[24];
        #pragma unroll
        for (int c = 0; c < 24; c++) in[c] = dws[(ny*24 + c)*49 + m];
        size_t ob = ((size_t)b*3136 + n)*392 + m;
        #pragma unroll
        for (int h = 0; h < 8; h++) {
            float r = 0.f;
            #pragma unroll
            for (int c = 0; c < 24; c++) r += in[c] * rw[h*24 + c];
            __nv_bfloat16 hh, ll; bsplit(r, hh, ll);
            g_ath[ob + h*49] = hh;
            g_atl[ob + h*49] = ll;
            lsum += r; lsq += r*r;
        }
    }
    red[t] = lsum; red[256 + t] = lsq;
    __syncthreads();
    for (int st = 128; st; st >>= 1) {
        if (t < st) { red[t] += red[t+st]; red[256+t] += red[256+t+st]; }
        __syncthreads();
    }
    if (!t) {
        g_part3[(b*392 + nt)*2]     = red[0];
        g_part3[(b*392 + nt)*2 + 1] = red[256];
    }
}

// ---------------- 9. GEMM2 (bf16x3 mma.sync) ----------------
#define G2_BUF 15360
#define G2_AH 0
#define G2_AL 5120
#define G2_BH 10240
#define G2_BL 12800
#define G2_SMEM (G2_BUF*2*2)
__device__ __forceinline__ void g2_load(uint32_t sb, int b, int nt0, int ct0,
                                        int kt, int p, int t) {
    int k0 = kt*32;
    uint32_t base = sb + (uint32_t)p*G2_BUF*2;
    #pragma unroll
    for (int rr = 0; rr < 2; rr++) {
        int idx = t + rr*256;
        int row = idx >> 2, q = idx & 3;
        int n = nt0 + row, j0 = k0 + q*8;
        bool v = (n < 3136) && (j0 < 392);
        size_t e = ((size_t)b*3136 + (n < 3136 ? n : 0))*392 + (j0 < 392 ? j0 : 0);
        uint32_t doff = (uint32_t)(row*40 + q*8)*2;
        cpa16(base + G2_AH*2 + doff, g_ath + e, v);
        cpa16(base + G2_AL*2 + doff, g_atl + e, v);
    }
    {
        int idx = t;
        int row = idx >> 2, q = idx & 3;
        int c = ct0 + row, j0 = k0 + q*8;
        bool v = j0 < 392;
        size_t e = ((size_t)b*512 + c)*392 + (v ? j0 : 0);
        uint32_t doff = (uint32_t)(row*40 + q*8)*2;
        cpa16(base + G2_BH*2 + doff, g_wvh + e, v);
        cpa16(base + G2_BL*2 + doff, g_wvl + e, v);
    }
}

__global__ __launch_bounds__(256) void k_gemm2_mma(float* __restrict__ out) {
    extern __shared__ __nv_bfloat16 dsm2[];
    uint32_t sb = smem_u32(dsm2);
    int b = blockIdx.z, nt0 = blockIdx.y*128, ct0 = blockIdx.x*64;
    int t = threadIdx.x, w = t >> 5, lane = t & 31;
    int wn = (w & 3)*32, wc = (w >> 2)*32;
    float acc[2][4][4];
    #pragma unroll
    for (int i = 0; i < 2; i++)
        #pragma unroll
        for (int j = 0; j < 4; j++)
            #pragma unroll
            for (int k = 0; k < 4; k++) acc[i][j][k] = 0.f;

    g2_load(sb, b, nt0, ct0, 0, 0, t);
    cp_commit();
    for (int kt = 0; kt < 13; kt++) {
        if (kt < 12) {
            g2_load(sb, b, nt0, ct0, kt+1, (kt+1) & 1, t);
            cp_commit();
            cp_wait1();
        } else cp_wait0();
        __syncthreads();
        uint32_t base = sb + (uint32_t)(kt & 1)*G2_BUF*2;
        #pragma unroll
        for (int kk = 0; kk < 2; kk++) {
            int kb = kk*16;
            uint32_t ah[2][4], al[2][4];
            #pragma unroll
            for (int mt = 0; mt < 2; mt++) {
                int row = wn + mt*16 + (lane & 15);
                int col = kb + ((lane & 16) ? 8 : 0);
                uint32_t off = (uint32_t)(row*40 + col)*2;
                ldm_x4(ah[mt], base + G2_AH*2 + off);
                ldm_x4(al[mt], base + G2_AL*2 + off);
            }
            uint32_t bh[4][2], bl[4][2];
            #pragma unroll
            for (int p = 0; p < 2; p++) {
                int crow = wc + p*16 + (lane & 7) + ((lane & 16) ? 8 : 0);
                int col = kb + ((lane & 8) ? 8 : 0);
                uint32_t off = (uint32_t)(crow*40 + col)*2;
                uint32_t r4[4];
                ldm_x4(r4, base + G2_BH*2 + off);
                bh[2*p][0]=r4[0]; bh[2*p][1]=r4[1]; bh[2*p+1][0]=r4[2]; bh[2*p+1][1]=r4[3];
                ldm_x4(r4, base + G2_BL*2 + off);
                bl[2*p][0]=r4[0]; bl[2*p][1]=r4[1]; bl[2*p+1][0]=r4[2]; bl[2*p+1][1]=r4[3];
            }
            #pragma unroll
            for (int mt = 0; mt < 2; mt++)
                #pragma unroll
                for (int ct = 0; ct < 4; ct++) {
                    mma_bf16(acc[mt][ct], ah[mt], bh[ct]);
                    mma_bf16(acc[mt][ct], al[mt], bh[ct]);
                    mma_bf16(acc[mt][ct], ah[mt], bl[ct]);
                }
        }
        __syncthreads();
    }
    int nrow = nt0 + wn + (lane >> 2);
    #pragma unroll
    for (int mt = 0; mt < 2; mt++) {
        #pragma unroll
        for (int ct = 0; ct < 4; ct++) {
            int c0 = ct0 + wc + ct*8 + ((lane & 3) << 1);
            float b0 = g_bias2[b*512 + c0];
            float b1 = g_bias2[b*512 + c0 + 1];
            #pragma unroll
            for (int half = 0; half < 2; half++) {
                int n = nrow + mt*16 + half*8;
                if (n < 3136) {
                    size_t o = ((size_t)b*3136 + n)*512 + c0;
                    *(float2*)&out[o] = make_float2(acc[mt][ct][half*2] + b0,
                                                    acc[mt][ct][half*2+1] + b1);
                }
            }
        }
    }
}

// ---------------- launcher ----------------
extern "C" void kernel_launch(void* const* d_in, const int* in_sizes, int n_in,
                              void* d_out, int out_size) {
    const float* x        = (const float*)d_in[0];
    const float* q_w      = (const float*)d_in[1];
    const float* down_w   = (const float*)d_in[2];
    const float* kv_w     = (const float*)d_in[3];
    const float* proj_w   = (const float*)d_in[4];
    const float* proj_b   = (const float*)d_in[5];
    const float* rel_bias = (const float*)d_in[6];
    const float* expand_w = (const float*)d_in[7];
    const float* gn1_s    = (const float*)d_in[8];
    const float* gn1_b    = (const float*)d_in[9];
    const float* dw_w     = (const float*)d_in[10];
    const float* gn2_s    = (const float*)d_in[11];
    const float* gn2_b    = (const float*)d_in[12];
    const float* reduce_w = (const float*)d_in[13];
    const float* gn3_s    = (const float*)d_in[14];
    const float* gn3_b    = (const float*)d_in[15];
    float* out = (float*)d_out;

    float *ab2, *ab3, *p2, *p3;
    cudaGetSymbolAddress((void**)&ab2, g_ab2);
    cudaGetSymbolAddress((void**)&ab3, g_ab3);
    cudaGetSymbolAddress((void**)&p2, g_part2);
    cudaGetSymbolAddress((void**)&p3, g_part3);

    cudaFuncSetAttribute(k_gemm1_fused, cudaFuncAttributeMaxDynamicSharedMemorySize, G1_SMEM);
    cudaFuncSetAttribute(k_gemm2_mma, cudaFuncAttributeMaxDynamicSharedMemorySize, G2_SMEM);
    cudaFuncSetAttribute(k_dw_gn2,    cudaFuncAttributeMaxDynamicSharedMemorySize, B_SMEM);
    cudaFuncSetAttribute(k_dla_out,   cudaFuncAttributeMaxDynamicSharedMemorySize, C_SMEM);

    k_xsplit<<<dim3(98, 16, BB), 256>>>(x);
    k_down<<<BB*CCH, 256>>>(x, down_w);
    k_kv  <<<dim3(4, 7, BB), 256>>>(kv_w);
    k_wqk_split<<<dim3(2, 8, BB), 256>>>(q_w);
    k_wvp <<<dim3(7, 8, BB), 256>>>(proj_w);
    k_gemm1_fused<<<dim3(49, BB), 256, G1_SMEM>>>(rel_bias);
    k_gn1_final<<<BB, 64>>>(gn1_s, gn1_b, expand_w);
    k_dw_gn2<<<dim3(196, BB), 256, B_SMEM>>>(dw_w, expand_w);
    k_stats_final<<<BB*3, 256>>>(gn2_s, gn2_b, ab2, p2, 3, 196);
    k_dla_out<<<dim3(392, BB), 256, C_SMEM>>>(dw_w, expand_w, reduce_w);
    k_stats_final<<<BB, 256>>>(gn3_s, gn3_b, ab3, p3, 1, 392);
    k_wvpsplit<<<dim3(13, 16, BB), 256>>>();
    k_wvpbias<<<BB, 512>>>(proj_b);
    k_gemm2_mma<<<dim3(8, 25, BB), 256, G2_SMEM>>>(out);
}

// round 10
// speedup vs baseline: 1.0327x; 1.0263x over previous
#include <cuda_runtime.h>
#include <cuda_bf16.h>
#include <math.h>
#include <stdint.h>

#define BB    16
#define CCH   512
#define NN    3136
#define NKK   49
#define HEADS 8
#define JJ    392
#define HIDC  24
#define SCALE 0.125f

// ---------------- device scratch ----------------
__device__ float g_kvx[BB*NKK*CCH];
__device__ float g_kv [BB*NKK*1024];
__device__ float g_Wvp[BB*JJ*CCH];
__device__ __nv_bfloat16 g_xTh[(size_t)BB*NN*CCH];
__device__ __nv_bfloat16 g_xTl[(size_t)BB*NN*CCH];
__device__ __nv_bfloat16 g_wqh[BB*JJ*CCH];
__device__ __nv_bfloat16 g_wql[BB*JJ*CCH];
__device__ __nv_bfloat16 g_wvh[BB*CCH*JJ];
__device__ __nv_bfloat16 g_wvl[BB*CCH*JJ];
__device__ float g_attn[(size_t)BB*NN*JJ];
__device__ __nv_bfloat16 g_ath[(size_t)BB*NN*JJ];
__device__ __nv_bfloat16 g_atl[(size_t)BB*NN*JJ];
__device__ float g_part1[BB*49*36];
__device__ float g_part2[BB*3*196*2];
__device__ float g_part3[BB*392*2];
__device__ float g_ab1[BB*HIDC*2];
__device__ float g_ab2[BB*HIDC*2];
__device__ float g_ab3[BB*HEADS*2];
__device__ float g_bias2[BB*CCH];

__device__ __forceinline__ float swishf(float x) { return x / (1.f + __expf(-x)); }

__device__ __forceinline__ void bsplit(float v, __nv_bfloat16& h, __nv_bfloat16& l) {
    h = __float2bfloat16(v);
    l = __float2bfloat16(v - __bfloat162float(h));
}

__device__ __forceinline__ uint32_t smem_u32(const void* p) {
    uint32_t a;
    asm("{ .reg .u64 t; cvta.to.shared.u64 t, %1; cvt.u32.u64 %0, t; }" : "=r"(a) : "l"(p));
    return a;
}
__device__ __forceinline__ void ldm_x4(uint32_t* r, uint32_t addr) {
    asm volatile("ldmatrix.sync.aligned.m8n8.x4.shared.b16 {%0,%1,%2,%3}, [%4];"
        : "=r"(r[0]), "=r"(r[1]), "=r"(r[2]), "=r"(r[3]) : "r"(addr));
}
__device__ __forceinline__ void ldm_x2(uint32_t* r, uint32_t addr) {
    asm volatile("ldmatrix.sync.aligned.m8n8.x2.shared.b16 {%0,%1}, [%2];"
        : "=r"(r[0]), "=r"(r[1]) : "r"(addr));
}
__device__ __forceinline__ void mma_bf16(float* c, const uint32_t* a, const uint32_t* b) {
    asm volatile(
        "mma.sync.aligned.m16n8k16.row.col.f32.bf16.bf16.f32 "
        "{%0,%1,%2,%3}, {%4,%5,%6,%7}, {%8,%9}, {%0,%1,%2,%3};"
        : "+f"(c[0]), "+f"(c[1]), "+f"(c[2]), "+f"(c[3])
        : "r"(a[0]), "r"(a[1]), "r"(a[2]), "r"(a[3]), "r"(b[0]), "r"(b[1]));
}
__device__ __forceinline__ void cpa16(uint32_t dst, const void* src, bool v) {
    int sz = v ? 16 : 0;
    asm volatile("cp.async.cg.shared.global [%0], [%1], 16, %2;"
        :: "r"(dst), "l"(src), "r"(sz) : "memory");
}
__device__ __forceinline__ void cp_commit() {
    asm volatile("cp.async.commit_group;" ::: "memory");
}
__device__ __forceinline__ void cp_wait1() {
    asm volatile("cp.async.wait_group 1;" ::: "memory");
}
__device__ __forceinline__ void cp_wait0() {
    asm volatile("cp.async.wait_group 0;" ::: "memory");
}

// ---------------- 1. k_prep: fused xsplit (blocks 0..25087) + down (blocks 25088..33279) ----------------
__global__ __launch_bounds__(256) void k_prep(const float* __restrict__ x,
                                              const float* __restrict__ down_w) {
    __shared__ float sh[3200];
    int blk = blockIdx.x;
    int t = threadIdx.x;
    if (blk < 25088) {
        // ---- xsplit: transpose + bf16 split ----
        int tn = blk % 98;
        int rest = blk / 98;
        int tc = rest & 15, b = rest >> 4;
        float (*tile)[33] = (float(*)[33])sh;
        int a = t >> 5, q = t & 31;
        #pragma unroll
        for (int r = 0; r < 4; r++) {
            int cc = tc*32 + a + r*8, nn = tn*32 + q;
            tile[a + r*8][q] = x[((size_t)b*512 + cc)*3136 + nn];
        }
        __syncthreads();
        #pragma unroll
        for (int r = 0; r < 4; r++) {
            int nn = tn*32 + a + r*8, cc = tc*32 + q;
            float v = tile[q][a + r*8];
            __nv_bfloat16 h, l; bsplit(v, h, l);
            size_t o = ((size_t)b*3136 + nn)*512 + cc;
            g_xTh[o] = h; g_xTl[o] = l;
        }
    } else {
        // ---- down: depthwise 8x8/8 ----
        int bc = blk - 25088, c = bc & 511, b = bc >> 9;
        float* plane = sh;
        float* w = sh + 3136;
        const float* xp = x + (size_t)bc * 3136;
        for (int i = t; i < 3136; i += 256) plane[i] = xp[i];
        if (t < 64) w[t] = down_w[c*64 + t];
        __syncthreads();
        if (t < 49) {
            int my = t / 7, mx = t % 7;
            float s = 0.f;
            #pragma unroll
            for (int i = 0; i < 8; i++)
                #pragma unroll
                for (int j = 0; j < 8; j++)
                    s += plane[(my*8+i)*56 + mx*8 + j] * w[i*8+j];
            g_kvx[(b*49 + t)*512 + c] = s;
        }
    }
}

// ---------------- 2. kv = kvx @ kv_w ----------------
__global__ void k_kv(const float* __restrict__ kv_w) {
    int b = blockIdx.z, m0 = blockIdx.y * 7, oc = blockIdx.x;
    __shared__ float a[7][512];
    for (int i = threadIdx.x; i < 7*512; i += 256)
        a[i >> 9][i & 511] = g_kvx[(b*49 + m0 + (i >> 9))*512 + (i & 511)];
    __syncthreads();
    int o = oc*256 + threadIdx.x;
    float acc[7] = {0,0,0,0,0,0,0};
    for (int c = 0; c < 512; c++) {
        float w = kv_w[c*1024 + o];
        #pragma unroll
        for (int mm = 0; mm < 7; mm++) acc[mm] += a[mm][c] * w;
    }
    #pragma unroll
    for (int mm = 0; mm < 7; mm++)
        g_kv[(b*49 + m0 + mm)*1024 + o] = acc[mm];
}

// ---------------- 3. k_qkvw: fused wqk_split (blocks 0..255) + wvp (blocks 256..1151) ----------------
__global__ __launch_bounds__(256) void k_qkvw(const float* __restrict__ q_w,
                                              const float* __restrict__ proj_w) {
    __shared__ float sh[3136];
    int blk = blockIdx.x;
    int t = threadIdx.x;
    if (blk < 256) {
        // ---- wqk_split ----
        int half = blk & 1, h = (blk >> 1) & 7, b = blk >> 4;
        float (*ks)[64] = (float(*)[64])sh;
        for (int i = t; i < 49*64; i += 256)
            ks[i >> 6][i & 63] = g_kv[(b*49 + (i >> 6))*1024 + h*64 + (i & 63)];
        __syncthreads();
        int cin = half*256 + t;
        float acc[49];
        #pragma unroll
        for (int m = 0; m < 49; m++) acc[m] = 0.f;
        const float4* q4 = (const float4*)(q_w + (size_t)cin*512 + h*64);
        const float4* ks4 = (const float4*)&ks[0][0];
        for (int d4 = 0; d4 < 16; d4++) {
            float4 q = __ldg(q4 + d4);
            #pragma unroll
            for (int m = 0; m < 49; m++) {
                float4 k = ks4[m*16 + d4];
                acc[m] += q.x*k.x + q.y*k.y + q.z*k.z + q.w*k.w;
            }
        }
        size_t obase = ((size_t)b*392 + h*49)*512 + cin;
        #pragma unroll
        for (int m = 0; m < 49; m++) {
            float v = acc[m] * SCALE;
            __nv_bfloat16 hh, ll; bsplit(v, hh, ll);
            g_wqh[obase + (size_t)m*512] = hh;
            g_wql[obase + (size_t)m*512] = ll;
        }
    } else {
        // ---- wvp ----
        int q = blk - 256;
        int mc = (q % 7) * 7, h = (q / 7) & 7, b = q / 56;
        float (*vs)[64] = (float(*)[64])sh;
        for (int i = t; i < 7*64; i += 256)
            vs[i >> 6][i & 63] = g_kv[(b*49 + mc + (i >> 6))*1024 + 512 + h*64 + (i & 63)];
        __syncthreads();
        float acc[7][2] = {{0}};
        for (int d = 0; d < 64; d++) {
            float w0 = proj_w[(h*64+d)*512 + t];
            float w1 = proj_w[(h*64+d)*512 + 256 + t];
            #pragma unroll
            for (int mm = 0; mm < 7; mm++) {
                float vv = vs[mm][d];
                acc[mm][0] += vv * w0;
                acc[mm][1] += vv * w1;
            }
        }
        #pragma unroll
        for (int mm = 0; mm < 7; mm++) {
            int j = h*49 + mc + mm;
            g_Wvp[(b*392 + j)*512 + t]       = acc[mm][0];
            g_Wvp[(b*392 + j)*512 + 256 + t] = acc[mm][1];
        }
    }
}

// ---------------- 4. GEMM1 fused (R7 config: k-tile 32, double-buffered) ----------------
#define G1_ABUF  5120u
#define G1_BBASE 20480u
#define G1_BBUF  33280u
#define G1_SMEM  153600
__device__ __forceinline__ void g1f_load(uint32_t sb, int b, int nt0, int kt, int p, int t) {
    int k0 = kt*32;
    {
        int row = t >> 2, q = t & 3;
        size_t e = ((size_t)b*3136 + nt0 + row)*512 + k0 + q*8;
        uint32_t doff = (uint32_t)(row*40 + q*8)*2;
        cpa16(sb + (p*2+0)*G1_ABUF + doff, g_xTh + e, true);
        cpa16(sb + (p*2+1)*G1_ABUF + doff, g_xTl + e, true);
    }
    #pragma unroll
    for (int rr = 0; rr < 13; rr++) {
        int idx = rr*256 + t;
        int hl = idx >= 1664;
        int ii = idx - hl*1664;
        int row = ii >> 2, q = ii & 3;
        bool v = row < 392;
        size_t e = ((size_t)b*392 + (v ? row : 0))*512 + k0 + q*8;
        uint32_t doff = (uint32_t)(row*40 + q*8)*2;
        const __nv_bfloat16* src = hl ? g_wql : g_wqh;
        cpa16(sb + G1_BBASE + (p*2+hl)*G1_BBUF + doff, src + e, v);
    }
}

__global__ __launch_bounds__(256) void k_gemm1_fused(const float* __restrict__ rel_bias) {
    extern __shared__ char smraw[];
    uint32_t sb = smem_u32(smraw);
    int b = blockIdx.y, nt0 = blockIdx.x * 64;
    int t = threadIdx.x, w = t >> 5, lane = t & 31;
    int wn = (w & 1)*32, wj = (w >> 1)*104;
    float acc[2][13][4];
    #pragma unroll
    for (int i = 0; i < 2; i++)
        #pragma unroll
        for (int j = 0; j < 13; j++)
            #pragma unroll
            for (int k = 0; k < 4; k++) acc[i][j][k] = 0.f;

    g1f_load(sb, b, nt0, 0, 0, t);
    cp_commit();
    for (int kt = 0; kt < 16; kt++) {
        if (kt < 15) {
            g1f_load(sb, b, nt0, kt+1, (kt+1) & 1, t);
            cp_commit();
            cp_wait1();
        } else cp_wait0();
        __syncthreads();
        int p = kt & 1;
        uint32_t pAh = sb + (p*2+0)*G1_ABUF;
        uint32_t pAl = sb + (p*2+1)*G1_ABUF;
        uint32_t pBh = sb + G1_BBASE + (p*2+0)*G1_BBUF;
        uint32_t pBl = sb + G1_BBASE + (p*2+1)*G1_BBUF;
        #pragma unroll
        for (int kk = 0; kk < 2; kk++) {
            int kb = kk*16;
            uint32_t ah[2][4], al[2][4];
            int arow = wn + (lane & 15);
            int acol = kb + ((lane & 16) ? 8 : 0);
            ldm_x4(ah[0], pAh + (uint32_t)(arow*40 + acol)*2);
            ldm_x4(ah[1], pAh + (uint32_t)((arow+16)*40 + acol)*2);
            ldm_x4(al[0], pAl + (uint32_t)(arow*40 + acol)*2);
            ldm_x4(al[1], pAl + (uint32_t)((arow+16)*40 + acol)*2);
            #pragma unroll
            for (int p2 = 0; p2 < 6; p2++) {
                int jrow = wj + p2*16 + (lane & 7) + ((lane & 16) ? 8 : 0);
                int col = kb + ((lane & 8) ? 8 : 0);
                uint32_t off = (uint32_t)(jrow*40 + col)*2;
                uint32_t rh[4], rl[4];
                ldm_x4(rh, pBh + off);
                ldm_x4(rl, pBl + off);
                #pragma unroll
                for (int mt = 0; mt < 2; mt++)
                    #pragma unroll
                    for (int e = 0; e < 2; e++) {
                        mma_bf16(acc[mt][2*p2+e], ah[mt], &rh[2*e]);
                        mma_bf16(acc[mt][2*p2+e], al[mt], &rh[2*e]);
                        mma_bf16(acc[mt][2*p2+e], ah[mt], &rl[2*e]);
                    }
            }
            {
                int jrow = wj + 96 + (lane & 7);
                int col = kb + ((lane & 8) ? 8 : 0);
                uint32_t off = (uint32_t)(jrow*40 + col)*2;
                uint32_t bh2[2], bl2[2];
                ldm_x2(bh2, pBh + off);
                ldm_x2(bl2, pBl + off);
                #pragma unroll
                for (int mt = 0; mt < 2; mt++) {
                    mma_bf16(acc[mt][12], ah[mt], bh2);
                    mma_bf16(acc[mt][12], al[mt], bh2);
                    mma_bf16(acc[mt][12], ah[mt], bl2);
                }
            }
        }
        __syncthreads();
    }
    // ---- epilogue: stage logits in SMEM ----
    float* S = (float*)smraw;            // [64][400]
    float* Gred = S + 64*400;            // [8][36]
    #pragma unroll
    for (int mt = 0; mt < 2; mt++) {
        int nl = wn + mt*16 + (lane >> 2);
        #pragma unroll
        for (int jt = 0; jt < 13; jt++) {
            int j0 = wj + jt*8 + ((lane & 3) << 1);
            if (j0 < 392) {
                S[nl*400 + j0]       = acc[mt][jt][0];
                S[nl*400 + j0 + 1]   = acc[mt][jt][1];
                S[(nl+8)*400 + j0]   = acc[mt][jt][2];
                S[(nl+8)*400 + j0+1] = acc[mt][jt][3];
            }
        }
    }
    __syncthreads();
    #pragma unroll
    for (int rr = 0; rr < 2; rr++) {
        int row = t + rr*256;
        int n = row >> 3, h = row & 7;
        float* p = S + n*400 + h*49;
        const float* rb = rel_bias + (size_t)(nt0 + n)*49;
        float mx = -1e30f;
        for (int i = 0; i < 49; i++) {
            float lv = p[i] + __ldg(rb + i);
            p[i] = lv;
            mx = fmaxf(mx, lv);
        }
        float sum = 0.f;
        for (int i = 0; i < 49; i++) { float e = __expf(p[i] - mx); p[i] = e; sum += e; }
        float inv = 1.f / sum;
        for (int i = 0; i < 49; i++) p[i] *= inv;
    }
    __syncthreads();
    float g[36];
    #pragma unroll
    for (int k = 0; k < 36; k++) g[k] = 0.f;
    for (int pos = t; pos < 64*49; pos += 256) {
        int n = pos / 49, m = pos - n*49;
        float a[8];
        #pragma unroll
        for (int h = 0; h < 8; h++) a[h] = S[n*400 + h*49 + m];
        int k = 0;
        #pragma unroll
        for (int h = 0; h < 8; h++)
            #pragma unroll
            for (int h2 = h; h2 < 8; h2++) { g[k] += a[h]*a[h2]; k++; }
    }
    size_t ob = ((size_t)b*3136 + nt0)*392;
    for (int i = t; i < 64*392; i += 256) {
        int n = i / 392, c = i - n*392;
        g_attn[ob + i] = S[n*400 + c];
    }
    #pragma unroll
    for (int s = 16; s; s >>= 1)
        #pragma unroll
        for (int k = 0; k < 36; k++) g[k] += __shfl_xor_sync(0xffffffffu, g[k], s);
    if (lane == 0)
        #pragma unroll
        for (int k = 0; k < 36; k++) Gred[w*36 + k] = g[k];
    __syncthreads();
    if (t < 36) {
        float s = 0.f;
        #pragma unroll
        for (int ww = 0; ww < 8; ww++) s += Gred[ww*36 + t];
        g_part1[((size_t)b*49 + blockIdx.x)*36 + t] = s;
    }
}

// ---------------- 5. gn1 finalize from Gram ----------------
__global__ void k_gn1_final(const float* __restrict__ gs, const float* __restrict__ gb,
                            const float* __restrict__ ew) {
    int b = blockIdx.x, t = threadIdx.x;   // 64 threads
    __shared__ float M36[36];
    __shared__ float Mf[64];
    __shared__ float s1s[24], sqs[24];
    __shared__ float mg[3], rg[3];
    if (t < 36) {
        float s = 0.f;
        for (int nt = 0; nt < 49; nt++) s += g_part1[((size_t)b*49 + nt)*36 + t];
        M36[t] = s;
    }
    __syncthreads();
    if (t == 0) {
        int k = 0;
        for (int h = 0; h < 8; h++)
            for (int h2 = h; h2 < 8; h2++) { Mf[h*8+h2] = M36[k]; Mf[h2*8+h] = M36[k]; k++; }
    }
    __syncthreads();
    if (t < 24) {
        float wv[8], sw = 0.f;
        #pragma unroll
        for (int h = 0; h < 8; h++) { wv[h] = ew[t*8+h]; sw += wv[h]; }
        float sq = 0.f;
        #pragma unroll
        for (int h = 0; h < 8; h++)
            #pragma unroll
            for (int h2 = 0; h2 < 8; h2++) sq += wv[h]*wv[h2]*Mf[h*8+h2];
        s1s[t] = 3136.f * sw;
        sqs[t] = sq;
    }
    __syncthreads();
    if (t < 3) {
        float s1 = 0.f, sq = 0.f;
        for (int c = 0; c < 8; c++) { s1 += s1s[t*8+c]; sq += sqs[t*8+c]; }
        float cnt = 8.f*3136.f*49.f;
        float mean = s1/cnt;
        float var  = sq/cnt - mean*mean;
        mg[t] = mean;
        rg[t] = rsqrtf(var + 1e-5f);
    }
    __syncthreads();
    if (t < 24) {
        float A = rg[t>>3]*gs[t];
        g_ab1[(b*24 + t)*2]     = A;
        g_ab1[(b*24 + t)*2 + 1] = gb[t] - mg[t>>3]*A;
    }
}

// ---------------- stats finalize (gn2/gn3) ----------------
__global__ void k_stats_final(const float* __restrict__ gs, const float* __restrict__ gb,
                              float* __restrict__ ab, const float* __restrict__ part,
                              int G, int npart) {
    int b = blockIdx.x / G, g = blockIdx.x % G;
    const float* p = part + (size_t)(b*G + g)*npart*2;
    float sm = 0.f, sq = 0.f;
    for (int i = threadIdx.x; i < npart; i += 256) { sm += p[2*i]; sq += p[2*i+1]; }
    __shared__ float rs[256], rq[256];
    __shared__ float mean_s, rstd_s;
    int t = threadIdx.x;
    rs[t] = sm; rq[t] = sq;
    __syncthreads();
    for (int st = 128; st; st >>= 1) {
        if (t < st) { rs[t] += rs[t+st]; rq[t] += rq[t+st]; }
        __syncthreads();
    }
    if (!t) {
        float cnt  = 8.f * 3136.f * 49.f;
        float mean = rs[0] / cnt;
        float var  = rq[0] / cnt - mean*mean;
        mean_s = mean;
        rstd_s = rsqrtf(var + 1e-5f);
    }
    __syncthreads();
    if (t < 8) {
        int c = g*8 + t;
        float A = rstd_s * gs[c];
        int CH = G*8;
        ab[(b*CH + c)*2]     = A;
        ab[(b*CH + c)*2 + 1] = gb[c] - mean_s*A;
    }
}

// ---------------- 6. pass B: warp-parallel expand+dw -> gn2 partials ----------------
#define B_AT  0
#define B_HID 7056
#define B_EW  14416
#define B_AB  14608
#define B_RED 14656
#define B_TOT (14656 + 1536)
#define B_SMEM (B_TOT*4)
__global__ __launch_bounds__(256) void k_dw_gn2(const float* __restrict__ dw_w,
                                                const float* __restrict__ expand_w) {
    extern __shared__ float sm[];
    float* at  = sm + B_AT;
    float* ew  = sm + B_EW;
    float* ab  = sm + B_AB;
    float* red = sm + B_RED;
    int nt = blockIdx.x, b = blockIdx.y, t = threadIdx.x;
    int w = t >> 5, lane = t & 31;
    float* hid = sm + B_HID + w*920;
    int n0 = nt * 16;
    if (t < 192) ew[t] = expand_w[t];
    if (t >= 192 && t < 240) ab[t-192] = g_ab1[b*48 + (t-192)];
    for (int i = t; i < 18*392; i += 256) {
        int r = i / 392, m = i - r*392;
        int n = n0 - 1 + r;
        at[i] = (n >= 0 && n < 3136) ? g_attn[((size_t)b*3136 + n)*392 + m] : 0.f;
    }
    __syncthreads();
    float sk[3] = {0,0,0}, qk[3] = {0,0,0};
    #pragma unroll
    for (int k = 0; k < 3; k++) {
        int c = w + k*8;
        float A1 = ab[c*2], B1 = ab[c*2+1];
        const float* wp = ew + c*8;
        for (int i = lane; i < 918; i += 32) {
            int r = i / 51, mm = i - r*51;
            int n = n0 - 1 + r;
            float v = 0.f;
            if (mm >= 1 && mm <= 49 && n >= 0 && n < 3136) {
                const float* sp = at + r*392 + (mm - 1);
                float hsum = 0.f;
                #pragma unroll
                for (int hh = 0; hh < 8; hh++) hsum += sp[hh*49] * wp[hh];
                v = swishf(A1*hsum + B1);
            }
            hid[i] = v;
        }
        __syncwarp();
        float lw[9];
        #pragma unroll
        for (int i = 0; i < 9; i++) lw[i] = dw_w[c*9 + i];
        for (int o = lane; o < 784; o += 32) {
            int ny = o / 49, m = o - ny*49;
            float a = 0.f;
            #pragma unroll
            for (int dy = 0; dy < 3; dy++)
                #pragma unroll
                for (int dx = 0; dx < 3; dx++)
                    a += hid[(ny+dy)*51 + m+dx] * lw[dy*3+dx];
            sk[k] += a; qk[k] += a*a;
        }
        __syncwarp();
    }
    #pragma unroll
    for (int g = 0; g < 3; g++) { red[g*256 + t] = sk[g]; red[(3+g)*256 + t] = qk[g]; }
    __syncthreads();
    for (int st = 128; st; st >>= 1) {
        if (t < st)
            #pragma unroll
            for (int g = 0; g < 6; g++) red[g*256 + t] += red[g*256 + t + st];
        __syncthreads();
    }
    if (t < 3) {
        g_part2[((b*3 + t)*196 + nt)*2]     = red[t*256];
        g_part2[((b*3 + t)*196 + nt)*2 + 1] = red[(t+3)*256];
    }
}

// ---------------- 7. pass C: expand+dw+norm2+swish, reduce -> attnF + gn3 ----------------
#define C_AT  0
#define C_HID 3920
#define C_DWS 8016
#define C_EW  17424
#define C_RW  17616
#define C_AB  17808
#define C_RED 17904
#define C_TOT (17904 + 512)
#define C_SMEM (C_TOT*4)
__global__ __launch_bounds__(256) void k_dla_out(const float* __restrict__ dw_w,
                                                 const float* __restrict__ expand_w,
                                                 const float* __restrict__ reduce_w) {
    extern __shared__ float sm[];
    float* at  = sm + C_AT;
    float* dws = sm + C_DWS;
    float* ew  = sm + C_EW;
    float* rw  = sm + C_RW;
    float* ab  = sm + C_AB;
    float* red = sm + C_RED;
    int nt = blockIdx.x, b = blockIdx.y, t = threadIdx.x;
    int w = t >> 5, lane = t & 31;
    float* hid = sm + C_HID + w*512;
    int n0 = nt * 8;
    if (t < 192) { ew[t] = expand_w[t]; rw[t] = reduce_w[t]; }
    if (t < 96) ab[t] = (t < 48) ? g_ab1[b*48 + t] : g_ab2[b*48 + (t-48)];
    for (int i = t; i < 10*392; i += 256) {
        int r = i / 392, m = i - r*392;
        int n = n0 - 1 + r;
        at[i] = (n >= 0 && n < 3136) ? g_attn[((size_t)b*3136 + n)*392 + m] : 0.f;
    }
    __syncthreads();
    #pragma unroll
    for (int k = 0; k < 3; k++) {
        int c = w + k*8;
        float A1 = ab[c*2], B1 = ab[c*2+1];
        float A2 = ab[48 + c*2], B2 = ab[49 + c*2];
        const float* wp = ew + c*8;
        for (int i = lane; i < 510; i += 32) {
            int r = i / 51, mm = i - r*51;
            int n = n0 - 1 + r;
            float v = 0.f;
            if (mm >= 1 && mm <= 49 && n >= 0 && n < 3136) {
                const float* sp = at + r*392 + (mm - 1);
                float hsum = 0.f;
                #pragma unroll
                for (int hh = 0; hh < 8; hh++) hsum += sp[hh*49] * wp[hh];
                v = swishf(A1*hsum + B1);
            }
            hid[i] = v;
        }
        __syncwarp();
        float lw[9];
        #pragma unroll
        for (int i = 0; i < 9; i++) lw[i] = dw_w[c*9 + i];
        for (int o = lane; o < 392; o += 32) {
            int ny = o / 49, m = o - ny*49;
            float a = 0.f;
            #pragma unroll
            for (int dy = 0; dy < 3; dy++)
                #pragma unroll
                for (int dx = 0; dx < 3; dx++)
                    a += hid[(ny+dy)*51 + m+dx] * lw[dy*3+dx];
            dws[(ny*24 + c)*49 + m] = swishf(A2*a + B2);
        }
        __syncwarp();
    }
    __syncthreads();
    float lsum = 0.f, lsq = 0.f;
    for (int o = t; o < 392; o += 256) {
        int ny = o / 49, m = o - ny*49;
        int n = n0 + ny;
        float in[24];
        #pragma unroll
        for (int c = 0; c < 24; c++) in[c] = dws[(ny*24 + c)*49 + m];
        size_t ob = ((size_t)b*3136 + n)*392 + m;
        #pragma unroll
        for (int h = 0; h < 8; h++) {
            float r = 0.f;
            #pragma unroll
            for (int c = 0; c < 24; c++) r += in[c] * rw[h*24 + c];
            __nv_bfloat16 hh, ll; bsplit(r, hh, ll);
            g_ath[ob + h*49] = hh;
            g_atl[ob + h*49] = ll;
            lsum += r; lsq += r*r;
        }
    }
    red[t] = lsum; red[256 + t] = lsq;
    __syncthreads();
    for (int st = 128; st; st >>= 1) {
        if (t < st) { red[t] += red[t+st]; red[256+t] += red[256+t+st]; }
        __syncthreads();
    }
    if (!t) {
        g_part3[(b*392 + nt)*2]     = red[0];
        g_part3[(b*392 + nt)*2 + 1] = red[256];
    }
}

// ---------------- 8. k_wvpfin: fused wvpsplit (blocks 0..3327) + wvpbias (3328..3343) ----------------
__global__ __launch_bounds__(256) void k_wvpfin(const float* __restrict__ proj_b) {
    __shared__ float tile[32][33];
    int blk = blockIdx.x;
    int t = threadIdx.x;
    if (blk < 3328) {
        int tj = blk % 13;
        int rest = blk / 13;
        int tc = rest & 15, b = rest >> 4;
        int a = t >> 5, q = t & 31;
        #pragma unroll
        for (int r = 0; r < 4; r++) {
            int jj = tj*32 + a + r*8, cc = tc*32 + q;
            float v = 0.f;
            if (jj < 392) v = g_Wvp[((size_t)b*392 + jj)*512 + cc] * g_ab3[(b*8 + jj/49)*2];
            tile[a + r*8][q] = v;
        }
        __syncthreads();
        #pragma unroll
        for (int r = 0; r < 4; r++) {
            int cc = tc*32 + a + r*8, jj = tj*32 + q;
            if (jj < 392) {
                float v = tile[q][a + r*8];
                __nv_bfloat16 h, l; bsplit(v, h, l);
                size_t o = ((size_t)b*512 + cc)*392 + jj;
                g_wvh[o] = h; g_wvl[o] = l;
            }
        }
    } else {
        int b = blk - 3328;
        #pragma unroll
        for (int cc = 0; cc < 2; cc++) {
            int c = t + cc*256;
            float acc = 0.f;
            for (int j = 0; j < 392; j++)
                acc += g_ab3[(b*8 + j/49)*2 + 1] * g_Wvp[((size_t)b*392 + j)*512 + c];
            g_bias2[b*512 + c] = acc + proj_b[c];
        }
    }
}

// ---------------- 9. GEMM2 (bf16x3 mma.sync) ----------------
#define G2_BUF 15360
#define G2_AH 0
#define G2_AL 5120
#define G2_BH 10240
#define G2_BL 12800
#define G2_SMEM (G2_BUF*2*2)
__device__ __forceinline__ void g2_load(uint32_t sb, int b, int nt0, int ct0,
                                        int kt, int p, int t) {
    int k0 = kt*32;
    uint32_t base = sb + (uint32_t)p*G2_BUF*2;
    #pragma unroll
    for (int rr = 0; rr < 2; rr++) {
        int idx = t + rr*256;
        int row = idx >> 2, q = idx & 3;
        int n = nt0 + row, j0 = k0 + q*8;
        bool v = (n < 3136) && (j0 < 392);
        size_t e = ((size_t)b*3136 + (n < 3136 ? n : 0))*392 + (j0 < 392 ? j0 : 0);
        uint32_t doff = (uint32_t)(row*40 + q*8)*2;
        cpa16(base + G2_AH*2 + doff, g_ath + e, v);
        cpa16(base + G2_AL*2 + doff, g_atl + e, v);
    }
    {
        int idx = t;
        int row = idx >> 2, q = idx & 3;
        int c = ct0 + row, j0 = k0 + q*8;
        bool v = j0 < 392;
        size_t e = ((size_t)b*512 + c)*392 + (v ? j0 : 0);
        uint32_t doff = (uint32_t)(row*40 + q*8)*2;
        cpa16(base + G2_BH*2 + doff, g_wvh + e, v);
        cpa16(base + G2_BL*2 + doff, g_wvl + e, v);
    }
}

__global__ __launch_bounds__(256) void k_gemm2_mma(float* __restrict__ out) {
    extern __shared__ __nv_bfloat16 dsm2[];
    uint32_t sb = smem_u32(dsm2);
    int b = blockIdx.z, nt0 = blockIdx.y*128, ct0 = blockIdx.x*64;
    int t = threadIdx.x, w = t >> 5, lane = t & 31;
    int wn = (w & 3)*32, wc = (w >> 2)*32;
    float acc[2][4][4];
    #pragma unroll
    for (int i = 0; i < 2; i++)
        #pragma unroll
        for (int j = 0; j < 4; j++)
            #pragma unroll
            for (int k = 0; k < 4; k++) acc[i][j][k] = 0.f;

    g2_load(sb, b, nt0, ct0, 0, 0, t);
    cp_commit();
    for (int kt = 0; kt < 13; kt++) {
        if (kt < 12) {
            g2_load(sb, b, nt0, ct0, kt+1, (kt+1) & 1, t);
            cp_commit();
            cp_wait1();
        } else cp_wait0();
        __syncthreads();
        uint32_t base = sb + (uint32_t)(kt & 1)*G2_BUF*2;
        #pragma unroll
        for (int kk = 0; kk < 2; kk++) {
            int kb = kk*16;
            uint32_t ah[2][4], al[2][4];
            #pragma unroll
            for (int mt = 0; mt < 2; mt++) {
                int row = wn + mt*16 + (lane & 15);
                int col = kb + ((lane & 16) ? 8 : 0);
                uint32_t off = (uint32_t)(row*40 + col)*2;
                ldm_x4(ah[mt], base + G2_AH*2 + off);
                ldm_x4(al[mt], base + G2_AL*2 + off);
            }
            uint32_t bh[4][2], bl[4][2];
            #pragma unroll
            for (int p = 0; p < 2; p++) {
                int crow = wc + p*16 + (lane & 7) + ((lane & 16) ? 8 : 0);
                int col = kb + ((lane & 8) ? 8 : 0);
                uint32_t off = (uint32_t)(crow*40 + col)*2;
                uint32_t r4[4];
                ldm_x4(r4, base + G2_BH*2 + off);
                bh[2*p][0]=r4[0]; bh[2*p][1]=r4[1]; bh[2*p+1][0]=r4[2]; bh[2*p+1][1]=r4[3];
                ldm_x4(r4, base + G2_BL*2 + off);
                bl[2*p][0]=r4[0]; bl[2*p][1]=r4[1]; bl[2*p+1][0]=r4[2]; bl[2*p+1][1]=r4[3];
            }
            #pragma unroll
            for (int mt = 0; mt < 2; mt++)
                #pragma unroll
                for (int ct = 0; ct < 4; ct++) {
                    mma_bf16(acc[mt][ct], ah[mt], bh[ct]);
                    mma_bf16(acc[mt][ct], al[mt], bh[ct]);
                    mma_bf16(acc[mt][ct], ah[mt], bl[ct]);
                }
        }
        __syncthreads();
    }
    int nrow = nt0 + wn + (lane >> 2);
    #pragma unroll
    for (int mt = 0; mt < 2; mt++) {
        #pragma unroll
        for (int ct = 0; ct < 4; ct++) {
            int c0 = ct0 + wc + ct*8 + ((lane & 3) << 1);
            float b0 = g_bias2[b*512 + c0];
            float b1 = g_bias2[b*512 + c0 + 1];
            #pragma unroll
            for (int half = 0; half < 2; half++) {
                int n = nrow + mt*16 + half*8;
                if (n < 3136) {
                    size_t o = ((size_t)b*3136 + n)*512 + c0;
                    *(float2*)&out[o] = make_float2(acc[mt][ct][half*2] + b0,
                                                    acc[mt][ct][half*2+1] + b1);
                }
            }
        }
    }
}

// ---------------- launcher ----------------
extern "C" void kernel_launch(void* const* d_in, const int* in_sizes, int n_in,
                              void* d_out, int out_size) {
    const float* x        = (const float*)d_in[0];
    const float* q_w      = (const float*)d_in[1];
    const float* down_w   = (const float*)d_in[2];
    const float* kv_w     = (const float*)d_in[3];
    const float* proj_w   = (const float*)d_in[4];
    const float* proj_b   = (const float*)d_in[5];
    const float* rel_bias = (const float*)d_in[6];
    const float* expand_w = (const float*)d_in[7];
    const float* gn1_s    = (const float*)d_in[8];
    const float* gn1_b    = (const float*)d_in[9];
    const float* dw_w     = (const float*)d_in[10];
    const float* gn2_s    = (const float*)d_in[11];
    const float* gn2_b    = (const float*)d_in[12];
    const float* reduce_w = (const float*)d_in[13];
    const float* gn3_s    = (const float*)d_in[14];
    const float* gn3_b    = (const float*)d_in[15];
    float* out = (float*)d_out;

    float *ab2, *ab3, *p2, *p3;
    cudaGetSymbolAddress((void**)&ab2, g_ab2);
    cudaGetSymbolAddress((void**)&ab3, g_ab3);
    cudaGetSymbolAddress((void**)&p2, g_part2);
    cudaGetSymbolAddress((void**)&p3, g_part3);

    cudaFuncSetAttribute(k_gemm1_fused, cudaFuncAttributeMaxDynamicSharedMemorySize, G1_SMEM);
    cudaFuncSetAttribute(k_gemm2_mma, cudaFuncAttributeMaxDynamicSharedMemorySize, G2_SMEM);
    cudaFuncSetAttribute(k_dw_gn2,    cudaFuncAttributeMaxDynamicSharedMemorySize, B_SMEM);
    cudaFuncSetAttribute(k_dla_out,   cudaFuncAttributeMaxDynamicSharedMemorySize, C_SMEM);

    k_prep<<<33280, 256>>>(x, down_w);
    k_kv  <<<dim3(4, 7, BB), 256>>>(kv_w);
    k_qkvw<<<1152, 256>>>(q_w, proj_w);
    k_gemm1_fused<<<dim3(49, BB), 256, G1_SMEM>>>(rel_bias);
    k_gn1_final<<<BB, 64>>>(gn1_s, gn1_b, expand_w);
    k_dw_gn2<<<dim3(196, BB), 256, B_SMEM>>>(dw_w, expand_w);
    k_stats_final<<<BB*3, 256>>>(gn2_s, gn2_b, ab2, p2, 3, 196);
    k_dla_out<<<dim3(392, BB), 256, C_SMEM>>>(dw_w, expand_w, reduce_w);
    k_stats_final<<<BB, 256>>>(gn3_s, gn3_b, ab3, p3, 1, 392);
    k_wvpfin<<<3344, 256>>>(proj_b);
    k_gemm2_mma<<<dim3(8, 25, BB), 256, G2_SMEM>>>(out);
}

// round 11
// speedup vs baseline: 1.0853x; 1.0508x over previous
#include <cuda_runtime.h>
#include <cuda_bf16.h>
#include <math.h>
#include <stdint.h>

#define BB    16
#define CCH   512
#define NN    3136
#define NKK   49
#define HEADS 8
#define JJ    392
#define HIDC  24
#define SCALE 0.125f

// ---------------- device scratch ----------------
__device__ float g_kvx[BB*NKK*CCH];
__device__ float g_kv [BB*NKK*1024];
__device__ float g_Wvp[BB*JJ*CCH];
__device__ __nv_bfloat16 g_xTh[(size_t)BB*NN*CCH];
__device__ __nv_bfloat16 g_xTl[(size_t)BB*NN*CCH];
__device__ __nv_bfloat16 g_wqh[BB*JJ*CCH];
__device__ __nv_bfloat16 g_wvh[BB*CCH*JJ];
__device__ __nv_bfloat16 g_wvl[BB*CCH*JJ];
__device__ float g_attn[(size_t)BB*NN*JJ];
__device__ __nv_bfloat16 g_ath[(size_t)BB*NN*JJ];
__device__ __nv_bfloat16 g_atl[(size_t)BB*NN*JJ];
__device__ float g_part1[BB*49*36];
__device__ float g_part2[BB*3*196*2];
__device__ float g_part3[BB*392*2];
__device__ float g_ab1[BB*HIDC*2];
__device__ float g_ab2[BB*HIDC*2];
__device__ float g_ab3[BB*HEADS*2];
__device__ float g_bias2[BB*CCH];

__device__ __forceinline__ float swishf(float x) { return x / (1.f + __expf(-x)); }

__device__ __forceinline__ void bsplit(float v, __nv_bfloat16& h, __nv_bfloat16& l) {
    h = __float2bfloat16(v);
    l = __float2bfloat16(v - __bfloat162float(h));
}

__device__ __forceinline__ uint32_t smem_u32(const void* p) {
    uint32_t a;
    asm("{ .reg .u64 t; cvta.to.shared.u64 t, %1; cvt.u32.u64 %0, t; }" : "=r"(a) : "l"(p));
    return a;
}
__device__ __forceinline__ void ldm_x4(uint32_t* r, uint32_t addr) {
    asm volatile("ldmatrix.sync.aligned.m8n8.x4.shared.b16 {%0,%1,%2,%3}, [%4];"
        : "=r"(r[0]), "=r"(r[1]), "=r"(r[2]), "=r"(r[3]) : "r"(addr));
}
__device__ __forceinline__ void ldm_x2(uint32_t* r, uint32_t addr) {
    asm volatile("ldmatrix.sync.aligned.m8n8.x2.shared.b16 {%0,%1}, [%2];"
        : "=r"(r[0]), "=r"(r[1]) : "r"(addr));
}
__device__ __forceinline__ void mma_bf16(float* c, const uint32_t* a, const uint32_t* b) {
    asm volatile(
        "mma.sync.aligned.m16n8k16.row.col.f32.bf16.bf16.f32 "
        "{%0,%1,%2,%3}, {%4,%5,%6,%7}, {%8,%9}, {%0,%1,%2,%3};"
        : "+f"(c[0]), "+f"(c[1]), "+f"(c[2]), "+f"(c[3])
        : "r"(a[0]), "r"(a[1]), "r"(a[2]), "r"(a[3]), "r"(b[0]), "r"(b[1]));
}
__device__ __forceinline__ void cpa16(uint32_t dst, const void* src, bool v) {
    int sz = v ? 16 : 0;
    asm volatile("cp.async.cg.shared.global [%0], [%1], 16, %2;"
        :: "r"(dst), "l"(src), "r"(sz) : "memory");
}
__device__ __forceinline__ void cp_commit() {
    asm volatile("cp.async.commit_group;" ::: "memory");
}
__device__ __forceinline__ void cp_wait1() {
    asm volatile("cp.async.wait_group 1;" ::: "memory");
}
__device__ __forceinline__ void cp_wait0() {
    asm volatile("cp.async.wait_group 0;" ::: "memory");
}

// ---------------- 1. k_prep: fused xsplit (blocks 0..25087) + down (blocks 25088..33279) ----------------
__global__ __launch_bounds__(256) void k_prep(const float* __restrict__ x,
                                              const float* __restrict__ down_w) {
    __shared__ float sh[3200];
    int blk = blockIdx.x;
    int t = threadIdx.x;
    if (blk < 25088) {
        int tn = blk % 98;
        int rest = blk / 98;
        int tc = rest & 15, b = rest >> 4;
        float (*tile)[33] = (float(*)[33])sh;
        int a = t >> 5, q = t & 31;
        #pragma unroll
        for (int r = 0; r < 4; r++) {
            int cc = tc*32 + a + r*8, nn = tn*32 + q;
            tile[a + r*8][q] = x[((size_t)b*512 + cc)*3136 + nn];
        }
        __syncthreads();
        #pragma unroll
        for (int r = 0; r < 4; r++) {
            int nn = tn*32 + a + r*8, cc = tc*32 + q;
            float v = tile[q][a + r*8];
            __nv_bfloat16 h, l; bsplit(v, h, l);
            size_t o = ((size_t)b*3136 + nn)*512 + cc;
            g_xTh[o] = h; g_xTl[o] = l;
        }
    } else {
        int bc = blk - 25088, c = bc & 511, b = bc >> 9;
        float* plane = sh;
        float* w = sh + 3136;
        const float* xp = x + (size_t)bc * 3136;
        for (int i = t; i < 3136; i += 256) plane[i] = xp[i];
        if (t < 64) w[t] = down_w[c*64 + t];
        __syncthreads();
        if (t < 49) {
            int my = t / 7, mx = t % 7;
            float s = 0.f;
            #pragma unroll
            for (int i = 0; i < 8; i++)
                #pragma unroll
                for (int j = 0; j < 8; j++)
                    s += plane[(my*8+i)*56 + mx*8 + j] * w[i*8+j];
            g_kvx[(b*49 + t)*512 + c] = s;
        }
    }
}

// ---------------- 2. kv = kvx @ kv_w ----------------
__global__ void k_kv(const float* __restrict__ kv_w) {
    int b = blockIdx.z, m0 = blockIdx.y * 7, oc = blockIdx.x;
    __shared__ float a[7][512];
    for (int i = threadIdx.x; i < 7*512; i += 256)
        a[i >> 9][i & 511] = g_kvx[(b*49 + m0 + (i >> 9))*512 + (i & 511)];
    __syncthreads();
    int o = oc*256 + threadIdx.x;
    float acc[7] = {0,0,0,0,0,0,0};
    for (int c = 0; c < 512; c++) {
        float w = kv_w[c*1024 + o];
        #pragma unroll
        for (int mm = 0; mm < 7; mm++) acc[mm] += a[mm][c] * w;
    }
    #pragma unroll
    for (int mm = 0; mm < 7; mm++)
        g_kv[(b*49 + m0 + mm)*1024 + o] = acc[mm];
}

// ---------------- 3. k_qkvw: fused wqk_split (blocks 0..255, high-only) + wvp (256..1151) ----------------
__global__ __launch_bounds__(256) void k_qkvw(const float* __restrict__ q_w,
                                              const float* __restrict__ proj_w) {
    __shared__ float sh[3136];
    int blk = blockIdx.x;
    int t = threadIdx.x;
    if (blk < 256) {
        int half = blk & 1, h = (blk >> 1) & 7, b = blk >> 4;
        float (*ks)[64] = (float(*)[64])sh;
        for (int i = t; i < 49*64; i += 256)
            ks[i >> 6][i & 63] = g_kv[(b*49 + (i >> 6))*1024 + h*64 + (i & 63)];
        __syncthreads();
        int cin = half*256 + t;
        float acc[49];
        #pragma unroll
        for (int m = 0; m < 49; m++) acc[m] = 0.f;
        const float4* q4 = (const float4*)(q_w + (size_t)cin*512 + h*64);
        const float4* ks4 = (const float4*)&ks[0][0];
        for (int d4 = 0; d4 < 16; d4++) {
            float4 q = __ldg(q4 + d4);
            #pragma unroll
            for (int m = 0; m < 49; m++) {
                float4 k = ks4[m*16 + d4];
                acc[m] += q.x*k.x + q.y*k.y + q.z*k.z + q.w*k.w;
            }
        }
        size_t obase = ((size_t)b*392 + h*49)*512 + cin;
        #pragma unroll
        for (int m = 0; m < 49; m++)
            g_wqh[obase + (size_t)m*512] = __float2bfloat16(acc[m] * SCALE);
    } else {
        int q = blk - 256;
        int mc = (q % 7) * 7, h = (q / 7) & 7, b = q / 56;
        float (*vs)[64] = (float(*)[64])sh;
        for (int i = t; i < 7*64; i += 256)
            vs[i >> 6][i & 63] = g_kv[(b*49 + mc + (i >> 6))*1024 + 512 + h*64 + (i & 63)];
        __syncthreads();
        float acc[7][2] = {{0}};
        for (int d = 0; d < 64; d++) {
            float w0 = proj_w[(h*64+d)*512 + t];
            float w1 = proj_w[(h*64+d)*512 + 256 + t];
            #pragma unroll
            for (int mm = 0; mm < 7; mm++) {
                float vv = vs[mm][d];
                acc[mm][0] += vv * w0;
                acc[mm][1] += vv * w1;
            }
        }
        #pragma unroll
        for (int mm = 0; mm < 7; mm++) {
            int j = h*49 + mc + mm;
            g_Wvp[(b*392 + j)*512 + t]       = acc[mm][0];
            g_Wvp[(b*392 + j)*512 + 256 + t] = acc[mm][1];
        }
    }
}

// ---------------- 4. GEMM1 fused (bf16x2: ah*bh + al*bh; k-tile 32, double-buffered, 2 CTAs/SM) ----------------
#define G1_BUFSZ 43520u
#define G1_AHOFF 0u
#define G1_ALOFF 5120u
#define G1_BHOFF 10240u
#define G1_SMEM  103552
__device__ __forceinline__ void g1f_load(uint32_t sb, int b, int nt0, int kt, int p, int t) {
    int k0 = kt*32;
    uint32_t base = sb + (uint32_t)p*G1_BUFSZ;
    {
        int row = t >> 2, q = t & 3;
        size_t e = ((size_t)b*3136 + nt0 + row)*512 + k0 + q*8;
        uint32_t doff = (uint32_t)(row*40 + q*8)*2;
        cpa16(base + G1_AHOFF + doff, g_xTh + e, true);
        cpa16(base + G1_ALOFF + doff, g_xTl + e, true);
    }
    #pragma unroll
    for (int rr = 0; rr < 7; rr++) {
        int idx = rr*256 + t;
        if (idx < 1664) {
            int row = idx >> 2, q = idx & 3;
            bool v = row < 392;
            size_t e = ((size_t)b*392 + (v ? row : 0))*512 + k0 + q*8;
            uint32_t doff = (uint32_t)(row*40 + q*8)*2;
            cpa16(base + G1_BHOFF + doff, g_wqh + e, v);
        }
    }
}

__global__ __launch_bounds__(256) void k_gemm1_fused(const float* __restrict__ rel_bias) {
    extern __shared__ char smraw[];
    uint32_t sb = smem_u32(smraw);
    int b = blockIdx.y, nt0 = blockIdx.x * 64;
    int t = threadIdx.x, w = t >> 5, lane = t & 31;
    int wn = (w & 1)*32, wj = (w >> 1)*104;
    float acc[2][13][4];
    #pragma unroll
    for (int i = 0; i < 2; i++)
        #pragma unroll
        for (int j = 0; j < 13; j++)
            #pragma unroll
            for (int k = 0; k < 4; k++) acc[i][j][k] = 0.f;

    g1f_load(sb, b, nt0, 0, 0, t);
    cp_commit();
    for (int kt = 0; kt < 16; kt++) {
        if (kt < 15) {
            g1f_load(sb, b, nt0, kt+1, (kt+1) & 1, t);
            cp_commit();
            cp_wait1();
        } else cp_wait0();
        __syncthreads();
        uint32_t base = sb + (uint32_t)(kt & 1)*G1_BUFSZ;
        #pragma unroll
        for (int kk = 0; kk < 2; kk++) {
            int kb = kk*16;
            uint32_t ah[2][4], al[2][4];
            int arow = wn + (lane & 15);
            int acol = kb + ((lane & 16) ? 8 : 0);
            ldm_x4(ah[0], base + G1_AHOFF + (uint32_t)(arow*40 + acol)*2);
            ldm_x4(ah[1], base + G1_AHOFF + (uint32_t)((arow+16)*40 + acol)*2);
            ldm_x4(al[0], base + G1_ALOFF + (uint32_t)(arow*40 + acol)*2);
            ldm_x4(al[1], base + G1_ALOFF + (uint32_t)((arow+16)*40 + acol)*2);
            #pragma unroll
            for (int p2 = 0; p2 < 6; p2++) {
                int jrow = wj + p2*16 + (lane & 7) + ((lane & 16) ? 8 : 0);
                int col = kb + ((lane & 8) ? 8 : 0);
                uint32_t off = (uint32_t)(jrow*40 + col)*2;
                uint32_t rh[4];
                ldm_x4(rh, base + G1_BHOFF + off);
                #pragma unroll
                for (int mt = 0; mt < 2; mt++)
                    #pragma unroll
                    for (int e = 0; e < 2; e++) {
                        mma_bf16(acc[mt][2*p2+e], ah[mt], &rh[2*e]);
                        mma_bf16(acc[mt][2*p2+e], al[mt], &rh[2*e]);
                    }
            }
            {
                int jrow = wj + 96 + (lane & 7);
                int col = kb + ((lane & 8) ? 8 : 0);
                uint32_t off = (uint32_t)(jrow*40 + col)*2;
                uint32_t bh2[2];
                ldm_x2(bh2, base + G1_BHOFF + off);
                #pragma unroll
                for (int mt = 0; mt < 2; mt++) {
                    mma_bf16(acc[mt][12], ah[mt], bh2);
                    mma_bf16(acc[mt][12], al[mt], bh2);
                }
            }
        }
        __syncthreads();
    }
    // ---- epilogue: stage logits in SMEM ----
    float* S = (float*)smraw;            // [64][400]
    float* Gred = S + 64*400;            // [8][36]
    #pragma unroll
    for (int mt = 0; mt < 2; mt++) {
        int nl = wn + mt*16 + (lane >> 2);
        #pragma unroll
        for (int jt = 0; jt < 13; jt++) {
            int j0 = wj + jt*8 + ((lane & 3) << 1);
            if (j0 < 392) {
                S[nl*400 + j0]       = acc[mt][jt][0];
                S[nl*400 + j0 + 1]   = acc[mt][jt][1];
                S[(nl+8)*400 + j0]   = acc[mt][jt][2];
                S[(nl+8)*400 + j0+1] = acc[mt][jt][3];
            }
        }
    }
    __syncthreads();
    #pragma unroll
    for (int rr = 0; rr < 2; rr++) {
        int row = t + rr*256;
        int n = row >> 3, h = row & 7;
        float* p = S + n*400 + h*49;
        const float* rb = rel_bias + (size_t)(nt0 + n)*49;
        float mx = -1e30f;
        for (int i = 0; i < 49; i++) {
            float lv = p[i] + __ldg(rb + i);
            p[i] = lv;
            mx = fmaxf(mx, lv);
        }
        float sum = 0.f;
        for (int i = 0; i < 49; i++) { float e = __expf(p[i] - mx); p[i] = e; sum += e; }
        float inv = 1.f / sum;
        for (int i = 0; i < 49; i++) p[i] *= inv;
    }
    __syncthreads();
    float g[36];
    #pragma unroll
    for (int k = 0; k < 36; k++) g[k] = 0.f;
    for (int pos = t; pos < 64*49; pos += 256) {
        int n = pos / 49, m = pos - n*49;
        float a[8];
        #pragma unroll
        for (int h = 0; h < 8; h++) a[h] = S[n*400 + h*49 + m];
        int k = 0;
        #pragma unroll
        for (int h = 0; h < 8; h++)
            #pragma unroll
            for (int h2 = h; h2 < 8; h2++) { g[k] += a[h]*a[h2]; k++; }
    }
    size_t ob = ((size_t)b*3136 + nt0)*392;
    for (int i = t; i < 64*392; i += 256) {
        int n = i / 392, c = i - n*392;
        g_attn[ob + i] = S[n*400 + c];
    }
    #pragma unroll
    for (int s = 16; s; s >>= 1)
        #pragma unroll
        for (int k = 0; k < 36; k++) g[k] += __shfl_xor_sync(0xffffffffu, g[k], s);
    if (lane == 0)
        #pragma unroll
        for (int k = 0; k < 36; k++) Gred[w*36 + k] = g[k];
    __syncthreads();
    if (t < 36) {
        float s = 0.f;
        #pragma unroll
        for (int ww = 0; ww < 8; ww++) s += Gred[ww*36 + t];
        g_part1[((size_t)b*49 + blockIdx.x)*36 + t] = s;
    }
}

// ---------------- 5. gn1 finalize from Gram ----------------
__global__ void k_gn1_final(const float* __restrict__ gs, const float* __restrict__ gb,
                            const float* __restrict__ ew) {
    int b = blockIdx.x, t = threadIdx.x;   // 64 threads
    __shared__ float M36[36];
    __shared__ float Mf[64];
    __shared__ float s1s[24], sqs[24];
    __shared__ float mg[3], rg[3];
    if (t < 36) {
        float s = 0.f;
        for (int nt = 0; nt < 49; nt++) s += g_part1[((size_t)b*49 + nt)*36 + t];
        M36[t] = s;
    }
    __syncthreads();
    if (t == 0) {
        int k = 0;
        for (int h = 0; h < 8; h++)
            for (int h2 = h; h2 < 8; h2++) { Mf[h*8+h2] = M36[k]; Mf[h2*8+h] = M36[k]; k++; }
    }
    __syncthreads();
    if (t < 24) {
        float wv[8], sw = 0.f;
        #pragma unroll
        for (int h = 0; h < 8; h++) { wv[h] = ew[t*8+h]; sw += wv[h]; }
        float sq = 0.f;
        #pragma unroll
        for (int h = 0; h < 8; h++)
            #pragma unroll
            for (int h2 = 0; h2 < 8; h2++) sq += wv[h]*wv[h2]*Mf[h*8+h2];
        s1s[t] = 3136.f * sw;
        sqs[t] = sq;
    }
    __syncthreads();
    if (t < 3) {
        float s1 = 0.f, sq = 0.f;
        for (int c = 0; c < 8; c++) { s1 += s1s[t*8+c]; sq += sqs[t*8+c]; }
        float cnt = 8.f*3136.f*49.f;
        float mean = s1/cnt;
        float var  = sq/cnt - mean*mean;
        mg[t] = mean;
        rg[t] = rsqrtf(var + 1e-5f);
    }
    __syncthreads();
    if (t < 24) {
        float A = rg[t>>3]*gs[t];
        g_ab1[(b*24 + t)*2]     = A;
        g_ab1[(b*24 + t)*2 + 1] = gb[t] - mg[t>>3]*A;
    }
}

// ---------------- stats finalize (gn2/gn3) ----------------
__global__ void k_stats_final(const float* __restrict__ gs, const float* __restrict__ gb,
                              float* __restrict__ ab, const float* __restrict__ part,
                              int G, int npart) {
    int b = blockIdx.x / G, g = blockIdx.x % G;
    const float* p = part + (size_t)(b*G + g)*npart*2;
    float sm = 0.f, sq = 0.f;
    for (int i = threadIdx.x; i < npart; i += 256) { sm += p[2*i]; sq += p[2*i+1]; }
    __shared__ float rs[256], rq[256];
    __shared__ float mean_s, rstd_s;
    int t = threadIdx.x;
    rs[t] = sm; rq[t] = sq;
    __syncthreads();
    for (int st = 128; st; st >>= 1) {
        if (t < st) { rs[t] += rs[t+st]; rq[t] += rq[t+st]; }
        __syncthreads();
    }
    if (!t) {
        float cnt  = 8.f * 3136.f * 49.f;
        float mean = rs[0] / cnt;
        float var  = rq[0] / cnt - mean*mean;
        mean_s = mean;
        rstd_s = rsqrtf(var + 1e-5f);
    }
    __syncthreads();
    if (t < 8) {
        int c = g*8 + t;
        float A = rstd_s * gs[c];
        int CH = G*8;
        ab[(b*CH + c)*2]     = A;
        ab[(b*CH + c)*2 + 1] = gb[c] - mean_s*A;
    }
}

// ---------------- 6. pass B: warp-parallel expand+dw -> gn2 partials ----------------
#define B_AT  0
#define B_HID 7056
#define B_EW  14416
#define B_AB  14608
#define B_RED 14656
#define B_TOT (14656 + 1536)
#define B_SMEM (B_TOT*4)
__global__ __launch_bounds__(256) void k_dw_gn2(const float* __restrict__ dw_w,
                                                const float* __restrict__ expand_w) {
    extern __shared__ float sm[];
    float* at  = sm + B_AT;
    float* ew  = sm + B_EW;
    float* ab  = sm + B_AB;
    float* red = sm + B_RED;
    int nt = blockIdx.x, b = blockIdx.y, t = threadIdx.x;
    int w = t >> 5, lane = t & 31;
    float* hid = sm + B_HID + w*920;
    int n0 = nt * 16;
    if (t < 192) ew[t] = expand_w[t];
    if (t >= 192 && t < 240) ab[t-192] = g_ab1[b*48 + (t-192)];
    for (int i = t; i < 18*392; i += 256) {
        int r = i / 392, m = i - r*392;
        int n = n0 - 1 + r;
        at[i] = (n >= 0 && n < 3136) ? g_attn[((size_t)b*3136 + n)*392 + m] : 0.f;
    }
    __syncthreads();
    float sk[3] = {0,0,0}, qk[3] = {0,0,0};
    #pragma unroll
    for (int k = 0; k < 3; k++) {
        int c = w + k*8;
        float A1 = ab[c*2], B1 = ab[c*2+1];
        const float* wp = ew + c*8;
        for (int i = lane; i < 918; i += 32) {
            int r = i / 51, mm = i - r*51;
            int n = n0 - 1 + r;
            float v = 0.f;
            if (mm >= 1 && mm <= 49 && n >= 0 && n < 3136) {
                const float* sp = at + r*392 + (mm - 1);
                float hsum = 0.f;
                #pragma unroll
                for (int hh = 0; hh < 8; hh++) hsum += sp[hh*49] * wp[hh];
                v = swishf(A1*hsum + B1);
            }
            hid[i] = v;
        }
        __syncwarp();
        float lw[9];
        #pragma unroll
        for (int i = 0; i < 9; i++) lw[i] = dw_w[c*9 + i];
        for (int o = lane; o < 784; o += 32) {
            int ny = o / 49, m = o - ny*49;
            float a = 0.f;
            #pragma unroll
            for (int dy = 0; dy < 3; dy++)
                #pragma unroll
                for (int dx = 0; dx < 3; dx++)
                    a += hid[(ny+dy)*51 + m+dx] * lw[dy*3+dx];
            sk[k] += a; qk[k] += a*a;
        }
        __syncwarp();
    }
    #pragma unroll
    for (int g = 0; g < 3; g++) { red[g*256 + t] = sk[g]; red[(3+g)*256 + t] = qk[g]; }
    __syncthreads();
    for (int st = 128; st; st >>= 1) {
        if (t < st)
            #pragma unroll
            for (int g = 0; g < 6; g++) red[g*256 + t] += red[g*256 + t + st];
        __syncthreads();
    }
    if (t < 3) {
        g_part2[((b*3 + t)*196 + nt)*2]     = red[t*256];
        g_part2[((b*3 + t)*196 + nt)*2 + 1] = red[(t+3)*256];
    }
}

// ---------------- 7. pass C: expand+dw+norm2+swish, reduce -> attnF + gn3 ----------------
#define C_AT  0
#define C_HID 3920
#define C_DWS 8016
#define C_EW  17424
#define C_RW  17616
#define C_AB  17808
#define C_RED 17904
#define C_TOT (17904 + 512)
#define C_SMEM (C_TOT*4)
__global__ __launch_bounds__(256) void k_dla_out(const float* __restrict__ dw_w,
                                                 const float* __restrict__ expand_w,
                                                 const float* __restrict__ reduce_w) {
    extern __shared__ float sm[];
    float* at  = sm + C_AT;
    float* dws = sm + C_DWS;
    float* ew  = sm + C_EW;
    float* rw  = sm + C_RW;
    float* ab  = sm + C_AB;
    float* red = sm + C_RED;
    int nt = blockIdx.x, b = blockIdx.y, t = threadIdx.x;
    int w = t >> 5, lane = t & 31;
    float* hid = sm + C_HID + w*512;
    int n0 = nt * 8;
    if (t < 192) { ew[t] = expand_w[t]; rw[t] = reduce_w[t]; }
    if (t < 96) ab[t] = (t < 48) ? g_ab1[b*48 + t] : g_ab2[b*48 + (t-48)];
    for (int i = t; i < 10*392; i += 256) {
        int r = i / 392, m = i - r*392;
        int n = n0 - 1 + r;
        at[i] = (n >= 0 && n < 3136) ? g_attn[((size_t)b*3136 + n)*392 + m] : 0.f;
    }
    __syncthreads();
    #pragma unroll
    for (int k = 0; k < 3; k++) {
        int c = w + k*8;
        float A1 = ab[c*2], B1 = ab[c*2+1];
        float A2 = ab[48 + c*2], B2 = ab[49 + c*2];
        const float* wp = ew + c*8;
        for (int i = lane; i < 510; i += 32) {
            int r = i / 51, mm = i - r*51;
            int n = n0 - 1 + r;
            float v = 0.f;
            if (mm >= 1 && mm <= 49 && n >= 0 && n < 3136) {
                const float* sp = at + r*392 + (mm - 1);
                float hsum = 0.f;
                #pragma unroll
                for (int hh = 0; hh < 8; hh++) hsum += sp[hh*49] * wp[hh];
                v = swishf(A1*hsum + B1);
            }
            hid[i] = v;
        }
        __syncwarp();
        float lw[9];
        #pragma unroll
        for (int i = 0; i < 9; i++) lw[i] = dw_w[c*9 + i];
        for (int o = lane; o < 392; o += 32) {
            int ny = o / 49, m = o - ny*49;
            float a = 0.f;
            #pragma unroll
            for (int dy = 0; dy < 3; dy++)
                #pragma unroll
                for (int dx = 0; dx < 3; dx++)
                    a += hid[(ny+dy)*51 + m+dx] * lw[dy*3+dx];
            dws[(ny*24 + c)*49 + m] = swishf(A2*a + B2);
        }
        __syncwarp();
    }
    __syncthreads();
    float lsum = 0.f, lsq = 0.f;
    for (int o = t; o < 392; o += 256) {
        int ny = o / 49, m = o - ny*49;
        int n = n0 + ny;
        float in[24];
        #pragma unroll
        for (int c = 0; c < 24; c++) in[c] = dws[(ny*24 + c)*49 + m];
        size_t ob = ((size_t)b*3136 + n)*392 + m;
        #pragma unroll
        for (int h = 0; h < 8; h++) {
            float r = 0.f;
            #pragma unroll
            for (int c = 0; c < 24; c++) r += in[c] * rw[h*24 + c];
            __nv_bfloat16 hh, ll; bsplit(r, hh, ll);
            g_ath[ob + h*49] = hh;
            g_atl[ob + h*49] = ll;
            lsum += r; lsq += r*r;
        }
    }
    red[t] = lsum; red[256 + t] = lsq;
    __syncthreads();
    for (int st = 128; st; st >>= 1) {
        if (t < st) { red[t] += red[t+st]; red[256+t] += red[256+t+st]; }
        __syncthreads();
    }
    if (!t) {
        g_part3[(b*392 + nt)*2]     = red[0];
        g_part3[(b*392 + nt)*2 + 1] = red[256];
    }
}

// ---------------- 8. k_wvpfin: fused wvpsplit (blocks 0..3327) + wvpbias (3328..3343) ----------------
__global__ __launch_bounds__(256) void k_wvpfin(const float* __restrict__ proj_b) {
    __shared__ float tile[32][33];
    int blk = blockIdx.x;
    int t = threadIdx.x;
    if (blk < 3328) {
        int tj = blk % 13;
        int rest = blk / 13;
        int tc = rest & 15, b = rest >> 4;
        int a = t >> 5, q = t & 31;
        #pragma unroll
        for (int r = 0; r < 4; r++) {
            int jj = tj*32 + a + r*8, cc = tc*32 + q;
            float v = 0.f;
            if (jj < 392) v = g_Wvp[((size_t)b*392 + jj)*512 + cc] * g_ab3[(b*8 + jj/49)*2];
            tile[a + r*8][q] = v;
        }
        __syncthreads();
        #pragma unroll
        for (int r = 0; r < 4; r++) {
            int cc = tc*32 + a + r*8, jj = tj*32 + q;
            if (jj < 392) {
                float v = tile[q][a + r*8];
                __nv_bfloat16 h, l; bsplit(v, h, l);
                size_t o = ((size_t)b*512 + cc)*392 + jj;
                g_wvh[o] = h; g_wvl[o] = l;
            }
        }
    } else {
        int b = blk - 3328;
        #pragma unroll
        for (int cc = 0; cc < 2; cc++) {
            int c = t + cc*256;
            float acc = 0.f;
            for (int j = 0; j < 392; j++)
                acc += g_ab3[(b*8 + j/49)*2 + 1] * g_Wvp[((size_t)b*392 + j)*512 + c];
            g_bias2[b*512 + c] = acc + proj_b[c];
        }
    }
}

// ---------------- 9. GEMM2 (bf16x3 mma.sync) ----------------
#define G2_BUF 15360
#define G2_AH 0
#define G2_AL 5120
#define G2_BH 10240
#define G2_BL 12800
#define G2_SMEM (G2_BUF*2*2)
__device__ __forceinline__ void g2_load(uint32_t sb, int b, int nt0, int ct0,
                                        int kt, int p, int t) {
    int k0 = kt*32;
    uint32_t base = sb + (uint32_t)p*G2_BUF*2;
    #pragma unroll
    for (int rr = 0; rr < 2; rr++) {
        int idx = t + rr*256;
        int row = idx >> 2, q = idx & 3;
        int n = nt0 + row, j0 = k0 + q*8;
        bool v = (n < 3136) && (j0 < 392);
        size_t e = ((size_t)b*3136 + (n < 3136 ? n : 0))*392 + (j0 < 392 ? j0 : 0);
        uint32_t doff = (uint32_t)(row*40 + q*8)*2;
        cpa16(base + G2_AH*2 + doff, g_ath + e, v);
        cpa16(base + G2_AL*2 + doff, g_atl + e, v);
    }
    {
        int idx = t;
        int row = idx >> 2, q = idx & 3;
        int c = ct0 + row, j0 = k0 + q*8;
        bool v = j0 < 392;
        size_t e = ((size_t)b*512 + c)*392 + (v ? j0 : 0);
        uint32_t doff = (uint32_t)(row*40 + q*8)*2;
        cpa16(base + G2_BH*2 + doff, g_wvh + e, v);
        cpa16(base + G2_BL*2 + doff, g_wvl + e, v);
    }
}

__global__ __launch_bounds__(256) void k_gemm2_mma(float* __restrict__ out) {
    extern __shared__ __nv_bfloat16 dsm2[];
    uint32_t sb = smem_u32(dsm2);
    int b = blockIdx.z, nt0 = blockIdx.y*128, ct0 = blockIdx.x*64;
    int t = threadIdx.x, w = t >> 5, lane = t & 31;
    int wn = (w & 3)*32, wc = (w >> 2)*32;
    float acc[2][4][4];
    #pragma unroll
    for (int i = 0; i < 2; i++)
        #pragma unroll
        for (int j = 0; j < 4; j++)
            #pragma unroll
            for (int k = 0; k < 4; k++) acc[i][j][k] = 0.f;

    g2_load(sb, b, nt0, ct0, 0, 0, t);
    cp_commit();
    for (int kt = 0; kt < 13; kt++) {
        if (kt < 12) {
            g2_load(sb, b, nt0, ct0, kt+1, (kt+1) & 1, t);
            cp_commit();
            cp_wait1();
        } else cp_wait0();
        __syncthreads();
        uint32_t base = sb + (uint32_t)(kt & 1)*G2_BUF*2;
        #pragma unroll
        for (int kk = 0; kk < 2; kk++) {
            int kb = kk*16;
            uint32_t ah[2][4], al[2][4];
            #pragma unroll
            for (int mt = 0; mt < 2; mt++) {
                int row = wn + mt*16 + (lane & 15);
                int col = kb + ((lane & 16) ? 8 : 0);
                uint32_t off = (uint32_t)(row*40 + col)*2;
                ldm_x4(ah[mt], base + G2_AH*2 + off);
                ldm_x4(al[mt], base + G2_AL*2 + off);
            }
            uint32_t bh[4][2], bl[4][2];
            #pragma unroll
            for (int p = 0; p < 2; p++) {
                int crow = wc + p*16 + (lane & 7) + ((lane & 16) ? 8 : 0);
                int col = kb + ((lane & 8) ? 8 : 0);
                uint32_t off = (uint32_t)(crow*40 + col)*2;
                uint32_t r4[4];
                ldm_x4(r4, base + G2_BH*2 + off);
                bh[2*p][0]=r4[0]; bh[2*p][1]=r4[1]; bh[2*p+1][0]=r4[2]; bh[2*p+1][1]=r4[3];
                ldm_x4(r4, base + G2_BL*2 + off);
                bl[2*p][0]=r4[0]; bl[2*p][1]=r4[1]; bl[2*p+1][0]=r4[2]; bl[2*p+1][1]=r4[3];
            }
            #pragma unroll
            for (int mt = 0; mt < 2; mt++)
                #pragma unroll
                for (int ct = 0; ct < 4; ct++) {
                    mma_bf16(acc[mt][ct], ah[mt], bh[ct]);
                    mma_bf16(acc[mt][ct], al[mt], bh[ct]);
                    mma_bf16(acc[mt][ct], ah[mt], bl[ct]);
                }
        }
        __syncthreads();
    }
    int nrow = nt0 + wn + (lane >> 2);
    #pragma unroll
    for (int mt = 0; mt < 2; mt++) {
        #pragma unroll
        for (int ct = 0; ct < 4; ct++) {
            int c0 = ct0 + wc + ct*8 + ((lane & 3) << 1);
            float b0 = g_bias2[b*512 + c0];
            float b1 = g_bias2[b*512 + c0 + 1];
            #pragma unroll
            for (int half = 0; half < 2; half++) {
                int n = nrow + mt*16 + half*8;
                if (n < 3136) {
                    size_t o = ((size_t)b*3136 + n)*512 + c0;
                    *(float2*)&out[o] = make_float2(acc[mt][ct][half*2] + b0,
                                                    acc[mt][ct][half*2+1] + b1);
                }
            }
        }
    }
}

// ---------------- launcher ----------------
extern "C" void kernel_launch(void* const* d_in, const int* in_sizes, int n_in,
                              void* d_out, int out_size) {
    const float* x        = (const float*)d_in[0];
    const float* q_w      = (const float*)d_in[1];
    const float* down_w   = (const float*)d_in[2];
    const float* kv_w     = (const float*)d_in[3];
    const float* proj_w   = (const float*)d_in[4];
    const float* proj_b   = (const float*)d_in[5];
    const float* rel_bias = (const float*)d_in[6];
    const float* expand_w = (const float*)d_in[7];
    const float* gn1_s    = (const float*)d_in[8];
    const float* gn1_b    = (const float*)d_in[9];
    const float* dw_w     = (const float*)d_in[10];
    const float* gn2_s    = (const float*)d_in[11];
    const float* gn2_b    = (const float*)d_in[12];
    const float* reduce_w = (const float*)d_in[13];
    const float* gn3_s    = (const float*)d_in[14];
    const float* gn3_b    = (const float*)d_in[15];
    float* out = (float*)d_out;

    float *ab2, *ab3, *p2, *p3;
    cudaGetSymbolAddress((void**)&ab2, g_ab2);
    cudaGetSymbolAddress((void**)&ab3, g_ab3);
    cudaGetSymbolAddress((void**)&p2, g_part2);
    cudaGetSymbolAddress((void**)&p3, g_part3);

    cudaFuncSetAttribute(k_gemm1_fused, cudaFuncAttributeMaxDynamicSharedMemorySize, G1_SMEM);
    cudaFuncSetAttribute(k_gemm2_mma, cudaFuncAttributeMaxDynamicSharedMemorySize, G2_SMEM);
    cudaFuncSetAttribute(k_dw_gn2,    cudaFuncAttributeMaxDynamicSharedMemorySize, B_SMEM);
    cudaFuncSetAttribute(k_dla_out,   cudaFuncAttributeMaxDynamicSharedMemorySize, C_SMEM);

    k_prep<<<33280, 256>>>(x, down_w);
    k_kv  <<<dim3(4, 7, BB), 256>>>(kv_w);
    k_qkvw<<<1152, 256>>>(q_w, proj_w);
    k_gemm1_fused<<<dim3(49, BB), 256, G1_SMEM>>>(rel_bias);
    k_gn1_final<<<BB, 64>>>(gn1_s, gn1_b, expand_w);
    k_dw_gn2<<<dim3(196, BB), 256, B_SMEM>>>(dw_w, expand_w);
    k_stats_final<<<BB*3, 256>>>(gn2_s, gn2_b, ab2, p2, 3, 196);
    k_dla_out<<<dim3(392, BB), 256, C_SMEM>>>(dw_w, expand_w, reduce_w);
    k_stats_final<<<BB, 256>>>(gn3_s, gn3_b, ab3, p3, 1, 392);
    k_wvpfin<<<3344, 256>>>(proj_b);
    k_gemm2_mma<<<dim3(8, 25, BB), 256, G2_SMEM>>>(out);
}

// round 12
// speedup vs baseline: 1.0955x; 1.0094x over previous
#include <cuda_runtime.h>
#include <cuda_bf16.h>
#include <math.h>
#include <stdint.h>

#define BB    16
#define CCH   512
#define NN    3136
#define NKK   49
#define HEADS 8
#define JJ    392
#define HIDC  24
#define SCALE 0.125f

// ---------------- device scratch ----------------
__device__ float g_kvx[BB*NKK*CCH];
__device__ float g_kv [BB*NKK*1024];
__device__ float g_Wvp[BB*JJ*CCH];
__device__ __nv_bfloat16 g_xTh[(size_t)BB*NN*CCH];
__device__ __nv_bfloat16 g_xTl[(size_t)BB*NN*CCH];
__device__ __nv_bfloat16 g_wqh[BB*JJ*CCH];
__device__ __nv_bfloat16 g_wvh[BB*CCH*JJ];
__device__ __nv_bfloat16 g_wvl[BB*CCH*JJ];
__device__ float g_attn[(size_t)BB*NN*JJ];
__device__ __nv_bfloat16 g_ath[(size_t)BB*NN*JJ];
__device__ __nv_bfloat16 g_atl[(size_t)BB*NN*JJ];
__device__ float g_part1[BB*49*36];
__device__ float g_part2[BB*3*196*2];
__device__ float g_part3[BB*392*2];
__device__ float g_ab1[BB*HIDC*2];
__device__ float g_ab2[BB*HIDC*2];
__device__ float g_ab3[BB*HEADS*2];
__device__ float g_bias2[BB*CCH];

__device__ __forceinline__ float swishf(float x) { return x / (1.f + __expf(-x)); }

__device__ __forceinline__ void bsplit(float v, __nv_bfloat16& h, __nv_bfloat16& l) {
    h = __float2bfloat16(v);
    l = __float2bfloat16(v - __bfloat162float(h));
}

__device__ __forceinline__ uint32_t smem_u32(const void* p) {
    uint32_t a;
    asm("{ .reg .u64 t; cvta.to.shared.u64 t, %1; cvt.u32.u64 %0, t; }" : "=r"(a) : "l"(p));
    return a;
}
__device__ __forceinline__ void ldm_x4(uint32_t* r, uint32_t addr) {
    asm volatile("ldmatrix.sync.aligned.m8n8.x4.shared.b16 {%0,%1,%2,%3}, [%4];"
        : "=r"(r[0]), "=r"(r[1]), "=r"(r[2]), "=r"(r[3]) : "r"(addr));
}
__device__ __forceinline__ void ldm_x2(uint32_t* r, uint32_t addr) {
    asm volatile("ldmatrix.sync.aligned.m8n8.x2.shared.b16 {%0,%1}, [%2];"
        : "=r"(r[0]), "=r"(r[1]) : "r"(addr));
}
__device__ __forceinline__ void mma_bf16(float* c, const uint32_t* a, const uint32_t* b) {
    asm volatile(
        "mma.sync.aligned.m16n8k16.row.col.f32.bf16.bf16.f32 "
        "{%0,%1,%2,%3}, {%4,%5,%6,%7}, {%8,%9}, {%0,%1,%2,%3};"
        : "+f"(c[0]), "+f"(c[1]), "+f"(c[2]), "+f"(c[3])
        : "r"(a[0]), "r"(a[1]), "r"(a[2]), "r"(a[3]), "r"(b[0]), "r"(b[1]));
}
__device__ __forceinline__ void cpa16(uint32_t dst, const void* src, bool v) {
    int sz = v ? 16 : 0;
    asm volatile("cp.async.cg.shared.global [%0], [%1], 16, %2;"
        :: "r"(dst), "l"(src), "r"(sz) : "memory");
}
__device__ __forceinline__ void cp_commit() {
    asm volatile("cp.async.commit_group;" ::: "memory");
}
__device__ __forceinline__ void cp_wait1() {
    asm volatile("cp.async.wait_group 1;" ::: "memory");
}
__device__ __forceinline__ void cp_wait0() {
    asm volatile("cp.async.wait_group 0;" ::: "memory");
}

// ---------------- 1. k_prep: fused xsplit (blocks 0..25087) + down (blocks 25088..33279) ----------------
__global__ __launch_bounds__(256) void k_prep(const float* __restrict__ x,
                                              const float* __restrict__ down_w) {
    __shared__ float sh[3200];
    int blk = blockIdx.x;
    int t = threadIdx.x;
    if (blk < 25088) {
        int tn = blk % 98;
        int rest = blk / 98;
        int tc = rest & 15, b = rest >> 4;
        float (*tile)[33] = (float(*)[33])sh;
        int a = t >> 5, q = t & 31;
        #pragma unroll
        for (int r = 0; r < 4; r++) {
            int cc = tc*32 + a + r*8, nn = tn*32 + q;
            tile[a + r*8][q] = x[((size_t)b*512 + cc)*3136 + nn];
        }
        __syncthreads();
        #pragma unroll
        for (int r = 0; r < 4; r++) {
            int nn = tn*32 + a + r*8, cc = tc*32 + q;
            float v = tile[q][a + r*8];
            __nv_bfloat16 h, l; bsplit(v, h, l);
            size_t o = ((size_t)b*3136 + nn)*512 + cc;
            g_xTh[o] = h; g_xTl[o] = l;
        }
    } else {
        int bc = blk - 25088, c = bc & 511, b = bc >> 9;
        float* plane = sh;
        float* w = sh + 3136;
        const float* xp = x + (size_t)bc * 3136;
        for (int i = t; i < 3136; i += 256) plane[i] = xp[i];
        if (t < 64) w[t] = down_w[c*64 + t];
        __syncthreads();
        if (t < 49) {
            int my = t / 7, mx = t % 7;
            float s = 0.f;
            #pragma unroll
            for (int i = 0; i < 8; i++)
                #pragma unroll
                for (int j = 0; j < 8; j++)
                    s += plane[(my*8+i)*56 + mx*8 + j] * w[i*8+j];
            g_kvx[(b*49 + t)*512 + c] = s;
        }
    }
}

// ---------------- 2. kv = kvx @ kv_w ----------------
__global__ void k_kv(const float* __restrict__ kv_w) {
    int b = blockIdx.z, m0 = blockIdx.y * 7, oc = blockIdx.x;
    __shared__ float a[7][512];
    for (int i = threadIdx.x; i < 7*512; i += 256)
        a[i >> 9][i & 511] = g_kvx[(b*49 + m0 + (i >> 9))*512 + (i & 511)];
    __syncthreads();
    int o = oc*256 + threadIdx.x;
    float acc[7] = {0,0,0,0,0,0,0};
    for (int c = 0; c < 512; c++) {
        float w = kv_w[c*1024 + o];
        #pragma unroll
        for (int mm = 0; mm < 7; mm++) acc[mm] += a[mm][c] * w;
    }
    #pragma unroll
    for (int mm = 0; mm < 7; mm++)
        g_kv[(b*49 + m0 + mm)*1024 + o] = acc[mm];
}

// ---------------- 3. k_qkvw: fused wqk_split (blocks 0..255, high-only) + wvp (256..1151) ----------------
__global__ __launch_bounds__(256) void k_qkvw(const float* __restrict__ q_w,
                                              const float* __restrict__ proj_w) {
    __shared__ float sh[3136];
    int blk = blockIdx.x;
    int t = threadIdx.x;
    if (blk < 256) {
        int half = blk & 1, h = (blk >> 1) & 7, b = blk >> 4;
        float (*ks)[64] = (float(*)[64])sh;
        for (int i = t; i < 49*64; i += 256)
            ks[i >> 6][i & 63] = g_kv[(b*49 + (i >> 6))*1024 + h*64 + (i & 63)];
        __syncthreads();
        int cin = half*256 + t;
        float acc[49];
        #pragma unroll
        for (int m = 0; m < 49; m++) acc[m] = 0.f;
        const float4* q4 = (const float4*)(q_w + (size_t)cin*512 + h*64);
        const float4* ks4 = (const float4*)&ks[0][0];
        for (int d4 = 0; d4 < 16; d4++) {
            float4 q = __ldg(q4 + d4);
            #pragma unroll
            for (int m = 0; m < 49; m++) {
                float4 k = ks4[m*16 + d4];
                acc[m] += q.x*k.x + q.y*k.y + q.z*k.z + q.w*k.w;
            }
        }
        size_t obase = ((size_t)b*392 + h*49)*512 + cin;
        #pragma unroll
        for (int m = 0; m < 49; m++)
            g_wqh[obase + (size_t)m*512] = __float2bfloat16(acc[m] * SCALE);
    } else {
        int q = blk - 256;
        int mc = (q % 7) * 7, h = (q / 7) & 7, b = q / 56;
        float (*vs)[64] = (float(*)[64])sh;
        for (int i = t; i < 7*64; i += 256)
            vs[i >> 6][i & 63] = g_kv[(b*49 + mc + (i >> 6))*1024 + 512 + h*64 + (i & 63)];
        __syncthreads();
        float acc[7][2] = {{0}};
        for (int d = 0; d < 64; d++) {
            float w0 = proj_w[(h*64+d)*512 + t];
            float w1 = proj_w[(h*64+d)*512 + 256 + t];
            #pragma unroll
            for (int mm = 0; mm < 7; mm++) {
                float vv = vs[mm][d];
                acc[mm][0] += vv * w0;
                acc[mm][1] += vv * w1;
            }
        }
        #pragma unroll
        for (int mm = 0; mm < 7; mm++) {
            int j = h*49 + mc + mm;
            g_Wvp[(b*392 + j)*512 + t]       = acc[mm][0];
            g_Wvp[(b*392 + j)*512 + 256 + t] = acc[mm][1];
        }
    }
}

// ---------------- 4. GEMM1 fused (bf16x2; k-tile 32, double-buffered, forced 2 CTAs/SM) ----------------
#define G1_BUFSZ 43520u
#define G1_AHOFF 0u
#define G1_ALOFF 5120u
#define G1_BHOFF 10240u
#define G1_SMEM  103552
__device__ __forceinline__ void g1f_load(uint32_t sb, int b, int nt0, int kt, int p, int t) {
    int k0 = kt*32;
    uint32_t base = sb + (uint32_t)p*G1_BUFSZ;
    {
        int row = t >> 2, q = t & 3;
        size_t e = ((size_t)b*3136 + nt0 + row)*512 + k0 + q*8;
        uint32_t doff = (uint32_t)(row*40 + q*8)*2;
        cpa16(base + G1_AHOFF + doff, g_xTh + e, true);
        cpa16(base + G1_ALOFF + doff, g_xTl + e, true);
    }
    #pragma unroll
    for (int rr = 0; rr < 7; rr++) {
        int idx = rr*256 + t;
        if (idx < 1664) {
            int row = idx >> 2, q = idx & 3;
            bool v = row < 392;
            size_t e = ((size_t)b*392 + (v ? row : 0))*512 + k0 + q*8;
            uint32_t doff = (uint32_t)(row*40 + q*8)*2;
            cpa16(base + G1_BHOFF + doff, g_wqh + e, v);
        }
    }
}

__global__ __launch_bounds__(256, 2) void k_gemm1_fused(const float* __restrict__ rel_bias) {
    extern __shared__ char smraw[];
    uint32_t sb = smem_u32(smraw);
    int b = blockIdx.y, nt0 = blockIdx.x * 64;
    int t = threadIdx.x, w = t >> 5, lane = t & 31;
    int wn = (w & 1)*32, wj = (w >> 1)*104;
    float acc[2][13][4];
    #pragma unroll
    for (int i = 0; i < 2; i++)
        #pragma unroll
        for (int j = 0; j < 13; j++)
            #pragma unroll
            for (int k = 0; k < 4; k++) acc[i][j][k] = 0.f;

    g1f_load(sb, b, nt0, 0, 0, t);
    cp_commit();
    for (int kt = 0; kt < 16; kt++) {
        if (kt < 15) {
            g1f_load(sb, b, nt0, kt+1, (kt+1) & 1, t);
            cp_commit();
            cp_wait1();
        } else cp_wait0();
        __syncthreads();
        uint32_t base = sb + (uint32_t)(kt & 1)*G1_BUFSZ;
        #pragma unroll
        for (int kk = 0; kk < 2; kk++) {
            int kb = kk*16;
            uint32_t ah[2][4], al[2][4];
            int arow = wn + (lane & 15);
            int acol = kb + ((lane & 16) ? 8 : 0);
            ldm_x4(ah[0], base + G1_AHOFF + (uint32_t)(arow*40 + acol)*2);
            ldm_x4(ah[1], base + G1_AHOFF + (uint32_t)((arow+16)*40 + acol)*2);
            ldm_x4(al[0], base + G1_ALOFF + (uint32_t)(arow*40 + acol)*2);
            ldm_x4(al[1], base + G1_ALOFF + (uint32_t)((arow+16)*40 + acol)*2);
            #pragma unroll
            for (int p2 = 0; p2 < 6; p2++) {
                int jrow = wj + p2*16 + (lane & 7) + ((lane & 16) ? 8 : 0);
                int col = kb + ((lane & 8) ? 8 : 0);
                uint32_t off = (uint32_t)(jrow*40 + col)*2;
                uint32_t rh[4];
                ldm_x4(rh, base + G1_BHOFF + off);
                #pragma unroll
                for (int mt = 0; mt < 2; mt++)
                    #pragma unroll
                    for (int e = 0; e < 2; e++) {
                        mma_bf16(acc[mt][2*p2+e], ah[mt], &rh[2*e]);
                        mma_bf16(acc[mt][2*p2+e], al[mt], &rh[2*e]);
                    }
            }
            {
                int jrow = wj + 96 + (lane & 7);
                int col = kb + ((lane & 8) ? 8 : 0);
                uint32_t off = (uint32_t)(jrow*40 + col)*2;
                uint32_t bh2[2];
                ldm_x2(bh2, base + G1_BHOFF + off);
                #pragma unroll
                for (int mt = 0; mt < 2; mt++) {
                    mma_bf16(acc[mt][12], ah[mt], bh2);
                    mma_bf16(acc[mt][12], al[mt], bh2);
                }
            }
        }
        __syncthreads();
    }
    // ---- epilogue: stage logits in SMEM ----
    float* S = (float*)smraw;            // [64][400]
    float* Gred = S + 64*400;            // [8][36]
    #pragma unroll
    for (int mt = 0; mt < 2; mt++) {
        int nl = wn + mt*16 + (lane >> 2);
        #pragma unroll
        for (int jt = 0; jt < 13; jt++) {
            int j0 = wj + jt*8 + ((lane & 3) << 1);
            if (j0 < 392) {
                S[nl*400 + j0]       = acc[mt][jt][0];
                S[nl*400 + j0 + 1]   = acc[mt][jt][1];
                S[(nl+8)*400 + j0]   = acc[mt][jt][2];
                S[(nl+8)*400 + j0+1] = acc[mt][jt][3];
            }
        }
    }
    __syncthreads();
    #pragma unroll
    for (int rr = 0; rr < 2; rr++) {
        int row = t + rr*256;
        int n = row >> 3, h = row & 7;
        float* p = S + n*400 + h*49;
        const float* rb = rel_bias + (size_t)(nt0 + n)*49;
        float mx = -1e30f;
        for (int i = 0; i < 49; i++) {
            float lv = p[i] + __ldg(rb + i);
            p[i] = lv;
            mx = fmaxf(mx, lv);
        }
        float sum = 0.f;
        for (int i = 0; i < 49; i++) { float e = __expf(p[i] - mx); p[i] = e; sum += e; }
        float inv = 1.f / sum;
        for (int i = 0; i < 49; i++) p[i] *= inv;
    }
    __syncthreads();
    float g[36];
    #pragma unroll
    for (int k = 0; k < 36; k++) g[k] = 0.f;
    for (int pos = t; pos < 64*49; pos += 256) {
        int n = pos / 49, m = pos - n*49;
        float a[8];
        #pragma unroll
        for (int h = 0; h < 8; h++) a[h] = S[n*400 + h*49 + m];
        int k = 0;
        #pragma unroll
        for (int h = 0; h < 8; h++)
            #pragma unroll
            for (int h2 = h; h2 < 8; h2++) { g[k] += a[h]*a[h2]; k++; }
    }
    size_t ob = ((size_t)b*3136 + nt0)*392;
    for (int i = t; i < 64*392; i += 256) {
        int n = i / 392, c = i - n*392;
        g_attn[ob + i] = S[n*400 + c];
    }
    #pragma unroll
    for (int s = 16; s; s >>= 1)
        #pragma unroll
        for (int k = 0; k < 36; k++) g[k] += __shfl_xor_sync(0xffffffffu, g[k], s);
    if (lane == 0)
        #pragma unroll
        for (int k = 0; k < 36; k++) Gred[w*36 + k] = g[k];
    __syncthreads();
    if (t < 36) {
        float s = 0.f;
        #pragma unroll
        for (int ww = 0; ww < 8; ww++) s += Gred[ww*36 + t];
        g_part1[((size_t)b*49 + blockIdx.x)*36 + t] = s;
    }
}

// ---------------- 5. gn1 finalize from Gram ----------------
__global__ void k_gn1_final(const float* __restrict__ gs, const float* __restrict__ gb,
                            const float* __restrict__ ew) {
    int b = blockIdx.x, t = threadIdx.x;   // 64 threads
    __shared__ float M36[36];
    __shared__ float Mf[64];
    __shared__ float s1s[24], sqs[24];
    __shared__ float mg[3], rg[3];
    if (t < 36) {
        float s = 0.f;
        for (int nt = 0; nt < 49; nt++) s += g_part1[((size_t)b*49 + nt)*36 + t];
        M36[t] = s;
    }
    __syncthreads();
    if (t == 0) {
        int k = 0;
        for (int h = 0; h < 8; h++)
            for (int h2 = h; h2 < 8; h2++) { Mf[h*8+h2] = M36[k]; Mf[h2*8+h] = M36[k]; k++; }
    }
    __syncthreads();
    if (t < 24) {
        float wv[8], sw = 0.f;
        #pragma unroll
        for (int h = 0; h < 8; h++) { wv[h] = ew[t*8+h]; sw += wv[h]; }
        float sq = 0.f;
        #pragma unroll
        for (int h = 0; h < 8; h++)
            #pragma unroll
            for (int h2 = 0; h2 < 8; h2++) sq += wv[h]*wv[h2]*Mf[h*8+h2];
        s1s[t] = 3136.f * sw;
        sqs[t] = sq;
    }
    __syncthreads();
    if (t < 3) {
        float s1 = 0.f, sq = 0.f;
        for (int c = 0; c < 8; c++) { s1 += s1s[t*8+c]; sq += sqs[t*8+c]; }
        float cnt = 8.f*3136.f*49.f;
        float mean = s1/cnt;
        float var  = sq/cnt - mean*mean;
        mg[t] = mean;
        rg[t] = rsqrtf(var + 1e-5f);
    }
    __syncthreads();
    if (t < 24) {
        float A = rg[t>>3]*gs[t];
        g_ab1[(b*24 + t)*2]     = A;
        g_ab1[(b*24 + t)*2 + 1] = gb[t] - mg[t>>3]*A;
    }
}

// ---------------- stats finalize (gn2/gn3) ----------------
__global__ void k_stats_final(const float* __restrict__ gs, const float* __restrict__ gb,
                              float* __restrict__ ab, const float* __restrict__ part,
                              int G, int npart) {
    int b = blockIdx.x / G, g = blockIdx.x % G;
    const float* p = part + (size_t)(b*G + g)*npart*2;
    float sm = 0.f, sq = 0.f;
    for (int i = threadIdx.x; i < npart; i += 256) { sm += p[2*i]; sq += p[2*i+1]; }
    __shared__ float rs[256], rq[256];
    __shared__ float mean_s, rstd_s;
    int t = threadIdx.x;
    rs[t] = sm; rq[t] = sq;
    __syncthreads();
    for (int st = 128; st; st >>= 1) {
        if (t < st) { rs[t] += rs[t+st]; rq[t] += rq[t+st]; }
        __syncthreads();
    }
    if (!t) {
        float cnt  = 8.f * 3136.f * 49.f;
        float mean = rs[0] / cnt;
        float var  = rq[0] / cnt - mean*mean;
        mean_s = mean;
        rstd_s = rsqrtf(var + 1e-5f);
    }
    __syncthreads();
    if (t < 8) {
        int c = g*8 + t;
        float A = rstd_s * gs[c];
        int CH = G*8;
        ab[(b*CH + c)*2]     = A;
        ab[(b*CH + c)*2 + 1] = gb[c] - mean_s*A;
    }
}

// ---------------- 6. pass B: warp-parallel expand+dw -> gn2 partials ----------------
#define B_AT  0
#define B_HID 7056
#define B_EW  14416
#define B_AB  14608
#define B_RED 14656
#define B_TOT (14656 + 1536)
#define B_SMEM (B_TOT*4)
__global__ __launch_bounds__(256) void k_dw_gn2(const float* __restrict__ dw_w,
                                                const float* __restrict__ expand_w) {
    extern __shared__ float sm[];
    float* at  = sm + B_AT;
    float* ew  = sm + B_EW;
    float* ab  = sm + B_AB;
    float* red = sm + B_RED;
    int nt = blockIdx.x, b = blockIdx.y, t = threadIdx.x;
    int w = t >> 5, lane = t & 31;
    float* hid = sm + B_HID + w*920;
    int n0 = nt * 16;
    if (t < 192) ew[t] = expand_w[t];
    if (t >= 192 && t < 240) ab[t-192] = g_ab1[b*48 + (t-192)];
    for (int i = t; i < 18*392; i += 256) {
        int r = i / 392, m = i - r*392;
        int n = n0 - 1 + r;
        at[i] = (n >= 0 && n < 3136) ? g_attn[((size_t)b*3136 + n)*392 + m] : 0.f;
    }
    __syncthreads();
    float sk[3] = {0,0,0}, qk[3] = {0,0,0};
    #pragma unroll
    for (int k = 0; k < 3; k++) {
        int c = w + k*8;
        float A1 = ab[c*2], B1 = ab[c*2+1];
        const float* wp = ew + c*8;
        for (int i = lane; i < 918; i += 32) {
            int r = i / 51, mm = i - r*51;
            int n = n0 - 1 + r;
            float v = 0.f;
            if (mm >= 1 && mm <= 49 && n >= 0 && n < 3136) {
                const float* sp = at + r*392 + (mm - 1);
                float hsum = 0.f;
                #pragma unroll
                for (int hh = 0; hh < 8; hh++) hsum += sp[hh*49] * wp[hh];
                v = swishf(A1*hsum + B1);
            }
            hid[i] = v;
        }
        __syncwarp();
        float lw[9];
        #pragma unroll
        for (int i = 0; i < 9; i++) lw[i] = dw_w[c*9 + i];
        for (int o = lane; o < 784; o += 32) {
            int ny = o / 49, m = o - ny*49;
            float a = 0.f;
            #pragma unroll
            for (int dy = 0; dy < 3; dy++)
                #pragma unroll
                for (int dx = 0; dx < 3; dx++)
                    a += hid[(ny+dy)*51 + m+dx] * lw[dy*3+dx];
            sk[k] += a; qk[k] += a*a;
        }
        __syncwarp();
    }
    #pragma unroll
    for (int g = 0; g < 3; g++) { red[g*256 + t] = sk[g]; red[(3+g)*256 + t] = qk[g]; }
    __syncthreads();
    for (int st = 128; st; st >>= 1) {
        if (t < st)
            #pragma unroll
            for (int g = 0; g < 6; g++) red[g*256 + t] += red[g*256 + t + st];
        __syncthreads();
    }
    if (t < 3) {
        g_part2[((b*3 + t)*196 + nt)*2]     = red[t*256];
        g_part2[((b*3 + t)*196 + nt)*2 + 1] = red[(t+3)*256];
    }
}

// ---------------- 7. pass C: expand+dw+norm2+swish, reduce -> attnF + gn3 ----------------
#define C_AT  0
#define C_HID 3920
#define C_DWS 8016
#define C_EW  17424
#define C_RW  17616
#define C_AB  17808
#define C_RED 17904
#define C_TOT (17904 + 512)
#define C_SMEM (C_TOT*4)
__global__ __launch_bounds__(256) void k_dla_out(const float* __restrict__ dw_w,
                                                 const float* __restrict__ expand_w,
                                                 const float* __restrict__ reduce_w) {
    extern __shared__ float sm[];
    float* at  = sm + C_AT;
    float* dws = sm + C_DWS;
    float* ew  = sm + C_EW;
    float* rw  = sm + C_RW;
    float* ab  = sm + C_AB;
    float* red = sm + C_RED;
    int nt = blockIdx.x, b = blockIdx.y, t = threadIdx.x;
    int w = t >> 5, lane = t & 31;
    float* hid = sm + C_HID + w*512;
    int n0 = nt * 8;
    if (t < 192) { ew[t] = expand_w[t]; rw[t] = reduce_w[t]; }
    if (t < 96) ab[t] = (t < 48) ? g_ab1[b*48 + t] : g_ab2[b*48 + (t-48)];
    for (int i = t; i < 10*392; i += 256) {
        int r = i / 392, m = i - r*392;
        int n = n0 - 1 + r;
        at[i] = (n >= 0 && n < 3136) ? g_attn[((size_t)b*3136 + n)*392 + m] : 0.f;
    }
    __syncthreads();
    #pragma unroll
    for (int k = 0; k < 3; k++) {
        int c = w + k*8;
        float A1 = ab[c*2], B1 = ab[c*2+1];
        float A2 = ab[48 + c*2], B2 = ab[49 + c*2];
        const float* wp = ew + c*8;
        for (int i = lane; i < 510; i += 32) {
            int r = i / 51, mm = i - r*51;
            int n = n0 - 1 + r;
            float v = 0.f;
            if (mm >= 1 && mm <= 49 && n >= 0 && n < 3136) {
                const float* sp = at + r*392 + (mm - 1);
                float hsum = 0.f;
                #pragma unroll
                for (int hh = 0; hh < 8; hh++) hsum += sp[hh*49] * wp[hh];
                v = swishf(A1*hsum + B1);
            }
            hid[i] = v;
        }
        __syncwarp();
        float lw[9];
        #pragma unroll
        for (int i = 0; i < 9; i++) lw[i] = dw_w[c*9 + i];
        for (int o = lane; o < 392; o += 32) {
            int ny = o / 49, m = o - ny*49;
            float a = 0.f;
            #pragma unroll
            for (int dy = 0; dy < 3; dy++)
                #pragma unroll
                for (int dx = 0; dx < 3; dx++)
                    a += hid[(ny+dy)*51 + m+dx] * lw[dy*3+dx];
            dws[(ny*24 + c)*49 + m] = swishf(A2*a + B2);
        }
        __syncwarp();
    }
    __syncthreads();
    float lsum = 0.f, lsq = 0.f;
    for (int o = t; o < 392; o += 256) {
        int ny = o / 49, m = o - ny*49;
        int n = n0 + ny;
        float in[24];
        #pragma unroll
        for (int c = 0; c < 24; c++) in[c] = dws[(ny*24 + c)*49 + m];
        size_t ob = ((size_t)b*3136 + n)*392 + m;
        #pragma unroll
        for (int h = 0; h < 8; h++) {
            float r = 0.f;
            #pragma unroll
            for (int c = 0; c < 24; c++) r += in[c] * rw[h*24 + c];
            __nv_bfloat16 hh, ll; bsplit(r, hh, ll);
            g_ath[ob + h*49] = hh;
            g_atl[ob + h*49] = ll;
            lsum += r; lsq += r*r;
        }
    }
    red[t] = lsum; red[256 + t] = lsq;
    __syncthreads();
    for (int st = 128; st; st >>= 1) {
        if (t < st) { red[t] += red[t+st]; red[256+t] += red[256+t+st]; }
        __syncthreads();
    }
    if (!t) {
        g_part3[(b*392 + nt)*2]     = red[0];
        g_part3[(b*392 + nt)*2 + 1] = red[256];
    }
}

// ---------------- 8. k_wvpfin: fused wvpsplit (blocks 0..3327) + wvpbias (3328..3343) ----------------
__global__ __launch_bounds__(256) void k_wvpfin(const float* __restrict__ proj_b) {
    __shared__ float tile[32][33];
    int blk = blockIdx.x;
    int t = threadIdx.x;
    if (blk < 3328) {
        int tj = blk % 13;
        int rest = blk / 13;
        int tc = rest & 15, b = rest >> 4;
        int a = t >> 5, q = t & 31;
        #pragma unroll
        for (int r = 0; r < 4; r++) {
            int jj = tj*32 + a + r*8, cc = tc*32 + q;
            float v = 0.f;
            if (jj < 392) v = g_Wvp[((size_t)b*392 + jj)*512 + cc] * g_ab3[(b*8 + jj/49)*2];
            tile[a + r*8][q] = v;
        }
        __syncthreads();
        #pragma unroll
        for (int r = 0; r < 4; r++) {
            int cc = tc*32 + a + r*8, jj = tj*32 + q;
            if (jj < 392) {
                float v = tile[q][a + r*8];
                __nv_bfloat16 h, l; bsplit(v, h, l);
                size_t o = ((size_t)b*512 + cc)*392 + jj;
                g_wvh[o] = h; g_wvl[o] = l;
            }
        }
    } else {
        int b = blk - 3328;
        #pragma unroll
        for (int cc = 0; cc < 2; cc++) {
            int c = t + cc*256;
            float acc = 0.f;
            for (int j = 0; j < 392; j++)
                acc += g_ab3[(b*8 + j/49)*2 + 1] * g_Wvp[((size_t)b*392 + j)*512 + c];
            g_bias2[b*512 + c] = acc + proj_b[c];
        }
    }
}

// ---------------- 9. GEMM2 (bf16x3 mma.sync) ----------------
#define G2_BUF 15360
#define G2_AH 0
#define G2_AL 5120
#define G2_BH 10240
#define G2_BL 12800
#define G2_SMEM (G2_BUF*2*2)
__device__ __forceinline__ void g2_load(uint32_t sb, int b, int nt0, int ct0,
                                        int kt, int p, int t) {
    int k0 = kt*32;
    uint32_t base = sb + (uint32_t)p*G2_BUF*2;
    #pragma unroll
    for (int rr = 0; rr < 2; rr++) {
        int idx = t + rr*256;
        int row = idx >> 2, q = idx & 3;
        int n = nt0 + row, j0 = k0 + q*8;
        bool v = (n < 3136) && (j0 < 392);
        size_t e = ((size_t)b*3136 + (n < 3136 ? n : 0))*392 + (j0 < 392 ? j0 : 0);
        uint32_t doff = (uint32_t)(row*40 + q*8)*2;
        cpa16(base + G2_AH*2 + doff, g_ath + e, v);
        cpa16(base + G2_AL*2 + doff, g_atl + e, v);
    }
    {
        int idx = t;
        int row = idx >> 2, q = idx & 3;
        int c = ct0 + row, j0 = k0 + q*8;
        bool v = j0 < 392;
        size_t e = ((size_t)b*512 + c)*392 + (v ? j0 : 0);
        uint32_t doff = (uint32_t)(row*40 + q*8)*2;
        cpa16(base + G2_BH*2 + doff, g_wvh + e, v);
        cpa16(base + G2_BL*2 + doff, g_wvl + e, v);
    }
}

__global__ __launch_bounds__(256) void k_gemm2_mma(float* __restrict__ out) {
    extern __shared__ __nv_bfloat16 dsm2[];
    uint32_t sb = smem_u32(dsm2);
    int b = blockIdx.z, nt0 = blockIdx.y*128, ct0 = blockIdx.x*64;
    int t = threadIdx.x, w = t >> 5, lane = t & 31;
    int wn = (w & 3)*32, wc = (w >> 2)*32;
    float acc[2][4][4];
    #pragma unroll
    for (int i = 0; i < 2; i++)
        #pragma unroll
        for (int j = 0; j < 4; j++)
            #pragma unroll
            for (int k = 0; k < 4; k++) acc[i][j][k] = 0.f;

    g2_load(sb, b, nt0, ct0, 0, 0, t);
    cp_commit();
    for (int kt = 0; kt < 13; kt++) {
        if (kt < 12) {
            g2_load(sb, b, nt0, ct0, kt+1, (kt+1) & 1, t);
            cp_commit();
            cp_wait1();
        } else cp_wait0();
        __syncthreads();
        uint32_t base = sb + (uint32_t)(kt & 1)*G2_BUF*2;
        #pragma unroll
        for (int kk = 0; kk < 2; kk++) {
            int kb = kk*16;
            uint32_t ah[2][4], al[2][4];
            #pragma unroll
            for (int mt = 0; mt < 2; mt++) {
                int row = wn + mt*16 + (lane & 15);
                int col = kb + ((lane & 16) ? 8 : 0);
                uint32_t off = (uint32_t)(row*40 + col)*2;
                ldm_x4(ah[mt], base + G2_AH*2 + off);
                ldm_x4(al[mt], base + G2_AL*2 + off);
            }
            uint32_t bh[4][2], bl[4][2];
            #pragma unroll
            for (int p = 0; p < 2; p++) {
                int crow = wc + p*16 + (lane & 7) + ((lane & 16) ? 8 : 0);
                int col = kb + ((lane & 8) ? 8 : 0);
                uint32_t off = (uint32_t)(crow*40 + col)*2;
                uint32_t r4[4];
                ldm_x4(r4, base + G2_BH*2 + off);
                bh[2*p][0]=r4[0]; bh[2*p][1]=r4[1]; bh[2*p+1][0]=r4[2]; bh[2*p+1][1]=r4[3];
                ldm_x4(r4, base + G2_BL*2 + off);
                bl[2*p][0]=r4[0]; bl[2*p][1]=r4[1]; bl[2*p+1][0]=r4[2]; bl[2*p+1][1]=r4[3];
            }
            #pragma unroll
            for (int mt = 0; mt < 2; mt++)
                #pragma unroll
                for (int ct = 0; ct < 4; ct++) {
                    mma_bf16(acc[mt][ct], ah[mt], bh[ct]);
                    mma_bf16(acc[mt][ct], al[mt], bh[ct]);
                    mma_bf16(acc[mt][ct], ah[mt], bl[ct]);
                }
        }
        __syncthreads();
    }
    int nrow = nt0 + wn + (lane >> 2);
    #pragma unroll
    for (int mt = 0; mt < 2; mt++) {
        #pragma unroll
        for (int ct = 0; ct < 4; ct++) {
            int c0 = ct0 + wc + ct*8 + ((lane & 3) << 1);
            float b0 = g_bias2[b*512 + c0];
            float b1 = g_bias2[b*512 + c0 + 1];
            #pragma unroll
            for (int half = 0; half < 2; half++) {
                int n = nrow + mt*16 + half*8;
                if (n < 3136) {
                    size_t o = ((size_t)b*3136 + n)*512 + c0;
                    *(float2*)&out[o] = make_float2(acc[mt][ct][half*2] + b0,
                                                    acc[mt][ct][half*2+1] + b1);
                }
            }
        }
    }
}

// ---------------- launcher ----------------
extern "C" void kernel_launch(void* const* d_in, const int* in_sizes, int n_in,
                              void* d_out, int out_size) {
    const float* x        = (const float*)d_in[0];
    const float* q_w      = (const float*)d_in[1];
    const float* down_w   = (const float*)d_in[2];
    const float* kv_w     = (const float*)d_in[3];
    const float* proj_w   = (const float*)d_in[4];
    const float* proj_b   = (const float*)d_in[5];
    const float* rel_bias = (const float*)d_in[6];
    const float* expand_w = (const float*)d_in[7];
    const float* gn1_s    = (const float*)d_in[8];
    const float* gn1_b    = (const float*)d_in[9];
    const float* dw_w     = (const float*)d_in[10];
    const float* gn2_s    = (const float*)d_in[11];
    const float* gn2_b    = (const float*)d_in[12];
    const float* reduce_w = (const float*)d_in[13];
    const float* gn3_s    = (const float*)d_in[14];
    const float* gn3_b    = (const float*)d_in[15];
    float* out = (float*)d_out;

    float *ab2, *ab3, *p2, *p3;
    cudaGetSymbolAddress((void**)&ab2, g_ab2);
    cudaGetSymbolAddress((void**)&ab3, g_ab3);
    cudaGetSymbolAddress((void**)&p2, g_part2);
    cudaGetSymbolAddress((void**)&p3, g_part3);

    cudaFuncSetAttribute(k_gemm1_fused, cudaFuncAttributeMaxDynamicSharedMemorySize, G1_SMEM);
    cudaFuncSetAttribute(k_gemm2_mma, cudaFuncAttributeMaxDynamicSharedMemorySize, G2_SMEM);
    cudaFuncSetAttribute(k_dw_gn2,    cudaFuncAttributeMaxDynamicSharedMemorySize, B_SMEM);
    cudaFuncSetAttribute(k_dla_out,   cudaFuncAttributeMaxDynamicSharedMemorySize, C_SMEM);

    k_prep<<<33280, 256>>>(x, down_w);
    k_kv  <<<dim3(4, 7, BB), 256>>>(kv_w);
    k_qkvw<<<1152, 256>>>(q_w, proj_w);
    k_gemm1_fused<<<dim3(49, BB), 256, G1_SMEM>>>(rel_bias);
    k_gn1_final<<<BB, 64>>>(gn1_s, gn1_b, expand_w);
    k_dw_gn2<<<dim3(196, BB), 256, B_SMEM>>>(dw_w, expand_w);
    k_stats_final<<<BB*3, 256>>>(gn2_s, gn2_b, ab2, p2, 3, 196);
    k_dla_out<<<dim3(392, BB), 256, C_SMEM>>>(dw_w, expand_w, reduce_w);
    k_stats_final<<<BB, 256>>>(gn3_s, gn3_b, ab3, p3, 1, 392);
    k_wvpfin<<<3344, 256>>>(proj_b);
    k_gemm2_mma<<<dim3(8, 25, BB), 256, G2_SMEM>>>(out);
}

// round 13
// speedup vs baseline: 1.0984x; 1.0026x over previous
#include <cuda_runtime.h>
#include <cuda_bf16.h>
#include <math.h>
#include <stdint.h>

#define BB    16
#define CCH   512
#define NN    3136
#define NKK   49
#define HEADS 8
#define JJ    392
#define HIDC  24
#define SCALE 0.125f

// ---------------- device scratch ----------------
__device__ float g_kvx[BB*NKK*CCH];
__device__ float g_kv [BB*NKK*1024];
__device__ float g_Wvp[BB*JJ*CCH];
__device__ __nv_bfloat16 g_xTh[(size_t)BB*NN*CCH];
__device__ __nv_bfloat16 g_xTl[(size_t)BB*NN*CCH];
__device__ __nv_bfloat16 g_wqh[BB*JJ*CCH];
__device__ __nv_bfloat16 g_wvh[BB*CCH*JJ];
__device__ __nv_bfloat16 g_wvl[BB*CCH*JJ];
__device__ float g_attn[(size_t)BB*NN*JJ];
__device__ __nv_bfloat16 g_ath[(size_t)BB*NN*JJ];
__device__ __nv_bfloat16 g_atl[(size_t)BB*NN*JJ];
__device__ float g_part1[BB*98*36];
__device__ float g_part2[BB*3*196*2];
__device__ float g_part3[BB*392*2];
__device__ float g_ab1[BB*HIDC*2];
__device__ float g_ab2[BB*HIDC*2];
__device__ float g_ab3[BB*HEADS*2];
__device__ float g_bias2[BB*CCH];

__device__ __forceinline__ float swishf(float x) { return x / (1.f + __expf(-x)); }

__device__ __forceinline__ void bsplit(float v, __nv_bfloat16& h, __nv_bfloat16& l) {
    h = __float2bfloat16(v);
    l = __float2bfloat16(v - __bfloat162float(h));
}

__device__ __forceinline__ uint32_t smem_u32(const void* p) {
    uint32_t a;
    asm("{ .reg .u64 t; cvta.to.shared.u64 t, %1; cvt.u32.u64 %0, t; }" : "=r"(a) : "l"(p));
    return a;
}
__device__ __forceinline__ void ldm_x4(uint32_t* r, uint32_t addr) {
    asm volatile("ldmatrix.sync.aligned.m8n8.x4.shared.b16 {%0,%1,%2,%3}, [%4];"
        : "=r"(r[0]), "=r"(r[1]), "=r"(r[2]), "=r"(r[3]) : "r"(addr));
}
__device__ __forceinline__ void ldm_x2(uint32_t* r, uint32_t addr) {
    asm volatile("ldmatrix.sync.aligned.m8n8.x2.shared.b16 {%0,%1}, [%2];"
        : "=r"(r[0]), "=r"(r[1]) : "r"(addr));
}
__device__ __forceinline__ void mma_bf16(float* c, const uint32_t* a, const uint32_t* b) {
    asm volatile(
        "mma.sync.aligned.m16n8k16.row.col.f32.bf16.bf16.f32 "
        "{%0,%1,%2,%3}, {%4,%5,%6,%7}, {%8,%9}, {%0,%1,%2,%3};"
        : "+f"(c[0]), "+f"(c[1]), "+f"(c[2]), "+f"(c[3])
        : "r"(a[0]), "r"(a[1]), "r"(a[2]), "r"(a[3]), "r"(b[0]), "r"(b[1]));
}
__device__ __forceinline__ void cpa16(uint32_t dst, const void* src, bool v) {
    int sz = v ? 16 : 0;
    asm volatile("cp.async.cg.shared.global [%0], [%1], 16, %2;"
        :: "r"(dst), "l"(src), "r"(sz) : "memory");
}
__device__ __forceinline__ void cp_commit() {
    asm volatile("cp.async.commit_group;" ::: "memory");
}
__device__ __forceinline__ void cp_wait1() {
    asm volatile("cp.async.wait_group 1;" ::: "memory");
}
__device__ __forceinline__ void cp_wait0() {
    asm volatile("cp.async.wait_group 0;" ::: "memory");
}

// ---------------- 1. k_prep: fused xsplit (blocks 0..25087) + down (blocks 25088..33279) ----------------
__global__ __launch_bounds__(256) void k_prep(const float* __restrict__ x,
                                              const float* __restrict__ down_w) {
    __shared__ float sh[3200];
    int blk = blockIdx.x;
    int t = threadIdx.x;
    if (blk < 25088) {
        int tn = blk % 98;
        int rest = blk / 98;
        int tc = rest & 15, b = rest >> 4;
        float (*tile)[33] = (float(*)[33])sh;
        int a = t >> 5, q = t & 31;
        #pragma unroll
        for (int r = 0; r < 4; r++) {
            int cc = tc*32 + a + r*8, nn = tn*32 + q;
            tile[a + r*8][q] = x[((size_t)b*512 + cc)*3136 + nn];
        }
        __syncthreads();
        #pragma unroll
        for (int r = 0; r < 4; r++) {
            int nn = tn*32 + a + r*8, cc = tc*32 + q;
            float v = tile[q][a + r*8];
            __nv_bfloat16 h, l; bsplit(v, h, l);
            size_t o = ((size_t)b*3136 + nn)*512 + cc;
            g_xTh[o] = h; g_xTl[o] = l;
        }
    } else {
        int bc = blk - 25088, c = bc & 511, b = bc >> 9;
        float* plane = sh;
        float* w = sh + 3136;
        const float* xp = x + (size_t)bc * 3136;
        for (int i = t; i < 3136; i += 256) plane[i] = xp[i];
        if (t < 64) w[t] = down_w[c*64 + t];
        __syncthreads();
        if (t < 49) {
            int my = t / 7, mx = t % 7;
            float s = 0.f;
            #pragma unroll
            for (int i = 0; i < 8; i++)
                #pragma unroll
                for (int j = 0; j < 8; j++)
                    s += plane[(my*8+i)*56 + mx*8 + j] * w[i*8+j];
            g_kvx[(b*49 + t)*512 + c] = s;
        }
    }
}

// ---------------- 2. kv = kvx @ kv_w ----------------
__global__ void k_kv(const float* __restrict__ kv_w) {
    int b = blockIdx.z, m0 = blockIdx.y * 7, oc = blockIdx.x;
    __shared__ float a[7][512];
    for (int i = threadIdx.x; i < 7*512; i += 256)
        a[i >> 9][i & 511] = g_kvx[(b*49 + m0 + (i >> 9))*512 + (i & 511)];
    __syncthreads();
    int o = oc*256 + threadIdx.x;
    float acc[7] = {0,0,0,0,0,0,0};
    for (int c = 0; c < 512; c++) {
        float w = kv_w[c*1024 + o];
        #pragma unroll
        for (int mm = 0; mm < 7; mm++) acc[mm] += a[mm][c] * w;
    }
    #pragma unroll
    for (int mm = 0; mm < 7; mm++)
        g_kv[(b*49 + m0 + mm)*1024 + o] = acc[mm];
}

// ---------------- 3. k_qkvw: fused wqk_split (blocks 0..255, high-only) + wvp (256..1151) ----------------
__global__ __launch_bounds__(256) void k_qkvw(const float* __restrict__ q_w,
                                              const float* __restrict__ proj_w) {
    __shared__ float sh[3136];
    int blk = blockIdx.x;
    int t = threadIdx.x;
    if (blk < 256) {
        int half = blk & 1, h = (blk >> 1) & 7, b = blk >> 4;
        float (*ks)[64] = (float(*)[64])sh;
        for (int i = t; i < 49*64; i += 256)
            ks[i >> 6][i & 63] = g_kv[(b*49 + (i >> 6))*1024 + h*64 + (i & 63)];
        __syncthreads();
        int cin = half*256 + t;
        float acc[49];
        #pragma unroll
        for (int m = 0; m < 49; m++) acc[m] = 0.f;
        const float4* q4 = (const float4*)(q_w + (size_t)cin*512 + h*64);
        const float4* ks4 = (const float4*)&ks[0][0];
        for (int d4 = 0; d4 < 16; d4++) {
            float4 q = __ldg(q4 + d4);
            #pragma unroll
            for (int m = 0; m < 49; m++) {
                float4 k = ks4[m*16 + d4];
                acc[m] += q.x*k.x + q.y*k.y + q.z*k.z + q.w*k.w;
            }
        }
        size_t obase = ((size_t)b*392 + h*49)*512 + cin;
        #pragma unroll
        for (int m = 0; m < 49; m++)
            g_wqh[obase + (size_t)m*512] = __float2bfloat16(acc[m] * SCALE);
    } else {
        int q = blk - 256;
        int mc = (q % 7) * 7, h = (q / 7) & 7, b = q / 56;
        float (*vs)[64] = (float(*)[64])sh;
        for (int i = t; i < 7*64; i += 256)
            vs[i >> 6][i & 63] = g_kv[(b*49 + mc + (i >> 6))*1024 + 512 + h*64 + (i & 63)];
        __syncthreads();
        float acc[7][2] = {{0}};
        for (int d = 0; d < 64; d++) {
            float w0 = proj_w[(h*64+d)*512 + t];
            float w1 = proj_w[(h*64+d)*512 + 256 + t];
            #pragma unroll
            for (int mm = 0; mm < 7; mm++) {
                float vv = vs[mm][d];
                acc[mm][0] += vv * w0;
                acc[mm][1] += vv * w1;
            }
        }
        #pragma unroll
        for (int mm = 0; mm < 7; mm++) {
            int j = h*49 + mc + mm;
            g_Wvp[(b*392 + j)*512 + t]       = acc[mm][0];
            g_Wvp[(b*392 + j)*512 + 256 + t] = acc[mm][1];
        }
    }
}

// ---------------- 4. GEMM1 fused (bf16x2; 32n x 416j tiles, k-tile 32, double-buffered, 2 CTAs/SM) ----------------
#define G1_BUFSZ 38400u
#define G1_AHOFF 0u
#define G1_ALOFF 2560u
#define G1_BHOFF 5120u
#define G1_SMEM  76800
__device__ __forceinline__ void g1f_load(uint32_t sb, int b, int nt0, int kt, int p, int t) {
    int k0 = kt*32;
    uint32_t base = sb + (uint32_t)p*G1_BUFSZ;
    {   // A: 32 rows x 4 chunks x {h,l} = 256 ops, one per thread
        int hl = t >= 128;
        int ii = t & 127;
        int row = ii >> 2, q = ii & 3;
        size_t e = ((size_t)b*3136 + nt0 + row)*512 + k0 + q*8;
        uint32_t doff = (uint32_t)(row*40 + q*8)*2;
        cpa16(base + (hl ? G1_ALOFF : G1_AHOFF) + doff, (hl ? g_xTl : g_xTh) + e, true);
    }
    #pragma unroll
    for (int rr = 0; rr < 7; rr++) {
        int idx = rr*256 + t;
        if (idx < 1664) {
            int row = idx >> 2, q = idx & 3;
            bool v = row < 392;
            size_t e = ((size_t)b*392 + (v ? row : 0))*512 + k0 + q*8;
            uint32_t doff = (uint32_t)(row*40 + q*8)*2;
            cpa16(base + G1_BHOFF + doff, g_wqh + e, v);
        }
    }
}

__global__ __launch_bounds__(256, 2) void k_gemm1_fused(const float* __restrict__ rel_bias) {
    extern __shared__ char smraw[];
    uint32_t sb = smem_u32(smraw);
    int b = blockIdx.y, nt0 = blockIdx.x * 32;
    int t = threadIdx.x, w = t >> 5, lane = t & 31;
    int wn = (w & 1)*16, wj = (w >> 1)*104;
    float acc[13][4];
    #pragma unroll
    for (int j = 0; j < 13; j++)
        #pragma unroll
        for (int k = 0; k < 4; k++) acc[j][k] = 0.f;

    g1f_load(sb, b, nt0, 0, 0, t);
    cp_commit();
    for (int kt = 0; kt < 16; kt++) {
        if (kt < 15) {
            g1f_load(sb, b, nt0, kt+1, (kt+1) & 1, t);
            cp_commit();
            cp_wait1();
        } else cp_wait0();
        __syncthreads();
        uint32_t base = sb + (uint32_t)(kt & 1)*G1_BUFSZ;
        #pragma unroll
        for (int kk = 0; kk < 2; kk++) {
            int kb = kk*16;
            uint32_t ah[4], al[4];
            int arow = wn + (lane & 15);
            int acol = kb + ((lane & 16) ? 8 : 0);
            ldm_x4(ah, base + G1_AHOFF + (uint32_t)(arow*40 + acol)*2);
            ldm_x4(al, base + G1_ALOFF + (uint32_t)(arow*40 + acol)*2);
            #pragma unroll
            for (int p2 = 0; p2 < 6; p2++) {
                int jrow = wj + p2*16 + (lane & 7) + ((lane & 16) ? 8 : 0);
                int col = kb + ((lane & 8) ? 8 : 0);
                uint32_t off = (uint32_t)(jrow*40 + col)*2;
                uint32_t rh[4];
                ldm_x4(rh, base + G1_BHOFF + off);
                #pragma unroll
                for (int e = 0; e < 2; e++) {
                    mma_bf16(acc[2*p2+e], ah, &rh[2*e]);
                    mma_bf16(acc[2*p2+e], al, &rh[2*e]);
                }
            }
            {
                int jrow = wj + 96 + (lane & 7);
                int col = kb + ((lane & 8) ? 8 : 0);
                uint32_t off = (uint32_t)(jrow*40 + col)*2;
                uint32_t bh2[2];
                ldm_x2(bh2, base + G1_BHOFF + off);
                mma_bf16(acc[12], ah, bh2);
                mma_bf16(acc[12], al, bh2);
            }
        }
        __syncthreads();
    }
    // ---- epilogue: stage logits in SMEM ----
    float* S = (float*)smraw;            // [32][400]
    float* Gred = S + 32*400;            // [8][36]
    {
        int nl = wn + (lane >> 2);
        #pragma unroll
        for (int jt = 0; jt < 13; jt++) {
            int j0 = wj + jt*8 + ((lane & 3) << 1);
            if (j0 < 392) {
                S[nl*400 + j0]       = acc[jt][0];
                S[nl*400 + j0 + 1]   = acc[jt][1];
                S[(nl+8)*400 + j0]   = acc[jt][2];
                S[(nl+8)*400 + j0+1] = acc[jt][3];
            }
        }
    }
    __syncthreads();
    {   // softmax: 256 rows = 1 per thread
        int n = t >> 3, h = t & 7;
        float* p = S + n*400 + h*49;
        const float* rb = rel_bias + (size_t)(nt0 + n)*49;
        float mx = -1e30f;
        for (int i = 0; i < 49; i++) {
            float lv = p[i] + __ldg(rb + i);
            p[i] = lv;
            mx = fmaxf(mx, lv);
        }
        float sum = 0.f;
        for (int i = 0; i < 49; i++) { float e = __expf(p[i] - mx); p[i] = e; sum += e; }
        float inv = 1.f / sum;
        for (int i = 0; i < 49; i++) p[i] *= inv;
    }
    __syncthreads();
    float g[36];
    #pragma unroll
    for (int k = 0; k < 36; k++) g[k] = 0.f;
    for (int pos = t; pos < 32*49; pos += 256) {
        int n = pos / 49, m = pos - n*49;
        float a[8];
        #pragma unroll
        for (int h = 0; h < 8; h++) a[h] = S[n*400 + h*49 + m];
        int k = 0;
        #pragma unroll
        for (int h = 0; h < 8; h++)
            #pragma unroll
            for (int h2 = h; h2 < 8; h2++) { g[k] += a[h]*a[h2]; k++; }
    }
    size_t ob = ((size_t)b*3136 + nt0)*392;
    for (int i = t; i < 32*392; i += 256) {
        int n = i / 392, c = i - n*392;
        g_attn[ob + i] = S[n*400 + c];
    }
    #pragma unroll
    for (int s = 16; s; s >>= 1)
        #pragma unroll
        for (int k = 0; k < 36; k++) g[k] += __shfl_xor_sync(0xffffffffu, g[k], s);
    if (lane == 0)
        #pragma unroll
        for (int k = 0; k < 36; k++) Gred[w*36 + k] = g[k];
    __syncthreads();
    if (t < 36) {
        float s = 0.f;
        #pragma unroll
        for (int ww = 0; ww < 8; ww++) s += Gred[ww*36 + t];
        g_part1[((size_t)b*98 + blockIdx.x)*36 + t] = s;
    }
}

// ---------------- 5. gn1 finalize from Gram ----------------
__global__ void k_gn1_final(const float* __restrict__ gs, const float* __restrict__ gb,
                            const float* __restrict__ ew) {
    int b = blockIdx.x, t = threadIdx.x;   // 64 threads
    __shared__ float M36[36];
    __shared__ float Mf[64];
    __shared__ float s1s[24], sqs[24];
    __shared__ float mg[3], rg[3];
    if (t < 36) {
        float s = 0.f;
        for (int nt = 0; nt < 98; nt++) s += g_part1[((size_t)b*98 + nt)*36 + t];
        M36[t] = s;
    }
    __syncthreads();
    if (t == 0) {
        int k = 0;
        for (int h = 0; h < 8; h++)
            for (int h2 = h; h2 < 8; h2++) { Mf[h*8+h2] = M36[k]; Mf[h2*8+h] = M36[k]; k++; }
    }
    __syncthreads();
    if (t < 24) {
        float wv[8], sw = 0.f;
        #pragma unroll
        for (int h = 0; h < 8; h++) { wv[h] = ew[t*8+h]; sw += wv[h]; }
        float sq = 0.f;
        #pragma unroll
        for (int h = 0; h < 8; h++)
            #pragma unroll
            for (int h2 = 0; h2 < 8; h2++) sq += wv[h]*wv[h2]*Mf[h*8+h2];
        s1s[t] = 3136.f * sw;
        sqs[t] = sq;
    }
    __syncthreads();
    if (t < 3) {
        float s1 = 0.f, sq = 0.f;
        for (int c = 0; c < 8; c++) { s1 += s1s[t*8+c]; sq += sqs[t*8+c]; }
        float cnt = 8.f*3136.f*49.f;
        float mean = s1/cnt;
        float var  = sq/cnt - mean*mean;
        mg[t] = mean;
        rg[t] = rsqrtf(var + 1e-5f);
    }
    __syncthreads();
    if (t < 24) {
        float A = rg[t>>3]*gs[t];
        g_ab1[(b*24 + t)*2]     = A;
        g_ab1[(b*24 + t)*2 + 1] = gb[t] - mg[t>>3]*A;
    }
}

// ---------------- stats finalize (gn2/gn3) ----------------
__global__ void k_stats_final(const float* __restrict__ gs, const float* __restrict__ gb,
                              float* __restrict__ ab, const float* __restrict__ part,
                              int G, int npart) {
    int b = blockIdx.x / G, g = blockIdx.x % G;
    const float* p = part + (size_t)(b*G + g)*npart*2;
    float sm = 0.f, sq = 0.f;
    for (int i = threadIdx.x; i < npart; i += 256) { sm += p[2*i]; sq += p[2*i+1]; }
    __shared__ float rs[256], rq[256];
    __shared__ float mean_s, rstd_s;
    int t = threadIdx.x;
    rs[t] = sm; rq[t] = sq;
    __syncthreads();
    for (int st = 128; st; st >>= 1) {
        if (t < st) { rs[t] += rs[t+st]; rq[t] += rq[t+st]; }
        __syncthreads();
    }
    if (!t) {
        float cnt  = 8.f * 3136.f * 49.f;
        float mean = rs[0] / cnt;
        float var  = rq[0] / cnt - mean*mean;
        mean_s = mean;
        rstd_s = rsqrtf(var + 1e-5f);
    }
    __syncthreads();
    if (t < 8) {
        int c = g*8 + t;
        float A = rstd_s * gs[c];
        int CH = G*8;
        ab[(b*CH + c)*2]     = A;
        ab[(b*CH + c)*2 + 1] = gb[c] - mean_s*A;
    }
}

// ---------------- 6. pass B: warp-parallel expand+dw -> gn2 partials ----------------
#define B_AT  0
#define B_HID 7056
#define B_EW  14416
#define B_AB  14608
#define B_RED 14656
#define B_TOT (14656 + 1536)
#define B_SMEM (B_TOT*4)
__global__ __launch_bounds__(256) void k_dw_gn2(const float* __restrict__ dw_w,
                                                const float* __restrict__ expand_w) {
    extern __shared__ float sm[];
    float* at  = sm + B_AT;
    float* ew  = sm + B_EW;
    float* ab  = sm + B_AB;
    float* red = sm + B_RED;
    int nt = blockIdx.x, b = blockIdx.y, t = threadIdx.x;
    int w = t >> 5, lane = t & 31;
    float* hid = sm + B_HID + w*920;
    int n0 = nt * 16;
    if (t < 192) ew[t] = expand_w[t];
    if (t >= 192 && t < 240) ab[t-192] = g_ab1[b*48 + (t-192)];
    for (int i = t; i < 18*392; i += 256) {
        int r = i / 392, m = i - r*392;
        int n = n0 - 1 + r;
        at[i] = (n >= 0 && n < 3136) ? g_attn[((size_t)b*3136 + n)*392 + m] : 0.f;
    }
    __syncthreads();
    float sk[3] = {0,0,0}, qk[3] = {0,0,0};
    #pragma unroll
    for (int k = 0; k < 3; k++) {
        int c = w + k*8;
        float A1 = ab[c*2], B1 = ab[c*2+1];
        const float* wp = ew + c*8;
        for (int i = lane; i < 918; i += 32) {
            int r = i / 51, mm = i - r*51;
            int n = n0 - 1 + r;
            float v = 0.f;
            if (mm >= 1 && mm <= 49 && n >= 0 && n < 3136) {
                const float* sp = at + r*392 + (mm - 1);
                float hsum = 0.f;
                #pragma unroll
                for (int hh = 0; hh < 8; hh++) hsum += sp[hh*49] * wp[hh];
                v = swishf(A1*hsum + B1);
            }
            hid[i] = v;
        }
        __syncwarp();
        float lw[9];
        #pragma unroll
        for (int i = 0; i < 9; i++) lw[i] = dw_w[c*9 + i];
        for (int o = lane; o < 784; o += 32) {
            int ny = o / 49, m = o - ny*49;
            float a = 0.f;
            #pragma unroll
            for (int dy = 0; dy < 3; dy++)
                #pragma unroll
                for (int dx = 0; dx < 3; dx++)
                    a += hid[(ny+dy)*51 + m+dx] * lw[dy*3+dx];
            sk[k] += a; qk[k] += a*a;
        }
        __syncwarp();
    }
    #pragma unroll
    for (int g = 0; g < 3; g++) { red[g*256 + t] = sk[g]; red[(3+g)*256 + t] = qk[g]; }
    __syncthreads();
    for (int st = 128; st; st >>= 1) {
        if (t < st)
            #pragma unroll
            for (int g = 0; g < 6; g++) red[g*256 + t] += red[g*256 + t + st];
        __syncthreads();
    }
    if (t < 3) {
        g_part2[((b*3 + t)*196 + nt)*2]     = red[t*256];
        g_part2[((b*3 + t)*196 + nt)*2 + 1] = red[(t+3)*256];
    }
}

// ---------------- 7. pass C: expand+dw+norm2+swish, reduce -> attnF + gn3 ----------------
#define C_AT  0
#define C_HID 3920
#define C_DWS 8016
#define C_EW  17424
#define C_RW  17616
#define C_AB  17808
#define C_RED 17904
#define C_TOT (17904 + 512)
#define C_SMEM (C_TOT*4)
__global__ __launch_bounds__(256) void k_dla_out(const float* __restrict__ dw_w,
                                                 const float* __restrict__ expand_w,
                                                 const float* __restrict__ reduce_w) {
    extern __shared__ float sm[];
    float* at  = sm + C_AT;
    float* dws = sm + C_DWS;
    float* ew  = sm + C_EW;
    float* rw  = sm + C_RW;
    float* ab  = sm + C_AB;
    float* red = sm + C_RED;
    int nt = blockIdx.x, b = blockIdx.y, t = threadIdx.x;
    int w = t >> 5, lane = t & 31;
    float* hid = sm + C_HID + w*512;
    int n0 = nt * 8;
    if (t < 192) { ew[t] = expand_w[t]; rw[t] = reduce_w[t]; }
    if (t < 96) ab[t] = (t < 48) ? g_ab1[b*48 + t] : g_ab2[b*48 + (t-48)];
    for (int i = t; i < 10*392; i += 256) {
        int r = i / 392, m = i - r*392;
        int n = n0 - 1 + r;
        at[i] = (n >= 0 && n < 3136) ? g_attn[((size_t)b*3136 + n)*392 + m] : 0.f;
    }
    __syncthreads();
    #pragma unroll
    for (int k = 0; k < 3; k++) {
        int c = w + k*8;
        float A1 = ab[c*2], B1 = ab[c*2+1];
        float A2 = ab[48 + c*2], B2 = ab[49 + c*2];
        const float* wp = ew + c*8;
        for (int i = lane; i < 510; i += 32) {
            int r = i / 51, mm = i - r*51;
            int n = n0 - 1 + r;
            float v = 0.f;
            if (mm >= 1 && mm <= 49 && n >= 0 && n < 3136) {
                const float* sp = at + r*392 + (mm - 1);
                float hsum = 0.f;
                #pragma unroll
                for (int hh = 0; hh < 8; hh++) hsum += sp[hh*49] * wp[hh];
                v = swishf(A1*hsum + B1);
            }
            hid[i] = v;
        }
        __syncwarp();
        float lw[9];
        #pragma unroll
        for (int i = 0; i < 9; i++) lw[i] = dw_w[c*9 + i];
        for (int o = lane; o < 392; o += 32) {
            int ny = o / 49, m = o - ny*49;
            float a = 0.f;
            #pragma unroll
            for (int dy = 0; dy < 3; dy++)
                #pragma unroll
                for (int dx = 0; dx < 3; dx++)
                    a += hid[(ny+dy)*51 + m+dx] * lw[dy*3+dx];
            dws[(ny*24 + c)*49 + m] = swishf(A2*a + B2);
        }
        __syncwarp();
    }
    __syncthreads();
    float lsum = 0.f, lsq = 0.f;
    for (int o = t; o < 392; o += 256) {
        int ny = o / 49, m = o - ny*49;
        int n = n0 + ny;
        float in[24];
        #pragma unroll
        for (int c = 0; c < 24; c++) in[c] = dws[(ny*24 + c)*49 + m];
        size_t ob = ((size_t)b*3136 + n)*392 + m;
        #pragma unroll
        for (int h = 0; h < 8; h++) {
            float r = 0.f;
            #pragma unroll
            for (int c = 0; c < 24; c++) r += in[c] * rw[h*24 + c];
            __nv_bfloat16 hh, ll; bsplit(r, hh, ll);
            g_ath[ob + h*49] = hh;
            g_atl[ob + h*49] = ll;
            lsum += r; lsq += r*r;
        }
    }
    red[t] = lsum; red[256 + t] = lsq;
    __syncthreads();
    for (int st = 128; st; st >>= 1) {
        if (t < st) { red[t] += red[t+st]; red[256+t] += red[256+t+st]; }
        __syncthreads();
    }
    if (!t) {
        g_part3[(b*392 + nt)*2]     = red[0];
        g_part3[(b*392 + nt)*2 + 1] = red[256];
    }
}

// ---------------- 8. k_wvpfin: fused wvpsplit (blocks 0..3327) + wvpbias (3328..3343) ----------------
__global__ __launch_bounds__(256) void k_wvpfin(const float* __restrict__ proj_b) {
    __shared__ float tile[32][33];
    int blk = blockIdx.x;
    int t = threadIdx.x;
    if (blk < 3328) {
        int tj = blk % 13;
        int rest = blk / 13;
        int tc = rest & 15, b = rest >> 4;
        int a = t >> 5, q = t & 31;
        #pragma unroll
        for (int r = 0; r < 4; r++) {
            int jj = tj*32 + a + r*8, cc = tc*32 + q;
            float v = 0.f;
            if (jj < 392) v = g_Wvp[((size_t)b*392 + jj)*512 + cc] * g_ab3[(b*8 + jj/49)*2];
            tile[a + r*8][q] = v;
        }
        __syncthreads();
        #pragma unroll
        for (int r = 0; r < 4; r++) {
            int cc = tc*32 + a + r*8, jj = tj*32 + q;
            if (jj < 392) {
                float v = tile[q][a + r*8];
                __nv_bfloat16 h, l; bsplit(v, h, l);
                size_t o = ((size_t)b*512 + cc)*392 + jj;
                g_wvh[o] = h; g_wvl[o] = l;
            }
        }
    } else {
        int b = blk - 3328;
        #pragma unroll
        for (int cc = 0; cc < 2; cc++) {
            int c = t + cc*256;
            float acc = 0.f;
            for (int j = 0; j < 392; j++)
                acc += g_ab3[(b*8 + j/49)*2 + 1] * g_Wvp[((size_t)b*392 + j)*512 + c];
            g_bias2[b*512 + c] = acc + proj_b[c];
        }
    }
}

// ---------------- 9. GEMM2 (bf16x3 mma.sync) ----------------
#define G2_BUF 15360
#define G2_AH 0
#define G2_AL 5120
#define G2_BH 10240
#define G2_BL 12800
#define G2_SMEM (G2_BUF*2*2)
__device__ __forceinline__ void g2_load(uint32_t sb, int b, int nt0, int ct0,
                                        int kt, int p, int t) {
    int k0 = kt*32;
    uint32_t base = sb + (uint32_t)p*G2_BUF*2;
    #pragma unroll
    for (int rr = 0; rr < 2; rr++) {
        int idx = t + rr*256;
        int row = idx >> 2, q = idx & 3;
        int n = nt0 + row, j0 = k0 + q*8;
        bool v = (n < 3136) && (j0 < 392);
        size_t e = ((size_t)b*3136 + (n < 3136 ? n : 0))*392 + (j0 < 392 ? j0 : 0);
        uint32_t doff = (uint32_t)(row*40 + q*8)*2;
        cpa16(base + G2_AH*2 + doff, g_ath + e, v);
        cpa16(base + G2_AL*2 + doff, g_atl + e, v);
    }
    {
        int idx = t;
        int row = idx >> 2, q = idx & 3;
        int c = ct0 + row, j0 = k0 + q*8;
        bool v = j0 < 392;
        size_t e = ((size_t)b*512 + c)*392 + (v ? j0 : 0);
        uint32_t doff = (uint32_t)(row*40 + q*8)*2;
        cpa16(base + G2_BH*2 + doff, g_wvh + e, v);
        cpa16(base + G2_BL*2 + doff, g_wvl + e, v);
    }
}

__global__ __launch_bounds__(256) void k_gemm2_mma(float* __restrict__ out) {
    extern __shared__ __nv_bfloat16 dsm2[];
    uint32_t sb = smem_u32(dsm2);
    int b = blockIdx.z, nt0 = blockIdx.y*128, ct0 = blockIdx.x*64;
    int t = threadIdx.x, w = t >> 5, lane = t & 31;
    int wn = (w & 3)*32, wc = (w >> 2)*32;
    float acc[2][4][4];
    #pragma unroll
    for (int i = 0; i < 2; i++)
        #pragma unroll
        for (int j = 0; j < 4; j++)
            #pragma unroll
            for (int k = 0; k < 4; k++) acc[i][j][k] = 0.f;

    g2_load(sb, b, nt0, ct0, 0, 0, t);
    cp_commit();
    for (int kt = 0; kt < 13; kt++) {
        if (kt < 12) {
            g2_load(sb, b, nt0, ct0, kt+1, (kt+1) & 1, t);
            cp_commit();
            cp_wait1();
        } else cp_wait0();
        __syncthreads();
        uint32_t base = sb + (uint32_t)(kt & 1)*G2_BUF*2;
        #pragma unroll
        for (int kk = 0; kk < 2; kk++) {
            int kb = kk*16;
            uint32_t ah[2][4], al[2][4];
            #pragma unroll
            for (int mt = 0; mt < 2; mt++) {
                int row = wn + mt*16 + (lane & 15);
                int col = kb + ((lane & 16) ? 8 : 0);
                uint32_t off = (uint32_t)(row*40 + col)*2;
                ldm_x4(ah[mt], base + G2_AH*2 + off);
                ldm_x4(al[mt], base + G2_AL*2 + off);
            }
            uint32_t bh[4][2], bl[4][2];
            #pragma unroll
            for (int p = 0; p < 2; p++) {
                int crow = wc + p*16 + (lane & 7) + ((lane & 16) ? 8 : 0);
                int col = kb + ((lane & 8) ? 8 : 0);
                uint32_t off = (uint32_t)(crow*40 + col)*2;
                uint32_t r4[4];
                ldm_x4(r4, base + G2_BH*2 + off);
                bh[2*p][0]=r4[0]; bh[2*p][1]=r4[1]; bh[2*p+1][0]=r4[2]; bh[2*p+1][1]=r4[3];
                ldm_x4(r4, base + G2_BL*2 + off);
                bl[2*p][0]=r4[0]; bl[2*p][1]=r4[1]; bl[2*p+1][0]=r4[2]; bl[2*p+1][1]=r4[3];
            }
            #pragma unroll
            for (int mt = 0; mt < 2; mt++)
                #pragma unroll
                for (int ct = 0; ct < 4; ct++) {
                    mma_bf16(acc[mt][ct], ah[mt], bh[ct]);
                    mma_bf16(acc[mt][ct], al[mt], bh[ct]);
                    mma_bf16(acc[mt][ct], ah[mt], bl[ct]);
                }
        }
        __syncthreads();
    }
    int nrow = nt0 + wn + (lane >> 2);
    #pragma unroll
    for (int mt = 0; mt < 2; mt++) {
        #pragma unroll
        for (int ct = 0; ct < 4; ct++) {
            int c0 = ct0 + wc + ct*8 + ((lane & 3) << 1);
            float b0 = g_bias2[b*512 + c0];
            float b1 = g_bias2[b*512 + c0 + 1];
            #pragma unroll
            for (int half = 0; half < 2; half++) {
                int n = nrow + mt*16 + half*8;
                if (n < 3136) {
                    size_t o = ((size_t)b*3136 + n)*512 + c0;
                    *(float2*)&out[o] = make_float2(acc[mt][ct][half*2] + b0,
                                                    acc[mt][ct][half*2+1] + b1);
                }
            }
        }
    }
}

// ---------------- launcher ----------------
extern "C" void kernel_launch(void* const* d_in, const int* in_sizes, int n_in,
                              void* d_out, int out_size) {
    const float* x        = (const float*)d_in[0];
    const float* q_w      = (const float*)d_in[1];
    const float* down_w   = (const float*)d_in[2];
    const float* kv_w     = (const float*)d_in[3];
    const float* proj_w   = (const float*)d_in[4];
    const float* proj_b   = (const float*)d_in[5];
    const float* rel_bias = (const float*)d_in[6];
    const float* expand_w = (const float*)d_in[7];
    const float* gn1_s    = (const float*)d_in[8];
    const float* gn1_b    = (const float*)d_in[9];
    const float* dw_w     = (const float*)d_in[10];
    const float* gn2_s    = (const float*)d_in[11];
    const float* gn2_b    = (const float*)d_in[12];
    const float* reduce_w = (const float*)d_in[13];
    const float* gn3_s    = (const float*)d_in[14];
    const float* gn3_b    = (const float*)d_in[15];
    float* out = (float*)d_out;

    float *ab2, *ab3, *p2, *p3;
    cudaGetSymbolAddress((void**)&ab2, g_ab2);
    cudaGetSymbolAddress((void**)&ab3, g_ab3);
    cudaGetSymbolAddress((void**)&p2, g_part2);
    cudaGetSymbolAddress((void**)&p3, g_part3);

    cudaFuncSetAttribute(k_gemm1_fused, cudaFuncAttributeMaxDynamicSharedMemorySize, G1_SMEM);
    cudaFuncSetAttribute(k_gemm2_mma, cudaFuncAttributeMaxDynamicSharedMemorySize, G2_SMEM);
    cudaFuncSetAttribute(k_dw_gn2,    cudaFuncAttributeMaxDynamicSharedMemorySize, B_SMEM);
    cudaFuncSetAttribute(k_dla_out,   cudaFuncAttributeMaxDynamicSharedMemorySize, C_SMEM);

    k_prep<<<33280, 256>>>(x, down_w);
    k_kv  <<<dim3(4, 7, BB), 256>>>(kv_w);
    k_qkvw<<<1152, 256>>>(q_w, proj_w);
    k_gemm1_fused<<<dim3(98, BB), 256, G1_SMEM>>>(rel_bias);
    k_gn1_final<<<BB, 64>>>(gn1_s, gn1_b, expand_w);
    k_dw_gn2<<<dim3(196, BB), 256, B_SMEM>>>(dw_w, expand_w);
    k_stats_final<<<BB*3, 256>>>(gn2_s, gn2_b, ab2, p2, 3, 196);
    k_dla_out<<<dim3(392, BB), 256, C_SMEM>>>(dw_w, expand_w, reduce_w);
    k_stats_final<<<BB, 256>>>(gn3_s, gn3_b, ab3, p3, 1, 392);
    k_wvpfin<<<3344, 256>>>(proj_b);
    k_gemm2_mma<<<dim3(8, 25, BB), 256, G2_SMEM>>>(out);
}